// round 1
// baseline (speedup 1.0000x reference)
#include <cuda_runtime.h>
#include <math.h>

#define BB 8
#define CC 32
#define HH 256
#define WW 256
#define HW (HH*WW)

// ---------------- scratch (device globals; no allocations allowed) ----------
__device__ float g_bufA[(size_t)BB * CC * HH * WW];        // 64 MiB: conv outputs
__device__ float g_gated[(size_t)BB * 4 * CC * HH * WW];   // 256 MiB: gated concat (also att scratch)
__device__ float g_wmap[(size_t)BB * 4 * HH * WW];         // 8 MiB: sigmoid gate maps

// ---------------- tiled direct 3x3 conv, pad=1 ------------------------------
// Output tile: TH=16 x TW=32 pixels, COB=16 output channels per block.
// cin processed in chunks of KC=8 staged in shared memory.
template <int CIN, int COUT, bool RELU>
__global__ __launch_bounds__(256)
void conv3x3_kernel(const float* __restrict__ in, const float* __restrict__ wts,
                    float* __restrict__ out) {
    constexpr int TW = 32, TH = 16, COB = 16, KC = 8;
    __shared__ float s_in[KC][TH + 2][TW + 2];
    __shared__ float s_w[COB][KC][9];

    const int tx = threadIdx.x & 31;
    const int ty = threadIdx.x >> 5;           // 0..7
    const int w0 = blockIdx.x * TW;
    const int h0 = blockIdx.y * TH;
    const int nCo = COUT / COB;
    const int co0 = (blockIdx.z % nCo) * COB;
    const int b = blockIdx.z / nCo;

    float acc0[COB], acc1[COB];
#pragma unroll
    for (int i = 0; i < COB; i++) { acc0[i] = 0.f; acc1[i] = 0.f; }

    const float* inb = in + (size_t)b * CIN * HW;

#pragma unroll 1
    for (int c0 = 0; c0 < CIN; c0 += KC) {
        // load input chunk (with zero padding)
        for (int i = threadIdx.x; i < KC * (TH + 2) * (TW + 2); i += 256) {
            int ci = i / ((TH + 2) * (TW + 2));
            int r = i % ((TH + 2) * (TW + 2));
            int y = r / (TW + 2), x = r % (TW + 2);
            int gh = h0 + y - 1, gw = w0 + x - 1;
            float v = 0.f;
            if (gh >= 0 && gh < HH && gw >= 0 && gw < WW)
                v = inb[((size_t)(c0 + ci) * HH + gh) * WW + gw];
            s_in[ci][y][x] = v;
        }
        // load weight chunk (OIHW)
        for (int i = threadIdx.x; i < COB * KC * 9; i += 256) {
            int co = i / (KC * 9);
            int r = i % (KC * 9);
            int ci = r / 9, k = r % 9;
            s_w[co][ci][k] = wts[((size_t)(co0 + co) * CIN + c0 + ci) * 9 + k];
        }
        __syncthreads();

#pragma unroll 2
        for (int ci = 0; ci < KC; ci++) {
#pragma unroll
            for (int k = 0; k < 9; k++) {
                const int ky = k / 3, kx = k % 3;
                float a0 = s_in[ci][ty + ky][tx + kx];
                float a1 = s_in[ci][ty + 8 + ky][tx + kx];
#pragma unroll
                for (int co = 0; co < COB; co++) {
                    float wv = s_w[co][ci][k];
                    acc0[co] += a0 * wv;
                    acc1[co] += a1 * wv;
                }
            }
        }
        __syncthreads();
    }

    float* ob = out + (size_t)b * COUT * HW;
#pragma unroll
    for (int co = 0; co < COB; co++) {
        float v0 = acc0[co], v1 = acc1[co];
        if (RELU) { v0 = fmaxf(v0, 0.f); v1 = fmaxf(v1, 0.f); }
        ob[((size_t)(co0 + co) * HH + h0 + ty) * WW + w0 + tx] = v0;
        ob[((size_t)(co0 + co) * HH + h0 + ty + 8) * WW + w0 + tx] = v1;
    }
}

// ---------------- attention 1x1 conv (16 -> 4) + bias + sigmoid -------------
__global__ void weight_kernel(const float* __restrict__ att2,
                              const float* __restrict__ w3,
                              const float* __restrict__ b3,
                              float* __restrict__ wmap) {
    int idx = blockIdx.x * blockDim.x + threadIdx.x;
    if (idx >= BB * HW) return;
    int b = idx / HW, p = idx % HW;
    const float* base = att2 + (size_t)b * 16 * HW + p;
    float v[16];
#pragma unroll
    for (int c = 0; c < 16; c++) v[c] = base[(size_t)c * HW];
#pragma unroll
    for (int d = 0; d < 4; d++) {
        float s = b3[d];
#pragma unroll
        for (int c = 0; c < 16; c++) s += v[c] * w3[d * 16 + c];
        wmap[((size_t)b * 4 + d) * HW + p] = 1.f / (1.f + expf(-s));
    }
}

// ---------------- final 1x1 conv (32 -> 1) + sigmoid -------------------------
__global__ void final_kernel(const float* __restrict__ in,
                             const float* __restrict__ w_out,
                             float* __restrict__ out) {
    int idx = blockIdx.x * blockDim.x + threadIdx.x;
    if (idx >= BB * HW) return;
    int b = idx / HW, p = idx % HW;
    const float* base = in + (size_t)b * CC * HW + p;
    float s = 0.f;
#pragma unroll
    for (int c = 0; c < CC; c++) s += base[(size_t)c * HW] * w_out[c];
    out[idx] = 1.f / (1.f + expf(-s));
}

// ---------------- vertical scans (top->down into dir0, down->top into dir2) --
// One thread per (b,c,w) column; coalesced across w. Gating fused.
__global__ void scan_vert(const float* __restrict__ x,
                          const float* __restrict__ alpha,
                          const float* __restrict__ wmap,
                          float* __restrict__ gated) {
    int bc = blockIdx.x;
    int b = bc / CC, c = bc % CC;
    int w = threadIdx.x;
    float a = alpha[c];
    const float* xp = x + ((size_t)bc * HH) * WW + w;
    const float* wm0 = wmap + ((size_t)b * 4 + 0) * HW + w;
    const float* wm2 = wmap + ((size_t)b * 4 + 2) * HW + w;
    float* g0 = gated + ((size_t)b * 4 * CC + c) * HW + w;
    float* g2 = gated + ((size_t)b * 4 * CC + 2 * CC + c) * HW + w;

    float prev = 0.f;
#pragma unroll 4
    for (int h = 0; h < HH; h++) {
        float v = fmaxf(xp[(size_t)h * WW] + a * prev, 0.f);
        g0[(size_t)h * WW] = v * wm0[(size_t)h * WW];
        prev = v;
    }
    prev = 0.f;
#pragma unroll 4
    for (int h = HH - 1; h >= 0; h--) {
        float v = fmaxf(xp[(size_t)h * WW] + a * prev, 0.f);
        g2[(size_t)h * WW] = v * wm2[(size_t)h * WW];
        prev = v;
    }
}

// ---------------- horizontal scan (one direction per launch) ----------------
// Block = 32 rows (all in one (b,c) since H%32==0). Coalesced smem staging,
// in-place sequential scan by warp 0 (bank-conflict-free via +1 pad).
template <bool REV>
__global__ void scan_horiz(const float* __restrict__ x,
                           const float* __restrict__ alpha,
                           const float* __restrict__ wmap,
                           float* __restrict__ gated) {
    __shared__ float tin[32][WW + 1];
    int R0 = blockIdx.x * 32;
    int bc = R0 / HH;
    int b = bc / CC, c = bc % CC;
    int h0 = R0 % HH;
    float a = alpha[c];

    const float* xp = x + (size_t)R0 * WW;
    for (int i = threadIdx.x; i < 32 * WW; i += blockDim.x) {
        int r = i >> 8, col = i & 255;
        tin[r][col] = xp[(size_t)r * WW + col];
    }
    __syncthreads();

    if (threadIdx.x < 32) {
        int r = threadIdx.x;
        float prev = 0.f;
        if (!REV) {
#pragma unroll 4
            for (int col = 0; col < WW; col++) {
                float v = fmaxf(tin[r][col] + a * prev, 0.f);
                tin[r][col] = v; prev = v;
            }
        } else {
#pragma unroll 4
            for (int col = WW - 1; col >= 0; col--) {
                float v = fmaxf(tin[r][col] + a * prev, 0.f);
                tin[r][col] = v; prev = v;
            }
        }
    }
    __syncthreads();

    const int dir = REV ? 3 : 1;
    const float* wm = wmap + ((size_t)b * 4 + dir) * HW + (size_t)h0 * WW;
    float* g = gated + ((size_t)b * 4 * CC + (REV ? 3 * CC : CC) + c) * HW + (size_t)h0 * WW;
    for (int i = threadIdx.x; i < 32 * WW; i += blockDim.x) {
        int r = i >> 8, col = i & 255;
        g[(size_t)r * WW + col] = tin[r][col] * wm[(size_t)r * WW + col];
    }
}

// ---------------- launch ------------------------------------------------------
extern "C" void kernel_launch(void* const* d_in, const int* in_sizes, int n_in,
                              void* d_out, int out_size) {
    const float* x      = (const float*)d_in[0];
    const float* alpha1 = (const float*)d_in[1];
    const float* alpha2 = (const float*)d_in[2];
    const float* w_in   = (const float*)d_in[3];
    const float* w2     = (const float*)d_in[4];
    const float* w3     = (const float*)d_in[5];
    const float* att_w1 = (const float*)d_in[6];
    const float* att_w2 = (const float*)d_in[7];
    const float* att_w3 = (const float*)d_in[8];
    const float* att_b3 = (const float*)d_in[9];
    const float* w_out  = (const float*)d_in[10];
    float* out = (float*)d_out;

    float *bufA, *gated, *wmap;
    cudaGetSymbolAddress((void**)&bufA, g_bufA);
    cudaGetSymbolAddress((void**)&gated, g_gated);
    cudaGetSymbolAddress((void**)&wmap, g_wmap);

    // attention scratch lives in g_gated before the gated concat is needed
    float* att1 = gated;
    float* att2 = gated + (size_t)BB * 16 * HW;

    dim3 blk(256);
    dim3 g16(WW / 32, HH / 16, BB);      // COUT=16 convs
    dim3 g32(WW / 32, HH / 16, BB * 2);  // COUT=32 convs

    // attention branch
    conv3x3_kernel<32, 16, true><<<g16, blk>>>(x, att_w1, att1);
    conv3x3_kernel<16, 16, true><<<g16, blk>>>(att1, att_w2, att2);
    weight_kernel<<<(BB * HW + 255) / 256, 256>>>(att2, att_w3, att_b3, wmap);

    // main trunk
    conv3x3_kernel<32, 32, false><<<g32, blk>>>(x, w_in, bufA);

    scan_vert<<<BB * CC, 256>>>(bufA, alpha1, wmap, gated);
    scan_horiz<false><<<(BB * CC * HH) / 32, 256>>>(bufA, alpha1, wmap, gated);
    scan_horiz<true><<<(BB * CC * HH) / 32, 256>>>(bufA, alpha1, wmap, gated);

    conv3x3_kernel<128, 32, false><<<g32, blk>>>(gated, w2, bufA);

    scan_vert<<<BB * CC, 256>>>(bufA, alpha2, wmap, gated);
    scan_horiz<false><<<(BB * CC * HH) / 32, 256>>>(bufA, alpha2, wmap, gated);
    scan_horiz<true><<<(BB * CC * HH) / 32, 256>>>(bufA, alpha2, wmap, gated);

    conv3x3_kernel<128, 32, true><<<g32, blk>>>(gated, w3, bufA);

    final_kernel<<<(BB * HW + 255) / 256, 256>>>(bufA, w_out, out);
}

// round 2
// speedup vs baseline: 1.5868x; 1.5868x over previous
#include <cuda_runtime.h>
#include <math.h>
#include <stdint.h>

#define BB 8
#define CC 32
#define HH 256
#define WW 256
#define HW (HH*WW)

// ---------------- scratch (device globals; no allocations allowed) ----------
__device__ float g_bufA[(size_t)BB * CC * HH * WW];        // 64 MiB: conv outputs
__device__ float g_gated[(size_t)BB * 4 * CC * HH * WW];   // 256 MiB: gated concat (also att scratch)
__device__ float g_wmap[(size_t)BB * 4 * HH * WW];         // 8 MiB: sigmoid gate maps

__device__ __forceinline__ uint32_t f2tf32(float f) {
    uint32_t r;
    asm("cvt.rna.tf32.f32 %0, %1;" : "=r"(r) : "f"(f));
    return r;
}

__device__ __forceinline__ void mma_tf32(float& d0, float& d1, float& d2, float& d3,
                                         uint32_t a0, uint32_t a1, uint32_t a2, uint32_t a3,
                                         uint32_t b0, uint32_t b1) {
    asm volatile(
        "mma.sync.aligned.m16n8k8.row.col.f32.tf32.tf32.f32 "
        "{%0,%1,%2,%3}, {%4,%5,%6,%7}, {%8,%9}, {%0,%1,%2,%3};"
        : "+f"(d0), "+f"(d1), "+f"(d2), "+f"(d3)
        : "r"(a0), "r"(a1), "r"(a2), "r"(a3), "r"(b0), "r"(b1));
}

// ---------------- tf32 tensor-core 3x3 conv, pad=1 ---------------------------
// Output tile per block: 16 rows x 32 cols, all COUT channels.
// Decomposition: O = sum_{k in 3x3} W[:,:,k] @ X_shift_k, K-dim = CIN in chunks of 8.
// mma.sync.m16n8k8 tf32: per warp, M=16 couts, N=8 pixels per n-tile.
template <int CIN, int COUT, bool RELU>
__global__ __launch_bounds__(256)
void conv3x3_mma(const float* __restrict__ in, const float* __restrict__ wts,
                 float* __restrict__ out) {
    constexpr int TW = 32, TH = 16, KC = 8;
    constexpr int PLANE = 616;                 // >= 18*34, stride%32==8 -> conflict-free quads
    constexpr int WPAD = COUT + 8;             // ci-stride mod 32 spreads quads
    constexpr int MW = COUT / 16;              // m-warps (1 or 2)
    constexpr int NWARP = 8 / MW;              // n-warps
    constexpr int RPW = TH / NWARP;            // rows per warp (2 or 4)
    constexpr int NT = RPW * 4;                // n-tiles per warp (8 px each)

    __shared__ uint32_t s_x[KC * PLANE];
    __shared__ uint32_t s_w[9 * KC * WPAD];

    const int tid = threadIdx.x;
    const int lane = tid & 31, warp = tid >> 5;
    const int q = lane >> 2, t = lane & 3;
    const int mw = warp / NWARP;
    const int nw = warp % NWARP;
    const int ry = nw * RPW;

    const int w0 = blockIdx.x * TW;
    const int h0 = blockIdx.y * TH;
    const int b = blockIdx.z;

    float acc[NT][4];
#pragma unroll
    for (int i = 0; i < NT; i++) { acc[i][0]=0.f; acc[i][1]=0.f; acc[i][2]=0.f; acc[i][3]=0.f; }

    const float* inb = in + (size_t)b * CIN * HW;

#pragma unroll 1
    for (int ci0 = 0; ci0 < CIN; ci0 += KC) {
        // stage input chunk (18x34 padded, tf32-converted)
        for (int i = tid; i < KC * 612; i += 256) {
            int ci = i / 612, rem = i % 612;
            int y = rem / 34, x = rem % 34;
            int gh = h0 + y - 1, gw = w0 + x - 1;
            float v = 0.f;
            if (gh >= 0 && gh < HH && gw >= 0 && gw < WW)
                v = inb[((size_t)(ci0 + ci) * HH + gh) * WW + gw];
            s_x[ci * PLANE + y * 34 + x] = f2tf32(v);
        }
        // stage weight chunk: s_w[kk][ci][co]
        for (int i = tid; i < COUT * KC * 9; i += 256) {
            int co = i / (KC * 9), rem = i % (KC * 9);
            int ci = rem / 9, kk = rem % 9;
            s_w[(kk * KC + ci) * WPAD + co] =
                f2tf32(wts[((size_t)co * CIN + ci0 + ci) * 9 + kk]);
        }
        __syncthreads();

#pragma unroll
        for (int kk = 0; kk < 9; kk++) {
            const int ky = kk / 3, kx = kk % 3;
            const uint32_t* wb = s_w + kk * KC * WPAD + mw * 16;
            uint32_t a0 = wb[t * WPAD + q];
            uint32_t a1 = wb[t * WPAD + q + 8];
            uint32_t a2 = wb[(t + 4) * WPAD + q];
            uint32_t a3 = wb[(t + 4) * WPAD + q + 8];
#pragma unroll
            for (int nt = 0; nt < NT; nt++) {
                const int r = ry + (nt >> 2);
                const int cb = (nt & 3) * 8;
                const int idx = (r + ky) * 34 + cb + q + kx;
                uint32_t b0 = s_x[t * PLANE + idx];
                uint32_t b1 = s_x[(t + 4) * PLANE + idx];
                mma_tf32(acc[nt][0], acc[nt][1], acc[nt][2], acc[nt][3],
                         a0, a1, a2, a3, b0, b1);
            }
        }
        __syncthreads();
    }

    float* ob = out + ((size_t)b * COUT + mw * 16) * HW;
#pragma unroll
    for (int nt = 0; nt < NT; nt++) {
        const int r = ry + (nt >> 2);
        const int cb = (nt & 3) * 8;
        const int h = h0 + r;
        const int w = w0 + cb + 2 * t;
        float v0 = acc[nt][0], v1 = acc[nt][1], v2 = acc[nt][2], v3 = acc[nt][3];
        if (RELU) {
            v0 = fmaxf(v0, 0.f); v1 = fmaxf(v1, 0.f);
            v2 = fmaxf(v2, 0.f); v3 = fmaxf(v3, 0.f);
        }
        *(float2*)&ob[((size_t)q * HH + h) * WW + w] = make_float2(v0, v1);
        *(float2*)&ob[((size_t)(q + 8) * HH + h) * WW + w] = make_float2(v2, v3);
    }
}

// ---------------- attention 1x1 conv (16 -> 4) + bias + sigmoid -------------
__global__ void weight_kernel(const float* __restrict__ att2,
                              const float* __restrict__ w3,
                              const float* __restrict__ b3,
                              float* __restrict__ wmap) {
    int idx = blockIdx.x * blockDim.x + threadIdx.x;
    if (idx >= BB * HW) return;
    int b = idx / HW, p = idx % HW;
    const float* base = att2 + (size_t)b * 16 * HW + p;
    float v[16];
#pragma unroll
    for (int c = 0; c < 16; c++) v[c] = base[(size_t)c * HW];
#pragma unroll
    for (int d = 0; d < 4; d++) {
        float s = b3[d];
#pragma unroll
        for (int c = 0; c < 16; c++) s += v[c] * w3[d * 16 + c];
        wmap[((size_t)b * 4 + d) * HW + p] = 1.f / (1.f + expf(-s));
    }
}

// ---------------- final 1x1 conv (32 -> 1) + sigmoid -------------------------
__global__ void final_kernel(const float* __restrict__ in,
                             const float* __restrict__ w_out,
                             float* __restrict__ out) {
    int idx = blockIdx.x * blockDim.x + threadIdx.x;
    if (idx >= BB * HW) return;
    int b = idx / HW, p = idx % HW;
    const float* base = in + (size_t)b * CC * HW + p;
    float s = 0.f;
#pragma unroll
    for (int c = 0; c < CC; c++) s += base[(size_t)c * HW] * w_out[c];
    out[idx] = 1.f / (1.f + expf(-s));
}

// ---------------- vertical scans (top->down into dir0, down->top into dir2) --
__global__ void scan_vert(const float* __restrict__ x,
                          const float* __restrict__ alpha,
                          const float* __restrict__ wmap,
                          float* __restrict__ gated) {
    int bc = blockIdx.x;
    int b = bc / CC, c = bc % CC;
    int w = threadIdx.x;
    float a = alpha[c];
    const float* xp = x + ((size_t)bc * HH) * WW + w;
    const float* wm0 = wmap + ((size_t)b * 4 + 0) * HW + w;
    const float* wm2 = wmap + ((size_t)b * 4 + 2) * HW + w;
    float* g0 = gated + ((size_t)b * 4 * CC + c) * HW + w;
    float* g2 = gated + ((size_t)b * 4 * CC + 2 * CC + c) * HW + w;

    float prev = 0.f;
#pragma unroll 4
    for (int h = 0; h < HH; h++) {
        float v = fmaxf(xp[(size_t)h * WW] + a * prev, 0.f);
        g0[(size_t)h * WW] = v * wm0[(size_t)h * WW];
        prev = v;
    }
    prev = 0.f;
#pragma unroll 4
    for (int h = HH - 1; h >= 0; h--) {
        float v = fmaxf(xp[(size_t)h * WW] + a * prev, 0.f);
        g2[(size_t)h * WW] = v * wm2[(size_t)h * WW];
        prev = v;
    }
}

// ---------------- horizontal scan (one direction per launch) ----------------
template <bool REV>
__global__ void scan_horiz(const float* __restrict__ x,
                           const float* __restrict__ alpha,
                           const float* __restrict__ wmap,
                           float* __restrict__ gated) {
    __shared__ float tin[32][WW + 1];
    int R0 = blockIdx.x * 32;
    int bc = R0 / HH;
    int b = bc / CC, c = bc % CC;
    int h0 = R0 % HH;
    float a = alpha[c];

    const float* xp = x + (size_t)R0 * WW;
    for (int i = threadIdx.x; i < 32 * WW; i += blockDim.x) {
        int r = i >> 8, col = i & 255;
        tin[r][col] = xp[(size_t)r * WW + col];
    }
    __syncthreads();

    if (threadIdx.x < 32) {
        int r = threadIdx.x;
        float prev = 0.f;
        if (!REV) {
#pragma unroll 4
            for (int col = 0; col < WW; col++) {
                float v = fmaxf(tin[r][col] + a * prev, 0.f);
                tin[r][col] = v; prev = v;
            }
        } else {
#pragma unroll 4
            for (int col = WW - 1; col >= 0; col--) {
                float v = fmaxf(tin[r][col] + a * prev, 0.f);
                tin[r][col] = v; prev = v;
            }
        }
    }
    __syncthreads();

    const int dir = REV ? 3 : 1;
    const float* wm = wmap + ((size_t)b * 4 + dir) * HW + (size_t)h0 * WW;
    float* g = gated + ((size_t)b * 4 * CC + (REV ? 3 * CC : CC) + c) * HW + (size_t)h0 * WW;
    for (int i = threadIdx.x; i < 32 * WW; i += blockDim.x) {
        int r = i >> 8, col = i & 255;
        g[(size_t)r * WW + col] = tin[r][col] * wm[(size_t)r * WW + col];
    }
}

// ---------------- launch ------------------------------------------------------
extern "C" void kernel_launch(void* const* d_in, const int* in_sizes, int n_in,
                              void* d_out, int out_size) {
    const float* x      = (const float*)d_in[0];
    const float* alpha1 = (const float*)d_in[1];
    const float* alpha2 = (const float*)d_in[2];
    const float* w_in   = (const float*)d_in[3];
    const float* w2     = (const float*)d_in[4];
    const float* w3     = (const float*)d_in[5];
    const float* att_w1 = (const float*)d_in[6];
    const float* att_w2 = (const float*)d_in[7];
    const float* att_w3 = (const float*)d_in[8];
    const float* att_b3 = (const float*)d_in[9];
    const float* w_out  = (const float*)d_in[10];
    float* out = (float*)d_out;

    float *bufA, *gated, *wmap;
    cudaGetSymbolAddress((void**)&bufA, g_bufA);
    cudaGetSymbolAddress((void**)&gated, g_gated);
    cudaGetSymbolAddress((void**)&wmap, g_wmap);

    // attention scratch lives in g_gated before the gated concat is needed
    float* att1 = gated;
    float* att2 = gated + (size_t)BB * 16 * HW;

    dim3 blk(256);
    dim3 gc(WW / 32, HH / 16, BB);

    // attention branch
    conv3x3_mma<32, 16, true><<<gc, blk>>>(x, att_w1, att1);
    conv3x3_mma<16, 16, true><<<gc, blk>>>(att1, att_w2, att2);
    weight_kernel<<<(BB * HW + 255) / 256, 256>>>(att2, att_w3, att_b3, wmap);

    // main trunk
    conv3x3_mma<32, 32, false><<<gc, blk>>>(x, w_in, bufA);

    scan_vert<<<BB * CC, 256>>>(bufA, alpha1, wmap, gated);
    scan_horiz<false><<<(BB * CC * HH) / 32, 256>>>(bufA, alpha1, wmap, gated);
    scan_horiz<true><<<(BB * CC * HH) / 32, 256>>>(bufA, alpha1, wmap, gated);

    conv3x3_mma<128, 32, false><<<gc, blk>>>(gated, w2, bufA);

    scan_vert<<<BB * CC, 256>>>(bufA, alpha2, wmap, gated);
    scan_horiz<false><<<(BB * CC * HH) / 32, 256>>>(bufA, alpha2, wmap, gated);
    scan_horiz<true><<<(BB * CC * HH) / 32, 256>>>(bufA, alpha2, wmap, gated);

    conv3x3_mma<128, 32, true><<<gc, blk>>>(gated, w3, bufA);

    final_kernel<<<(BB * HW + 255) / 256, 256>>>(bufA, w_out, out);
}

// round 3
// speedup vs baseline: 2.0249x; 1.2761x over previous
#include <cuda_runtime.h>
#include <math.h>
#include <stdint.h>

#define BB 8
#define CC 32
#define HH 256
#define WW 256
#define HW (HH*WW)

// ---------------- scratch (device globals; no allocations allowed) ----------
__device__ float g_bufA[(size_t)BB * CC * HH * WW];        // 64 MiB: conv outputs
__device__ float g_gated[(size_t)BB * 4 * CC * HH * WW];   // 256 MiB: gated concat (also att scratch)
__device__ float g_wmap[(size_t)BB * 4 * HH * WW];         // 8 MiB: sigmoid gate maps

__device__ __forceinline__ uint32_t f2tf32(float f) {
    uint32_t r;
    asm("cvt.rna.tf32.f32 %0, %1;" : "=r"(r) : "f"(f));
    return r;
}

__device__ __forceinline__ void mma_tf32(float& d0, float& d1, float& d2, float& d3,
                                         uint32_t a0, uint32_t a1, uint32_t a2, uint32_t a3,
                                         uint32_t b0, uint32_t b1) {
    asm volatile(
        "mma.sync.aligned.m16n8k8.row.col.f32.tf32.tf32.f32 "
        "{%0,%1,%2,%3}, {%4,%5,%6,%7}, {%8,%9}, {%0,%1,%2,%3};"
        : "+f"(d0), "+f"(d1), "+f"(d2), "+f"(d3)
        : "r"(a0), "r"(a1), "r"(a2), "r"(a3), "r"(b0), "r"(b1));
}

// ---------------- tf32 tensor-core 3x3 conv, pad=1 ---------------------------
// Output tile per block: 16 rows x 32 cols, all COUT channels.
// Paired-cin smem layout: uint2 holds cins (t, t+4) so each B-fragment is one
// LDS.64 and each A-pair is one LDS.64. launch_bounds(256,2) -> 2 blocks/SM.
template <int CIN, int COUT, bool RELU>
__global__ __launch_bounds__(256, 2)
void conv3x3_mma(const float* __restrict__ in, const float* __restrict__ wts,
                 float* __restrict__ out) {
    constexpr int KC = 8;
    constexpr int PLANE = 612;                 // u2 units = 18*34; 2*612 % 32 == 8
    constexpr int WP2 = COUT + 4;              // u2 units; % 16 == 4
    constexpr int MW = COUT / 16;              // m-warps (1 or 2)
    constexpr int NWARP = 8 / MW;              // n-warps
    constexpr int RPW = 16 / NWARP;            // rows per warp
    constexpr int NT = RPW * 4;                // n-tiles per warp (8 px each)

    __shared__ uint2 s_x[4 * PLANE];
    __shared__ uint2 s_w[9 * 4 * WP2];

    const int tid = threadIdx.x;
    const int lane = tid & 31, warp = tid >> 5;
    const int q = lane >> 2, t = lane & 3;
    const int mw = warp / NWARP;
    const int nw = warp % NWARP;
    const int ry = nw * RPW;

    const int w0 = blockIdx.x * 32;
    const int h0 = blockIdx.y * 16;
    const int b = blockIdx.z;

    float acc[NT][4];
#pragma unroll
    for (int i = 0; i < NT; i++) { acc[i][0]=0.f; acc[i][1]=0.f; acc[i][2]=0.f; acc[i][3]=0.f; }

    const float* inb = in + (size_t)b * CIN * HW;
    uint32_t* xw = (uint32_t*)s_x;
    uint32_t* ww = (uint32_t*)s_w;

#pragma unroll 1
    for (int ci0 = 0; ci0 < CIN; ci0 += KC) {
        // stage input chunk (18x34 padded, tf32, paired over (ci&3, ci>>2))
        for (int i = tid; i < KC * 612; i += 256) {
            int ci = i / 612, pos = i % 612;
            int y = pos / 34, x = pos % 34;
            int gh = h0 + y - 1, gw = w0 + x - 1;
            float v = 0.f;
            if (gh >= 0 && gh < HH && gw >= 0 && gw < WW)
                v = inb[((size_t)(ci0 + ci) * HH + gh) * WW + gw];
            xw[((((ci & 3) * PLANE + pos)) << 1) | (ci >> 2)] = f2tf32(v);
        }
        // stage weight chunk: pairs {w[ci][co], w[ci+4][co]} at s_w[kk*4 + ci&3][co]
        for (int i = tid; i < COUT * KC * 9; i += 256) {
            int co = i / (KC * 9), rem = i % (KC * 9);
            int ci = rem / 9, kk = rem % 9;
            ww[((((kk * 4 + (ci & 3)) * WP2 + co)) << 1) | (ci >> 2)] =
                f2tf32(wts[((size_t)co * CIN + ci0 + ci) * 9 + kk]);
        }
        __syncthreads();

#pragma unroll
        for (int kk = 0; kk < 9; kk++) {
            const int ky = kk / 3, kx = kk % 3;
            const uint2* wb = s_w + (kk * 4 + t) * WP2 + mw * 16;
            uint2 pa0 = wb[q];        // {A[q][t],   A[q][t+4]}   = {a0, a2}
            uint2 pa1 = wb[q + 8];    // {A[q+8][t], A[q+8][t+4]} = {a1, a3}
            const uint2* xb = s_x + t * PLANE + ky * 34 + kx + q;
#pragma unroll
            for (int nt = 0; nt < NT; nt++) {
                const int r = ry + (nt >> 2);
                const int cb = (nt & 3) * 8;
                uint2 pb = xb[r * 34 + cb];   // {b0, b1}
                mma_tf32(acc[nt][0], acc[nt][1], acc[nt][2], acc[nt][3],
                         pa0.x, pa1.x, pa0.y, pa1.y, pb.x, pb.y);
            }
        }
        __syncthreads();
    }

    float* ob = out + ((size_t)b * COUT + mw * 16) * HW;
#pragma unroll
    for (int nt = 0; nt < NT; nt++) {
        const int r = ry + (nt >> 2);
        const int cb = (nt & 3) * 8;
        const int h = h0 + r;
        const int w = w0 + cb + 2 * t;
        float v0 = acc[nt][0], v1 = acc[nt][1], v2 = acc[nt][2], v3 = acc[nt][3];
        if (RELU) {
            v0 = fmaxf(v0, 0.f); v1 = fmaxf(v1, 0.f);
            v2 = fmaxf(v2, 0.f); v3 = fmaxf(v3, 0.f);
        }
        *(float2*)&ob[((size_t)q * HH + h) * WW + w] = make_float2(v0, v1);
        *(float2*)&ob[((size_t)(q + 8) * HH + h) * WW + w] = make_float2(v2, v3);
    }
}

// ---------------- attention 1x1 conv (16 -> 4) + bias + sigmoid -------------
__global__ void weight_kernel(const float* __restrict__ att2,
                              const float* __restrict__ w3,
                              const float* __restrict__ b3,
                              float* __restrict__ wmap) {
    int idx = blockIdx.x * blockDim.x + threadIdx.x;
    if (idx >= BB * HW) return;
    int b = idx / HW, p = idx % HW;
    const float* base = att2 + (size_t)b * 16 * HW + p;
    float v[16];
#pragma unroll
    for (int c = 0; c < 16; c++) v[c] = base[(size_t)c * HW];
#pragma unroll
    for (int d = 0; d < 4; d++) {
        float s = b3[d];
#pragma unroll
        for (int c = 0; c < 16; c++) s += v[c] * w3[d * 16 + c];
        wmap[((size_t)b * 4 + d) * HW + p] = 1.f / (1.f + expf(-s));
    }
}

// ---------------- final 1x1 conv (32 -> 1) + sigmoid -------------------------
__global__ void final_kernel(const float* __restrict__ in,
                             const float* __restrict__ w_out,
                             float* __restrict__ out) {
    int idx = blockIdx.x * blockDim.x + threadIdx.x;
    if (idx >= BB * HW) return;
    int b = idx / HW, p = idx % HW;
    const float* base = in + (size_t)b * CC * HW + p;
    float s = 0.f;
#pragma unroll
    for (int c = 0; c < CC; c++) s += base[(size_t)c * HW] * w_out[c];
    out[idx] = 1.f / (1.f + expf(-s));
}

// ---------------- vertical scans (top->down into dir0, down->top into dir2) --
__global__ void scan_vert(const float* __restrict__ x,
                          const float* __restrict__ alpha,
                          const float* __restrict__ wmap,
                          float* __restrict__ gated) {
    int bc = blockIdx.x;
    int b = bc / CC, c = bc % CC;
    int w = threadIdx.x;
    float a = alpha[c];
    const float* xp = x + ((size_t)bc * HH) * WW + w;
    const float* wm0 = wmap + ((size_t)b * 4 + 0) * HW + w;
    const float* wm2 = wmap + ((size_t)b * 4 + 2) * HW + w;
    float* g0 = gated + ((size_t)b * 4 * CC + c) * HW + w;
    float* g2 = gated + ((size_t)b * 4 * CC + 2 * CC + c) * HW + w;

    float prev = 0.f;
#pragma unroll 4
    for (int h = 0; h < HH; h++) {
        float v = fmaxf(xp[(size_t)h * WW] + a * prev, 0.f);
        g0[(size_t)h * WW] = v * wm0[(size_t)h * WW];
        prev = v;
    }
    prev = 0.f;
#pragma unroll 4
    for (int h = HH - 1; h >= 0; h--) {
        float v = fmaxf(xp[(size_t)h * WW] + a * prev, 0.f);
        g2[(size_t)h * WW] = v * wm2[(size_t)h * WW];
        prev = v;
    }
}

// ---------------- horizontal scan (one direction per launch) ----------------
template <bool REV>
__global__ void scan_horiz(const float* __restrict__ x,
                           const float* __restrict__ alpha,
                           const float* __restrict__ wmap,
                           float* __restrict__ gated) {
    __shared__ float tin[32][WW + 1];
    int R0 = blockIdx.x * 32;
    int bc = R0 / HH;
    int b = bc / CC, c = bc % CC;
    int h0 = R0 % HH;
    float a = alpha[c];

    const float* xp = x + (size_t)R0 * WW;
    for (int i = threadIdx.x; i < 32 * WW; i += blockDim.x) {
        int r = i >> 8, col = i & 255;
        tin[r][col] = xp[(size_t)r * WW + col];
    }
    __syncthreads();

    if (threadIdx.x < 32) {
        int r = threadIdx.x;
        float prev = 0.f;
        if (!REV) {
#pragma unroll 4
            for (int col = 0; col < WW; col++) {
                float v = fmaxf(tin[r][col] + a * prev, 0.f);
                tin[r][col] = v; prev = v;
            }
        } else {
#pragma unroll 4
            for (int col = WW - 1; col >= 0; col--) {
                float v = fmaxf(tin[r][col] + a * prev, 0.f);
                tin[r][col] = v; prev = v;
            }
        }
    }
    __syncthreads();

    const int dir = REV ? 3 : 1;
    const float* wm = wmap + ((size_t)b * 4 + dir) * HW + (size_t)h0 * WW;
    float* g = gated + ((size_t)b * 4 * CC + (REV ? 3 * CC : CC) + c) * HW + (size_t)h0 * WW;
    for (int i = threadIdx.x; i < 32 * WW; i += blockDim.x) {
        int r = i >> 8, col = i & 255;
        g[(size_t)r * WW + col] = tin[r][col] * wm[(size_t)r * WW + col];
    }
}

// ---------------- launch ------------------------------------------------------
extern "C" void kernel_launch(void* const* d_in, const int* in_sizes, int n_in,
                              void* d_out, int out_size) {
    const float* x      = (const float*)d_in[0];
    const float* alpha1 = (const float*)d_in[1];
    const float* alpha2 = (const float*)d_in[2];
    const float* w_in   = (const float*)d_in[3];
    const float* w2     = (const float*)d_in[4];
    const float* w3     = (const float*)d_in[5];
    const float* att_w1 = (const float*)d_in[6];
    const float* att_w2 = (const float*)d_in[7];
    const float* att_w3 = (const float*)d_in[8];
    const float* att_b3 = (const float*)d_in[9];
    const float* w_out  = (const float*)d_in[10];
    float* out = (float*)d_out;

    float *bufA, *gated, *wmap;
    cudaGetSymbolAddress((void**)&bufA, g_bufA);
    cudaGetSymbolAddress((void**)&gated, g_gated);
    cudaGetSymbolAddress((void**)&wmap, g_wmap);

    // attention scratch lives in g_gated before the gated concat is needed
    float* att1 = gated;
    float* att2 = gated + (size_t)BB * 16 * HW;

    dim3 blk(256);
    dim3 gc(WW / 32, HH / 16, BB);

    // attention branch
    conv3x3_mma<32, 16, true><<<gc, blk>>>(x, att_w1, att1);
    conv3x3_mma<16, 16, true><<<gc, blk>>>(att1, att_w2, att2);
    weight_kernel<<<(BB * HW + 255) / 256, 256>>>(att2, att_w3, att_b3, wmap);

    // main trunk
    conv3x3_mma<32, 32, false><<<gc, blk>>>(x, w_in, bufA);

    scan_vert<<<BB * CC, 256>>>(bufA, alpha1, wmap, gated);
    scan_horiz<false><<<(BB * CC * HH) / 32, 256>>>(bufA, alpha1, wmap, gated);
    scan_horiz<true><<<(BB * CC * HH) / 32, 256>>>(bufA, alpha1, wmap, gated);

    conv3x3_mma<128, 32, false><<<gc, blk>>>(gated, w2, bufA);

    scan_vert<<<BB * CC, 256>>>(bufA, alpha2, wmap, gated);
    scan_horiz<false><<<(BB * CC * HH) / 32, 256>>>(bufA, alpha2, wmap, gated);
    scan_horiz<true><<<(BB * CC * HH) / 32, 256>>>(bufA, alpha2, wmap, gated);

    conv3x3_mma<128, 32, true><<<gc, blk>>>(gated, w3, bufA);

    final_kernel<<<(BB * HW + 255) / 256, 256>>>(bufA, w_out, out);
}

// round 4
// speedup vs baseline: 2.6069x; 1.2874x over previous
#include <cuda_runtime.h>
#include <math.h>
#include <stdint.h>

#define BB 8
#define CC 32
#define HH 256
#define WW 256
#define HW (HH*WW)

// ---------------- scratch (device globals; no allocations allowed) ----------
__device__ float g_bufA[(size_t)BB * CC * HW];         // 64 MiB: conv outputs
__device__ float g_gated[(size_t)BB * 4 * CC * HW];    // 256 MiB: gated concat (also att scratch)
__device__ float g_wmap[(size_t)BB * 4 * HW];          // 8 MiB: sigmoid gate maps
__device__ float g_xr[(size_t)BB * CC * HW];           // 64 MiB: rna-tf32-rounded x
__device__ float g_wr[131072];                         // rounded conv weights

// g_wr offsets
#define OFF_WIN 0
#define OFF_W2  9216
#define OFF_W3  46080
#define OFF_AW1 82944
#define OFF_AW2 87552

__device__ __forceinline__ float rndf(float f) {
    uint32_t r; asm("cvt.rna.tf32.f32 %0, %1;" : "=r"(r) : "f"(f));
    return __uint_as_float(r);
}

__device__ __forceinline__ void mma_tf32(float& d0, float& d1, float& d2, float& d3,
                                         uint32_t a0, uint32_t a1, uint32_t a2, uint32_t a3,
                                         uint32_t b0, uint32_t b1) {
    asm volatile(
        "mma.sync.aligned.m16n8k8.row.col.f32.tf32.tf32.f32 "
        "{%0,%1,%2,%3}, {%4,%5,%6,%7}, {%8,%9}, {%0,%1,%2,%3};"
        : "+f"(d0), "+f"(d1), "+f"(d2), "+f"(d3)
        : "r"(a0), "r"(a1), "r"(a2), "r"(a3), "r"(b0), "r"(b1));
}

__device__ __forceinline__ void cp4(uint32_t saddr, const float* g, bool p) {
    int sz = p ? 4 : 0;
    asm volatile("cp.async.ca.shared.global [%0], [%1], 4, %2;"
                 :: "r"(saddr), "l"(g), "r"(sz));
}

// ---------------- rounding passes -------------------------------------------
__global__ void round4_kernel(const float4* __restrict__ in, float4* __restrict__ out, int n4) {
    int i = blockIdx.x * blockDim.x + threadIdx.x;
    if (i >= n4) return;
    float4 v = in[i];
    out[i] = make_float4(rndf(v.x), rndf(v.y), rndf(v.z), rndf(v.w));
}
__global__ void round1_kernel(const float* __restrict__ in, float* __restrict__ out, int n) {
    int i = blockIdx.x * blockDim.x + threadIdx.x;
    if (i < n) out[i] = rndf(in[i]);
}

// ---------------- tf32 tensor-core 3x3 conv, pad=1 ---------------------------
// cp.async double-buffered staging (raw fp32 bits; inputs/weights pre-rounded
// to rna-tf32 so mma's bit-truncation is exact). Paired-cin uint2 layout.
template <int CIN, int COUT, bool RELU, bool RND>
__global__ __launch_bounds__(256, 2)
void conv3x3_mma(const float* __restrict__ in, const float* __restrict__ wts,
                 float* __restrict__ out) {
    constexpr int KC = 8;
    constexpr int PLANE = 612;                 // u2 units = 18*34
    constexpr int WP2 = COUT + 4;
    constexpr int XBUF = 4 * PLANE;            // u2 per input buffer
    constexpr int WBUF = 9 * 4 * WP2;          // u2 per weight buffer
    constexpr int MW = COUT / 16;
    constexpr int NWARP = 8 / MW;
    constexpr int RPW = 16 / NWARP;
    constexpr int NT = RPW * 4;
    constexpr int NCH = CIN / KC;

    extern __shared__ uint2 smem[];
    uint2* s_x = smem;                 // [2][XBUF]
    uint2* s_w = smem + 2 * XBUF;      // [2][WBUF]

    const int tid = threadIdx.x;
    const int lane = tid & 31, warp = tid >> 5;
    const int q = lane >> 2, t = lane & 3;
    const int mw = warp / NWARP;
    const int nw = warp % NWARP;
    const int ry = nw * RPW;

    const int w0 = blockIdx.x * 32;
    const int h0 = blockIdx.y * 16;
    const int b = blockIdx.z;

    float acc[NT][4];
#pragma unroll
    for (int i = 0; i < NT; i++) { acc[i][0]=0.f; acc[i][1]=0.f; acc[i][2]=0.f; acc[i][3]=0.f; }

    const float* inb = in + (size_t)b * CIN * HW;
    const uint32_t xb0 = (uint32_t)__cvta_generic_to_shared(s_x);
    const uint32_t wb0 = (uint32_t)__cvta_generic_to_shared(s_w);

    auto stage = [&](int ch, int buf) {
        const float* inp = inb + (size_t)(ch * KC) * HW;
        const uint32_t xbase = xb0 + buf * (XBUF * 8);
        for (int i = tid; i < KC * 612; i += 256) {
            int ci = i / 612, pos = i % 612;
            int y = pos / 34, x = pos % 34;
            int gh = h0 + y - 1, gw = w0 + x - 1;
            bool ok = (gh >= 0 && gh < HH && gw >= 0 && gw < WW);
            int ghc = min(max(gh, 0), HH - 1), gwc = min(max(gw, 0), WW - 1);
            const float* src = inp + (size_t)ci * HW + ghc * WW + gwc;
            uint32_t sa = xbase + ((((ci & 3) * PLANE + pos) << 1) | (ci >> 2)) * 4;
            cp4(sa, src, ok);
        }
        const uint32_t wbase = wb0 + buf * (WBUF * 8);
        for (int i = tid; i < COUT * KC * 9; i += 256) {
            int co = i / (KC * 9), rem = i % (KC * 9);
            int ci = rem / 9, kk = rem % 9;
            const float* src = wts + ((size_t)co * CIN + ch * KC + ci) * 9 + kk;
            uint32_t sa = wbase + ((((kk * 4 + (ci & 3)) * WP2 + co) << 1) | (ci >> 2)) * 4;
            cp4(sa, src, true);
        }
    };

    stage(0, 0);
    asm volatile("cp.async.commit_group;");

#pragma unroll 1
    for (int c = 0; c < NCH; c++) {
        if (c + 1 < NCH) {
            stage(c + 1, (c + 1) & 1);
            asm volatile("cp.async.commit_group;");
            asm volatile("cp.async.wait_group 1;");
        } else {
            asm volatile("cp.async.wait_group 0;");
        }
        __syncthreads();

        const uint2* cx = s_x + (c & 1) * XBUF;
        const uint2* cw = s_w + (c & 1) * WBUF;
#pragma unroll
        for (int kk = 0; kk < 9; kk++) {
            const int ky = kk / 3, kx = kk % 3;
            const uint2* wb = cw + (kk * 4 + t) * WP2 + mw * 16;
            uint2 pa0 = wb[q];
            uint2 pa1 = wb[q + 8];
            const uint2* xb = cx + t * PLANE + ky * 34 + kx + q;
#pragma unroll
            for (int nt = 0; nt < NT; nt++) {
                const int r = ry + (nt >> 2);
                const int cb = (nt & 3) * 8;
                uint2 pb = xb[r * 34 + cb];
                mma_tf32(acc[nt][0], acc[nt][1], acc[nt][2], acc[nt][3],
                         pa0.x, pa1.x, pa0.y, pa1.y, pb.x, pb.y);
            }
        }
        __syncthreads();
    }

    float* ob = out + ((size_t)b * COUT + mw * 16) * HW;
#pragma unroll
    for (int nt = 0; nt < NT; nt++) {
        const int r = ry + (nt >> 2);
        const int cb = (nt & 3) * 8;
        const int h = h0 + r;
        const int w = w0 + cb + 2 * t;
        float v0 = acc[nt][0], v1 = acc[nt][1], v2 = acc[nt][2], v3 = acc[nt][3];
        if (RELU) {
            v0 = fmaxf(v0, 0.f); v1 = fmaxf(v1, 0.f);
            v2 = fmaxf(v2, 0.f); v3 = fmaxf(v3, 0.f);
        }
        if (RND) { v0 = rndf(v0); v1 = rndf(v1); v2 = rndf(v2); v3 = rndf(v3); }
        *(float2*)&ob[((size_t)q * HH + h) * WW + w] = make_float2(v0, v1);
        *(float2*)&ob[((size_t)(q + 8) * HH + h) * WW + w] = make_float2(v2, v3);
    }
}

// ---------------- attention 1x1 conv (16 -> 4) + bias + sigmoid -------------
__global__ void weight_kernel(const float* __restrict__ att2,
                              const float* __restrict__ w3,
                              const float* __restrict__ b3,
                              float* __restrict__ wmap) {
    int idx = blockIdx.x * blockDim.x + threadIdx.x;
    if (idx >= BB * HW) return;
    int b = idx / HW, p = idx % HW;
    const float* base = att2 + (size_t)b * 16 * HW + p;
    float v[16];
#pragma unroll
    for (int c = 0; c < 16; c++) v[c] = base[(size_t)c * HW];
#pragma unroll
    for (int d = 0; d < 4; d++) {
        float s = b3[d];
#pragma unroll
        for (int c = 0; c < 16; c++) s += v[c] * w3[d * 16 + c];
        wmap[((size_t)b * 4 + d) * HW + p] = 1.f / (1.f + expf(-s));
    }
}

// ---------------- final 1x1 conv (32 -> 1) + sigmoid -------------------------
__global__ void final_kernel(const float* __restrict__ in,
                             const float* __restrict__ w_out,
                             float* __restrict__ out) {
    int idx = blockIdx.x * blockDim.x + threadIdx.x;
    if (idx >= BB * HW) return;
    int b = idx / HW, p = idx % HW;
    const float* base = in + (size_t)b * CC * HW + p;
    float s = 0.f;
#pragma unroll
    for (int c = 0; c < CC; c++) s += base[(size_t)c * HW] * w_out[c];
    out[idx] = 1.f / (1.f + expf(-s));
}

// ---------------- vertical scans: 4 h-chunks, warmup restart, fwd+rev fused --
#define WARM 16
__global__ void scan_vert(const float* __restrict__ x,
                          const float* __restrict__ alpha,
                          const float* __restrict__ wmap,
                          float* __restrict__ gated) {
    int bc = blockIdx.x;
    int chunk = blockIdx.y;
    int b = bc / CC, c = bc % CC;
    int w = threadIdx.x;
    float a = alpha[c];
    int h0 = chunk * 64;
    const float* xp = x + (size_t)bc * HW + w;
    const float* wm0 = wmap + ((size_t)b * 4 + 0) * HW + w;
    const float* wm2 = wmap + ((size_t)b * 4 + 2) * HW + w;
    float* g0 = gated + ((size_t)b * 4 * CC + c) * HW + w;
    float* g2 = gated + ((size_t)b * 4 * CC + 2 * CC + c) * HW + w;

    int hs = max(0, h0 - WARM);
    float prev = 0.f;
#pragma unroll 4
    for (int h = hs; h < h0 + 64; h++) {
        float v = fmaxf(xp[(size_t)h * WW] + a * prev, 0.f);
        if (h >= h0) g0[(size_t)h * WW] = rndf(v * wm0[(size_t)h * WW]);
        prev = v;
    }
    int he = min(HH - 1, h0 + 63 + WARM);
    prev = 0.f;
#pragma unroll 4
    for (int h = he; h >= h0; h--) {
        float v = fmaxf(xp[(size_t)h * WW] + a * prev, 0.f);
        if (h < h0 + 64) g2[(size_t)h * WW] = rndf(v * wm2[(size_t)h * WW]);
        prev = v;
    }
}

// ---------------- horizontal scan: both dirs, 2 col-chunks, one kernel -------
__global__ __launch_bounds__(256, 2)
void scan_horiz2(const float* __restrict__ x,
                 const float* __restrict__ alpha,
                 const float* __restrict__ wmap,
                 float* __restrict__ gated) {
    extern __shared__ float sh[];
    float (*tin)[261] = (float(*)[261])sh;
    float (*tf)[261]  = (float(*)[261])(sh + 32 * 261);
    float (*tr)[261]  = (float(*)[261])(sh + 2 * 32 * 261);

    int R0 = blockIdx.x * 32;
    int bc = R0 / HH;
    int b = bc / CC, c = bc % CC;
    int h0 = R0 % HH;
    float a = alpha[c];
    const int tid = threadIdx.x;

    const float* xp = x + (size_t)R0 * WW;
    for (int i = tid; i < 32 * 256; i += 256) tin[i >> 8][i & 255] = xp[i];
    __syncthreads();

    int warp = tid >> 5, lane = tid & 31;
    if (warp == 0) {                       // fwd, cols 0..127 (exact)
        float prev = 0.f;
        for (int col = 0; col < 128; col++) {
            float v = fmaxf(tin[lane][col] + a * prev, 0.f);
            tf[lane][col] = v; prev = v;
        }
    } else if (warp == 1) {                // fwd, warmup 104..127, emit 128..255
        float prev = 0.f;
        for (int col = 104; col < 256; col++) {
            float v = fmaxf(tin[lane][col] + a * prev, 0.f);
            if (col >= 128) tf[lane][col] = v;
            prev = v;
        }
    } else if (warp == 2) {                // rev, cols 255..128 (exact)
        float prev = 0.f;
        for (int col = 255; col >= 128; col--) {
            float v = fmaxf(tin[lane][col] + a * prev, 0.f);
            tr[lane][col] = v; prev = v;
        }
    } else if (warp == 3) {                // rev, warmup 151..128, emit 127..0
        float prev = 0.f;
        for (int col = 151; col >= 0; col--) {
            float v = fmaxf(tin[lane][col] + a * prev, 0.f);
            if (col < 128) tr[lane][col] = v;
            prev = v;
        }
    }
    __syncthreads();

    const float* wm1 = wmap + ((size_t)b * 4 + 1) * HW + (size_t)h0 * WW;
    const float* wm3 = wmap + ((size_t)b * 4 + 3) * HW + (size_t)h0 * WW;
    float* g1 = gated + ((size_t)b * 4 * CC + CC + c) * HW + (size_t)h0 * WW;
    float* g3 = gated + ((size_t)b * 4 * CC + 3 * CC + c) * HW + (size_t)h0 * WW;
    for (int i = tid; i < 32 * 256; i += 256) {
        int r = i >> 8, col = i & 255;
        float m1 = wm1[i], m3 = wm3[i];
        g1[i] = rndf(tf[r][col] * m1);
        g3[i] = rndf(tr[r][col] * m3);
    }
}

// ---------------- launch ------------------------------------------------------
extern "C" void kernel_launch(void* const* d_in, const int* in_sizes, int n_in,
                              void* d_out, int out_size) {
    const float* x      = (const float*)d_in[0];
    const float* alpha1 = (const float*)d_in[1];
    const float* alpha2 = (const float*)d_in[2];
    const float* w_in   = (const float*)d_in[3];
    const float* w2     = (const float*)d_in[4];
    const float* w3     = (const float*)d_in[5];
    const float* att_w1 = (const float*)d_in[6];
    const float* att_w2 = (const float*)d_in[7];
    const float* att_w3 = (const float*)d_in[8];
    const float* att_b3 = (const float*)d_in[9];
    const float* w_out  = (const float*)d_in[10];
    float* out = (float*)d_out;

    float *bufA, *gated, *wmap, *xr, *wr;
    cudaGetSymbolAddress((void**)&bufA, g_bufA);
    cudaGetSymbolAddress((void**)&gated, g_gated);
    cudaGetSymbolAddress((void**)&wmap, g_wmap);
    cudaGetSymbolAddress((void**)&xr, g_xr);
    cudaGetSymbolAddress((void**)&wr, g_wr);

    // dynamic smem limits
    constexpr int SM32 = 2 * 4 * 612 * 8 + 2 * 9 * 4 * 36 * 8;   // 59904
    constexpr int SM16 = 2 * 4 * 612 * 8 + 2 * 9 * 4 * 20 * 8;   // 50688
    constexpr int SMH  = 3 * 32 * 261 * 4;                        // 100224
    cudaFuncSetAttribute(conv3x3_mma<32, 32, false, false>, cudaFuncAttributeMaxDynamicSharedMemorySize, SM32);
    cudaFuncSetAttribute(conv3x3_mma<128, 32, false, false>, cudaFuncAttributeMaxDynamicSharedMemorySize, SM32);
    cudaFuncSetAttribute(conv3x3_mma<128, 32, true, false>, cudaFuncAttributeMaxDynamicSharedMemorySize, SM32);
    cudaFuncSetAttribute(conv3x3_mma<32, 16, true, true>, cudaFuncAttributeMaxDynamicSharedMemorySize, SM16);
    cudaFuncSetAttribute(conv3x3_mma<16, 16, true, false>, cudaFuncAttributeMaxDynamicSharedMemorySize, SM16);
    cudaFuncSetAttribute(scan_horiz2, cudaFuncAttributeMaxDynamicSharedMemorySize, SMH);

    // attention scratch lives in g_gated before the gated concat is needed
    float* att1 = gated;
    float* att2 = gated + (size_t)BB * 16 * HW;

    // pre-round inputs/weights to rna-tf32 (then mma truncation is exact)
    int n4 = BB * CC * HW / 4;
    round4_kernel<<<(n4 + 255) / 256, 256>>>((const float4*)x, (float4*)xr, n4);
    round1_kernel<<<(9216 + 255) / 256, 256>>>(w_in, wr + OFF_WIN, 9216);
    round1_kernel<<<(36864 + 255) / 256, 256>>>(w2, wr + OFF_W2, 36864);
    round1_kernel<<<(36864 + 255) / 256, 256>>>(w3, wr + OFF_W3, 36864);
    round1_kernel<<<(4608 + 255) / 256, 256>>>(att_w1, wr + OFF_AW1, 4608);
    round1_kernel<<<(2304 + 255) / 256, 256>>>(att_w2, wr + OFF_AW2, 2304);

    dim3 blk(256);
    dim3 gc(WW / 32, HH / 16, BB);

    // attention branch
    conv3x3_mma<32, 16, true, true><<<gc, blk, SM16>>>(xr, wr + OFF_AW1, att1);
    conv3x3_mma<16, 16, true, false><<<gc, blk, SM16>>>(att1, wr + OFF_AW2, att2);
    weight_kernel<<<(BB * HW + 255) / 256, 256>>>(att2, att_w3, att_b3, wmap);

    // main trunk
    conv3x3_mma<32, 32, false, false><<<gc, blk, SM32>>>(xr, wr + OFF_WIN, bufA);

    scan_vert<<<dim3(BB * CC, 4), 256>>>(bufA, alpha1, wmap, gated);
    scan_horiz2<<<(BB * CC * HH) / 32, 256, SMH>>>(bufA, alpha1, wmap, gated);

    conv3x3_mma<128, 32, false, false><<<gc, blk, SM32>>>(gated, wr + OFF_W2, bufA);

    scan_vert<<<dim3(BB * CC, 4), 256>>>(bufA, alpha2, wmap, gated);
    scan_horiz2<<<(BB * CC * HH) / 32, 256, SMH>>>(bufA, alpha2, wmap, gated);

    conv3x3_mma<128, 32, true, false><<<gc, blk, SM32>>>(gated, wr + OFF_W3, bufA);

    final_kernel<<<(BB * HW + 255) / 256, 256>>>(bufA, w_out, out);
}

// round 5
// speedup vs baseline: 3.0543x; 1.1716x over previous
#include <cuda_runtime.h>
#include <math.h>
#include <stdint.h>

#define BB 8
#define CC 32
#define HH 256
#define WW 256
#define HW (HH*WW)

// ---------------- scratch (device globals; no allocations allowed) ----------
__device__ float  g_bufA[(size_t)BB * CC * HW];        // 64 MiB: conv outputs (planar)
__device__ float2 g_gated2[(size_t)BB * 64 * HW];      // 256 MiB: gated concat, pair layout
__device__ float  g_wmap[(size_t)BB * 4 * HW];         // 8 MiB: sigmoid gate maps
__device__ float2 g_x2[(size_t)BB * 16 * HW];          // 64 MiB: rounded x, pair layout
__device__ uint4  g_wp[32768];                          // prepacked weights (smem images)
__device__ float  g_wr[4096];                           // rounded flat att_w2

// g_wp offsets in uint4 units
#define WP_WIN 0
#define WP_W2  2592
#define WP_W3  12960
#define WP_AW1 23328

__device__ __forceinline__ float rndf(float f) {
    uint32_t r; asm("cvt.rna.tf32.f32 %0, %1;" : "=r"(r) : "f"(f));
    return __uint_as_float(r);
}
__device__ __forceinline__ uint32_t rndb(float f) {
    uint32_t r; asm("cvt.rna.tf32.f32 %0, %1;" : "=r"(r) : "f"(f));
    return r;
}

__device__ __forceinline__ void mma_tf32(float& d0, float& d1, float& d2, float& d3,
                                         uint32_t a0, uint32_t a1, uint32_t a2, uint32_t a3,
                                         uint32_t b0, uint32_t b1) {
    asm volatile(
        "mma.sync.aligned.m16n8k8.row.col.f32.tf32.tf32.f32 "
        "{%0,%1,%2,%3}, {%4,%5,%6,%7}, {%8,%9}, {%0,%1,%2,%3};"
        : "+f"(d0), "+f"(d1), "+f"(d2), "+f"(d3)
        : "r"(a0), "r"(a1), "r"(a2), "r"(a3), "r"(b0), "r"(b1));
}

// ---------------- setup: repack + round x into pair layout -------------------
// plane id = b*16 + ch*4 + t holds {x[8ch+t], x[8ch+t+4]}
__global__ void repack_x(const float* __restrict__ x, float2* __restrict__ x2) {
    size_t i = (size_t)blockIdx.x * 256 + threadIdx.x;
    int p = (int)(i & (HW - 1));
    int pl = (int)(i >> 16);
    int b = pl >> 4, ch = (pl >> 2) & 3, t = pl & 3;
    const float* s = x + ((size_t)(b * CC + ch * 8 + t)) * HW + p;
    x2[i] = make_float2(rndf(s[0]), rndf(s[(size_t)4 * HW]));
}

// ---------------- setup: prepack weights into per-chunk smem images ----------
// dst[ch][(kk*4+tt)*WP2 + co] = {w[co][8ch+tt][kk], w[co][8ch+tt+4][kk]} (tf32-rounded)
__global__ void prepack_w(const float* __restrict__ w, uint2* __restrict__ dst,
                          int CIN, int COUT, int WP2) {
    int NCH = CIN >> 3;
    int total = NCH * 9 * 4 * WP2;
    int i = blockIdx.x * 256 + threadIdx.x;
    if (i >= total) return;
    int wp = i % WP2; int rem = i / WP2;
    int tt = rem & 3; rem >>= 2; int kk = rem % 9; int ch = rem / 9;
    uint2 v = make_uint2(0u, 0u);
    if (wp < COUT) {
        v.x = rndb(w[((size_t)wp * CIN + ch * 8 + tt) * 9 + kk]);
        v.y = rndb(w[((size_t)wp * CIN + ch * 8 + tt + 4) * 9 + kk]);
    }
    dst[i] = v;
}

__global__ void round1_kernel(const float* __restrict__ in, float* __restrict__ out, int n) {
    int i = blockIdx.x * blockDim.x + threadIdx.x;
    if (i < n) out[i] = rndf(in[i]);
}

// ---------------- tf32 tensor-core 3x3 conv (pair-layout input) --------------
// 16x32 output tile, all COUT channels per block. 8-byte cp.async staging from
// pair-layout gmem with precomputed smem idx table; weights linear-copied from
// prepacked images; 3-stage pipeline, 1 sync/chunk; 2 m-tiles per warp (COUT=32).
template <int CIN, int COUT, bool RELU, bool RND>
__global__ __launch_bounds__(256, 2)
void conv3x3_pair(const float2* __restrict__ in2, const uint4* __restrict__ wpk,
                  float* __restrict__ out) {
    constexpr int PLANE = 612;
    constexpr int WP2 = COUT + 4;
    constexpr int XBUF = 4 * PLANE;     // u2 slots per stage
    constexpr int WBUF = 9 * 4 * WP2;   // u2 slots per stage
    constexpr int NCH = CIN / 8;
    constexpr int NSL = 4 * 612;        // 2448

    extern __shared__ uint2 sm[];
    uint2* s_x = sm;
    uint2* s_w = sm + 3 * XBUF;
    int* s_idx = (int*)(sm + 3 * (XBUF + WBUF));

    const int tid = threadIdx.x;
    const int lane = tid & 31, warp = tid >> 5;
    const int q = lane >> 2, t = lane & 3;
    const int w0 = blockIdx.x * 32, h0 = blockIdx.y * 16, b = blockIdx.z;

    // one-time idx table: off8 (18b) | pad (1b); smem slot == i (PLANE==612)
    for (int i = tid; i < NSL; i += 256) {
        int tt = i / 612, pos = i % 612;
        int y = pos / 34, xx = pos % 34;
        int gh = h0 + y - 1, gw = w0 + xx - 1;
        bool ok = (gh >= 0) && (gh < HH) && (gw >= 0) && (gw < WW);
        int ghc = min(max(gh, 0), HH - 1), gwc = min(max(gw, 0), WW - 1);
        int off8 = tt * HW + ghc * WW + gwc;
        s_idx[i] = off8 | ((ok ? 0 : 1) << 18);
    }

    const uint32_t smx = (uint32_t)__cvta_generic_to_shared(s_x);
    const uint32_t smw = (uint32_t)__cvta_generic_to_shared(s_w);

    auto stage_x = [&](int ch, int buf) {
        const char* base = (const char*)in2 + ((size_t)b * NCH + ch) * 4 * HW * 8;
        uint32_t sb = smx + buf * (XBUF * 8);
#pragma unroll
        for (int j = 0; j < 10; j++) {
            int i = tid + j * 256;
            if (i < NSL) {
                int wv = s_idx[i];
                const char* src = base + ((size_t)(wv & 0x3FFFF)) * 8;
                int sz = ((wv >> 18) & 1) ? 0 : 8;
                asm volatile("cp.async.ca.shared.global [%0], [%1], 8, %2;"
                             :: "r"(sb + (unsigned)i * 8), "l"(src), "r"(sz));
            }
        }
    };
    auto stage_w = [&](int ch, int buf) {
        const uint4* src = wpk + ch * (WBUF / 2);
        uint32_t sb = smw + buf * (WBUF * 8);
#pragma unroll
        for (int j = 0; j < 3; j++) {
            int i = tid + j * 256;
            if (i < WBUF / 2)
                asm volatile("cp.async.cg.shared.global [%0], [%1], 16;"
                             :: "r"(sb + (unsigned)i * 16), "l"(src + i));
        }
    };

    float acc0[8][4], acc1[8][4];
#pragma unroll
    for (int i = 0; i < 8; i++)
#pragma unroll
        for (int k = 0; k < 4; k++) { acc0[i][k] = 0.f; acc1[i][k] = 0.f; }

    stage_x(0, 0); stage_w(0, 0);
    asm volatile("cp.async.commit_group;");
    stage_x(1, 1); stage_w(1, 1);
    asm volatile("cp.async.commit_group;");

#pragma unroll 1
    for (int c = 0; c < NCH; c++) {
        if (c + 1 < NCH) asm volatile("cp.async.wait_group 1;");
        else             asm volatile("cp.async.wait_group 0;");
        __syncthreads();
        if (c + 2 < NCH) {
            stage_x(c + 2, (c + 2) % 3); stage_w(c + 2, (c + 2) % 3);
            asm volatile("cp.async.commit_group;");
        }

        const uint2* cx = s_x + (c % 3) * XBUF;
        const uint2* cw = s_w + (c % 3) * WBUF;
#pragma unroll
        for (int kk = 0; kk < 9; kk++) {
            const int ky = kk / 3, kx = kk % 3;
            const uint2* wb = cw + (kk * 4 + t) * WP2;
            uint2 a00 = wb[q], a01 = wb[q + 8];
            uint2 a10 = make_uint2(0, 0), a11 = make_uint2(0, 0);
            if (COUT == 32) { a10 = wb[q + 16]; a11 = wb[q + 24]; }
            const uint2* xb = cx + t * PLANE + ky * 34 + kx + q;
#pragma unroll
            for (int nt = 0; nt < 8; nt++) {
                int r = 2 * warp + (nt >> 2);
                int cb = (nt & 3) * 8;
                uint2 pb = xb[r * 34 + cb];
                mma_tf32(acc0[nt][0], acc0[nt][1], acc0[nt][2], acc0[nt][3],
                         a00.x, a01.x, a00.y, a01.y, pb.x, pb.y);
                if (COUT == 32)
                    mma_tf32(acc1[nt][0], acc1[nt][1], acc1[nt][2], acc1[nt][3],
                             a10.x, a11.x, a10.y, a11.y, pb.x, pb.y);
            }
        }
    }

    float* ob = out + (size_t)b * COUT * HW;
#pragma unroll
    for (int nt = 0; nt < 8; nt++) {
        int h = h0 + 2 * warp + (nt >> 2);
        int w = w0 + (nt & 3) * 8 + 2 * t;
        size_t pix = (size_t)h * WW + w;
        float v[8] = {acc0[nt][0], acc0[nt][1], acc0[nt][2], acc0[nt][3],
                      acc1[nt][0], acc1[nt][1], acc1[nt][2], acc1[nt][3]};
#pragma unroll
        for (int m = 0; m < (COUT == 32 ? 4 : 2); m++) {
            float v0 = v[m * 2], v1 = v[m * 2 + 1];
            if (RELU) { v0 = fmaxf(v0, 0.f); v1 = fmaxf(v1, 0.f); }
            if (RND)  { v0 = rndf(v0); v1 = rndf(v1); }
            int co = (m & 1) * 8 + (m >> 1) * 16 + q;
            *(float2*)&ob[(size_t)co * HW + pix] = make_float2(v0, v1);
        }
    }
}

// ---------------- planar-input conv (att2 only, CIN=16) ----------------------
template <int CIN, int COUT, bool RELU, bool RND>
__global__ __launch_bounds__(256, 2)
void conv3x3_planar(const float* __restrict__ in, const float* __restrict__ wts,
                    float* __restrict__ out) {
    constexpr int KC = 8;
    constexpr int PLANE = 612;
    constexpr int WP2 = COUT + 4;
    constexpr int XBUF = 4 * PLANE;
    constexpr int WBUF = 9 * 4 * WP2;
    constexpr int NWARP = 8;
    constexpr int NT = 8;
    constexpr int NCH = CIN / KC;

    extern __shared__ uint2 smem[];
    uint2* s_x = smem;
    uint2* s_w = smem + 2 * XBUF;

    const int tid = threadIdx.x;
    const int lane = tid & 31, warp = tid >> 5;
    const int q = lane >> 2, t = lane & 3;
    const int ry = warp * 2;
    const int w0 = blockIdx.x * 32, h0 = blockIdx.y * 16, b = blockIdx.z;

    float acc[NT][4];
#pragma unroll
    for (int i = 0; i < NT; i++) { acc[i][0]=0.f; acc[i][1]=0.f; acc[i][2]=0.f; acc[i][3]=0.f; }

    const float* inb = in + (size_t)b * CIN * HW;
    const uint32_t xb0 = (uint32_t)__cvta_generic_to_shared(s_x);
    const uint32_t wb0 = (uint32_t)__cvta_generic_to_shared(s_w);

    auto stage = [&](int ch, int buf) {
        const float* inp = inb + (size_t)(ch * KC) * HW;
        const uint32_t xbase = xb0 + buf * (XBUF * 8);
        for (int i = tid; i < KC * 612; i += 256) {
            int ci = i / 612, pos = i % 612;
            int y = pos / 34, x = pos % 34;
            int gh = h0 + y - 1, gw = w0 + x - 1;
            bool ok = (gh >= 0 && gh < HH && gw >= 0 && gw < WW);
            int ghc = min(max(gh, 0), HH - 1), gwc = min(max(gw, 0), WW - 1);
            const float* src = inp + (size_t)ci * HW + ghc * WW + gwc;
            uint32_t sa = xbase + ((((ci & 3) * PLANE + pos) << 1) | (ci >> 2)) * 4;
            int sz = ok ? 4 : 0;
            asm volatile("cp.async.ca.shared.global [%0], [%1], 4, %2;"
                         :: "r"(sa), "l"(src), "r"(sz));
        }
        const uint32_t wbase = wb0 + buf * (WBUF * 8);
        for (int i = tid; i < COUT * KC * 9; i += 256) {
            int co = i / (KC * 9), rem = i % (KC * 9);
            int ci = rem / 9, kk = rem % 9;
            const float* src = wts + ((size_t)co * CIN + ch * KC + ci) * 9 + kk;
            uint32_t sa = wbase + ((((kk * 4 + (ci & 3)) * WP2 + co) << 1) | (ci >> 2)) * 4;
            asm volatile("cp.async.ca.shared.global [%0], [%1], 4, 4;"
                         :: "r"(sa), "l"(src));
        }
    };

    stage(0, 0);
    asm volatile("cp.async.commit_group;");
#pragma unroll 1
    for (int c = 0; c < NCH; c++) {
        if (c + 1 < NCH) {
            stage(c + 1, (c + 1) & 1);
            asm volatile("cp.async.commit_group;");
            asm volatile("cp.async.wait_group 1;");
        } else {
            asm volatile("cp.async.wait_group 0;");
        }
        __syncthreads();
        const uint2* cx = s_x + (c & 1) * XBUF;
        const uint2* cw = s_w + (c & 1) * WBUF;
#pragma unroll
        for (int kk = 0; kk < 9; kk++) {
            const int ky = kk / 3, kx = kk % 3;
            const uint2* wb = cw + (kk * 4 + t) * WP2;
            uint2 pa0 = wb[q];
            uint2 pa1 = wb[q + 8];
            const uint2* xb = cx + t * PLANE + ky * 34 + kx + q;
#pragma unroll
            for (int nt = 0; nt < NT; nt++) {
                const int r = ry + (nt >> 2);
                const int cb = (nt & 3) * 8;
                uint2 pb = xb[r * 34 + cb];
                mma_tf32(acc[nt][0], acc[nt][1], acc[nt][2], acc[nt][3],
                         pa0.x, pa1.x, pa0.y, pa1.y, pb.x, pb.y);
            }
        }
        __syncthreads();
    }

    float* ob = out + (size_t)b * COUT * HW;
#pragma unroll
    for (int nt = 0; nt < NT; nt++) {
        const int r = ry + (nt >> 2);
        const int cb = (nt & 3) * 8;
        const int h = h0 + r;
        const int w = w0 + cb + 2 * t;
        float v0 = acc[nt][0], v1 = acc[nt][1], v2 = acc[nt][2], v3 = acc[nt][3];
        if (RELU) { v0 = fmaxf(v0, 0.f); v1 = fmaxf(v1, 0.f); v2 = fmaxf(v2, 0.f); v3 = fmaxf(v3, 0.f); }
        if (RND)  { v0 = rndf(v0); v1 = rndf(v1); v2 = rndf(v2); v3 = rndf(v3); }
        *(float2*)&ob[((size_t)q * HH + h) * WW + w] = make_float2(v0, v1);
        *(float2*)&ob[((size_t)(q + 8) * HH + h) * WW + w] = make_float2(v2, v3);
    }
}

// ---------------- attention 1x1 conv (16 -> 4) + bias + sigmoid -------------
__global__ void weight_kernel(const float* __restrict__ att2,
                              const float* __restrict__ w3,
                              const float* __restrict__ b3,
                              float* __restrict__ wmap) {
    int idx = blockIdx.x * blockDim.x + threadIdx.x;
    if (idx >= BB * HW) return;
    int b = idx / HW, p = idx % HW;
    const float* base = att2 + (size_t)b * 16 * HW + p;
    float v[16];
#pragma unroll
    for (int c = 0; c < 16; c++) v[c] = base[(size_t)c * HW];
#pragma unroll
    for (int d = 0; d < 4; d++) {
        float s = b3[d];
#pragma unroll
        for (int c = 0; c < 16; c++) s += v[c] * w3[d * 16 + c];
        wmap[((size_t)b * 4 + d) * HW + p] = 1.f / (1.f + expf(-s));
    }
}

// ---------------- final 1x1 conv (32 -> 1) + sigmoid -------------------------
__global__ void final_kernel(const float* __restrict__ in,
                             const float* __restrict__ w_out,
                             float* __restrict__ out) {
    int idx = blockIdx.x * blockDim.x + threadIdx.x;
    if (idx >= BB * HW) return;
    int b = idx / HW, p = idx % HW;
    const float* base = in + (size_t)b * CC * HW + p;
    float s = 0.f;
#pragma unroll
    for (int c = 0; c < CC; c++) s += base[(size_t)c * HW] * w_out[c];
    out[idx] = 1.f / (1.f + expf(-s));
}

// ---------------- vertical scans: pair channels, 64-row chunks, warm 16 ------
__global__ void scan_vert(const float* __restrict__ x,
                          const float* __restrict__ alpha,
                          const float* __restrict__ wmap,
                          float2* __restrict__ gated2) {
    int b = blockIdx.x, pg = blockIdx.y, cn = blockIdx.z;
    int c = (pg >> 2) * 8 + (pg & 3);
    int w = threadIdx.x;
    float a1v = alpha[c], a2v = alpha[c + 4];
    const float* xp = x + ((size_t)b * CC + c) * HW + w;
    const float* xq = xp + (size_t)4 * HW;
    float2* g0 = gated2 + ((size_t)(b * 16 + 0 + (c >> 3)) * 4 + (c & 3)) * HW + w;
    float2* g2 = gated2 + ((size_t)(b * 16 + 8 + (c >> 3)) * 4 + (c & 3)) * HW + w;
    const float* wm0 = wmap + ((size_t)b * 4 + 0) * HW + w;
    const float* wm2 = wmap + ((size_t)b * 4 + 2) * HW + w;
    int h0 = cn * 64;

    float p1 = 0.f, p2 = 0.f;
#pragma unroll 4
    for (int h = max(0, h0 - 16); h < h0 + 64; h++) {
        size_t o = (size_t)h * WW;
        float v1 = fmaxf(xp[o] + a1v * p1, 0.f);
        float v2 = fmaxf(xq[o] + a2v * p2, 0.f);
        if (h >= h0) {
            float m = wm0[o];
            g0[o] = make_float2(rndf(v1 * m), rndf(v2 * m));
        }
        p1 = v1; p2 = v2;
    }
    p1 = 0.f; p2 = 0.f;
#pragma unroll 4
    for (int h = min(HH - 1, h0 + 63 + 16); h >= h0; h--) {
        size_t o = (size_t)h * WW;
        float v1 = fmaxf(xp[o] + a1v * p1, 0.f);
        float v2 = fmaxf(xq[o] + a2v * p2, 0.f);
        if (h < h0 + 64) {
            float m = wm2[o];
            g2[o] = make_float2(rndf(v1 * m), rndf(v2 * m));
        }
        p1 = v1; p2 = v2;
    }
}

// ---------------- horizontal scans: pair channels, 32-col chunks, warm 16 ----
__global__ __launch_bounds__(256, 2)
void scan_horiz(const float* __restrict__ x, const float* __restrict__ alpha,
                const float* __restrict__ wmap, float2* __restrict__ gated2) {
    extern __shared__ float2 sh2[];
    float2* tin = sh2;
    float2* tf = sh2 + 16 * 261;
    float2* tr = sh2 + 2 * 16 * 261;
    int b = blockIdx.x, pg = blockIdx.y, hc = blockIdx.z;
    int c = (pg >> 2) * 8 + (pg & 3);
    int tid = threadIdx.x;
    float a1v = alpha[c], a2v = alpha[c + 4];

    const float* xc = x + ((size_t)b * CC + c) * HW + (size_t)hc * 16 * WW;
    const float* xd = xc + (size_t)4 * HW;
    for (int i = tid; i < 16 * 256; i += 256) {
        int r = i >> 8, col = i & 255;
        tin[r * 261 + col] = make_float2(xc[i], xd[i]);
    }
    __syncthreads();

    if (tid < 128) {
        int r = tid & 15, cc = tid >> 4;
        int base = cc * 32;
        float p1 = 0.f, p2 = 0.f;
        for (int col = max(0, base - 16); col < base + 32; col++) {
            float2 xv = tin[r * 261 + col];
            float v1 = fmaxf(xv.x + a1v * p1, 0.f);
            float v2 = fmaxf(xv.y + a2v * p2, 0.f);
            if (col >= base) tf[r * 261 + col] = make_float2(v1, v2);
            p1 = v1; p2 = v2;
        }
        p1 = 0.f; p2 = 0.f;
        for (int col = min(255, base + 47); col >= base; col--) {
            float2 xv = tin[r * 261 + col];
            float v1 = fmaxf(xv.x + a1v * p1, 0.f);
            float v2 = fmaxf(xv.y + a2v * p2, 0.f);
            if (col < base + 32) tr[r * 261 + col] = make_float2(v1, v2);
            p1 = v1; p2 = v2;
        }
    }
    __syncthreads();

    size_t hoff = (size_t)hc * 16 * WW;
    const float* wm1 = wmap + ((size_t)b * 4 + 1) * HW + hoff;
    const float* wm3 = wmap + ((size_t)b * 4 + 3) * HW + hoff;
    float2* g1 = gated2 + ((size_t)(b * 16 + 4 + (c >> 3)) * 4 + (c & 3)) * HW + hoff;
    float2* g3 = gated2 + ((size_t)(b * 16 + 12 + (c >> 3)) * 4 + (c & 3)) * HW + hoff;
    for (int i = tid; i < 16 * 256; i += 256) {
        int r = i >> 8, col = i & 255;
        float m1 = wm1[i], m3 = wm3[i];
        float2 f = tf[r * 261 + col], rv = tr[r * 261 + col];
        g1[i] = make_float2(rndf(f.x * m1), rndf(f.y * m1));
        g3[i] = make_float2(rndf(rv.x * m3), rndf(rv.y * m3));
    }
}

// ---------------- launch ------------------------------------------------------
extern "C" void kernel_launch(void* const* d_in, const int* in_sizes, int n_in,
                              void* d_out, int out_size) {
    const float* x      = (const float*)d_in[0];
    const float* alpha1 = (const float*)d_in[1];
    const float* alpha2 = (const float*)d_in[2];
    const float* w_in   = (const float*)d_in[3];
    const float* w2     = (const float*)d_in[4];
    const float* w3     = (const float*)d_in[5];
    const float* att_w1 = (const float*)d_in[6];
    const float* att_w2 = (const float*)d_in[7];
    const float* att_w3 = (const float*)d_in[8];
    const float* att_b3 = (const float*)d_in[9];
    const float* w_out  = (const float*)d_in[10];
    float* out = (float*)d_out;

    float *bufA, *wmap, *wr;
    float2 *gated2, *x2;
    uint4* wp;
    cudaGetSymbolAddress((void**)&bufA, g_bufA);
    cudaGetSymbolAddress((void**)&gated2, g_gated2);
    cudaGetSymbolAddress((void**)&wmap, g_wmap);
    cudaGetSymbolAddress((void**)&x2, g_x2);
    cudaGetSymbolAddress((void**)&wp, g_wp);
    cudaGetSymbolAddress((void**)&wr, g_wr);

    // smem sizes
    constexpr int SMP32 = 3 * (2448 + 9 * 4 * 36) * 8 + 2448 * 4;   // 99648
    constexpr int SMP16 = 3 * (2448 + 9 * 4 * 20) * 8 + 2448 * 4;   // 85824
    constexpr int SMATT = 2 * (2448 * 8 + 9 * 4 * 20 * 8);          // 50688
    constexpr int SMH   = 3 * 16 * 261 * 8;                          // 100224
    cudaFuncSetAttribute(conv3x3_pair<32, 32, false, false>, cudaFuncAttributeMaxDynamicSharedMemorySize, SMP32);
    cudaFuncSetAttribute(conv3x3_pair<128, 32, false, false>, cudaFuncAttributeMaxDynamicSharedMemorySize, SMP32);
    cudaFuncSetAttribute(conv3x3_pair<128, 32, true, false>, cudaFuncAttributeMaxDynamicSharedMemorySize, SMP32);
    cudaFuncSetAttribute(conv3x3_pair<32, 16, true, true>, cudaFuncAttributeMaxDynamicSharedMemorySize, SMP16);
    cudaFuncSetAttribute(conv3x3_planar<16, 16, true, false>, cudaFuncAttributeMaxDynamicSharedMemorySize, SMATT);
    cudaFuncSetAttribute(scan_horiz, cudaFuncAttributeMaxDynamicSharedMemorySize, SMH);

    // attention scratch: planar floats at head of gated2 region (used before gating)
    float* att1 = (float*)gated2;
    float* att2 = (float*)gated2 + (size_t)BB * 16 * HW;

    // setup: repack/round x; prepack weights
    repack_x<<<BB * 16 * HW / 256, 256>>>(x, x2);
    prepack_w<<<(4 * 9 * 4 * 36 + 255) / 256, 256>>>(w_in, (uint2*)(wp + WP_WIN), 32, 32, 36);
    prepack_w<<<(16 * 9 * 4 * 36 + 255) / 256, 256>>>(w2, (uint2*)(wp + WP_W2), 128, 32, 36);
    prepack_w<<<(16 * 9 * 4 * 36 + 255) / 256, 256>>>(w3, (uint2*)(wp + WP_W3), 128, 32, 36);
    prepack_w<<<(4 * 9 * 4 * 20 + 255) / 256, 256>>>(att_w1, (uint2*)(wp + WP_AW1), 32, 16, 20);
    round1_kernel<<<(2304 + 255) / 256, 256>>>(att_w2, wr, 2304);

    dim3 blk(256);
    dim3 gc(WW / 32, HH / 16, BB);

    // attention branch
    conv3x3_pair<32, 16, true, true><<<gc, blk, SMP16>>>(x2, wp + WP_AW1, att1);
    conv3x3_planar<16, 16, true, false><<<gc, blk, SMATT>>>(att1, wr, att2);
    weight_kernel<<<(BB * HW + 255) / 256, 256>>>(att2, att_w3, att_b3, wmap);

    // main trunk
    conv3x3_pair<32, 32, false, false><<<gc, blk, SMP32>>>(x2, wp + WP_WIN, bufA);

    scan_vert<<<dim3(BB, 16, 4), 256>>>(bufA, alpha1, wmap, gated2);
    scan_horiz<<<dim3(BB, 16, 16), 256, SMH>>>(bufA, alpha1, wmap, gated2);

    conv3x3_pair<128, 32, false, false><<<gc, blk, SMP32>>>(gated2, wp + WP_W2, bufA);

    scan_vert<<<dim3(BB, 16, 4), 256>>>(bufA, alpha2, wmap, gated2);
    scan_horiz<<<dim3(BB, 16, 16), 256, SMH>>>(bufA, alpha2, wmap, gated2);

    conv3x3_pair<128, 32, true, false><<<gc, blk, SMP32>>>(gated2, wp + WP_W3, bufA);

    final_kernel<<<(BB * HW + 255) / 256, 256>>>(bufA, w_out, out);
}

// round 6
// speedup vs baseline: 4.2052x; 1.3768x over previous
#include <cuda_runtime.h>
#include <math.h>
#include <stdint.h>

#define BB 8
#define CC 32
#define HH 256
#define WW 256
#define HW (HH*WW)

// ---------------- scratch (device globals; no allocations allowed) ----------
__device__ float g_bufA[(size_t)BB * CC * HW];         // 64 MiB: conv outputs (planar f32)
__device__ uint2 g_gated2[(size_t)BB * 8 * 4 * HW];    // 128 MiB: gated concat, bf16 pair layout
__device__ float g_wmap[(size_t)BB * 4 * HW];          // 8 MiB: sigmoid gate maps
__device__ uint2 g_x2[(size_t)BB * 2 * 4 * HW];        // 32 MiB: bf16-packed x
__device__ uint4 g_wp[16384];                          // prepacked bf16 weights (smem images)

// g_wp offsets in uint4 units
#define WP_WIN 0
#define WP_W2  1296
#define WP_W3  6480
#define WP_AW1 11664
#define WP_AW2 12384

__device__ __forceinline__ uint32_t pbf(float lo, float hi) {
    uint32_t r;
    asm("cvt.rn.bf16x2.f32 %0, %1, %2;" : "=r"(r) : "f"(hi), "f"(lo));
    return r;
}

__device__ __forceinline__ void mma_bf16(float& d0, float& d1, float& d2, float& d3,
                                         uint32_t a0, uint32_t a1, uint32_t a2, uint32_t a3,
                                         uint32_t b0, uint32_t b1) {
    asm volatile(
        "mma.sync.aligned.m16n8k16.row.col.f32.bf16.bf16.f32 "
        "{%0,%1,%2,%3}, {%4,%5,%6,%7}, {%8,%9}, {%0,%1,%2,%3};"
        : "+f"(d0), "+f"(d1), "+f"(d2), "+f"(d3)
        : "r"(a0), "r"(a1), "r"(a2), "r"(a3), "r"(b0), "r"(b1));
}

// ---------------- setup: pack x into bf16 pair layout ------------------------
// plane = (b*2 + ch)*4 + t; word = {bf16x2(c=16ch+2t, +1), bf16x2(+8, +9)}
__global__ void repack_x(const float* __restrict__ x, uint2* __restrict__ x2) {
    size_t i = (size_t)blockIdx.x * 256 + threadIdx.x;
    int p = (int)(i & (HW - 1));
    int pl = (int)(i >> 16);
    int b = pl >> 3, ch = (pl >> 2) & 1, t = pl & 3;
    const float* s = x + ((size_t)(b * CC + ch * 16 + 2 * t)) * HW + p;
    uint2 v;
    v.x = pbf(s[0], s[(size_t)HW]);
    v.y = pbf(s[(size_t)8 * HW], s[(size_t)9 * HW]);
    x2[i] = v;
}

// ---------------- setup: prepack weights into per-chunk smem images ----------
// dst[((ch*9 + kk)*4 + t)*WP2 + co] = {pack(w[co][16ch+2t][kk], w[..+1]), pack(+8, +9)}
__global__ void prepack_w(const float* __restrict__ w, uint2* __restrict__ dst,
                          int CIN, int COUT, int WP2) {
    int NCH = CIN >> 4;
    int total = NCH * 9 * 4 * WP2;
    int i = blockIdx.x * 256 + threadIdx.x;
    if (i >= total) return;
    int wp = i % WP2; int rem = i / WP2;
    int t = rem & 3; rem >>= 2; int kk = rem % 9; int ch = rem / 9;
    uint2 v = make_uint2(0u, 0u);
    if (wp < COUT) {
        int cb = ch * 16 + 2 * t;
        v.x = pbf(w[((size_t)wp * CIN + cb) * 9 + kk],     w[((size_t)wp * CIN + cb + 1) * 9 + kk]);
        v.y = pbf(w[((size_t)wp * CIN + cb + 8) * 9 + kk], w[((size_t)wp * CIN + cb + 9) * 9 + kk]);
    }
    dst[i] = v;
}

// ---------------- bf16 tensor-core 3x3 conv (pair-layout input) --------------
// 16x32 tile, all COUT per block; chunk = 16 cin; m16n8k16; 3-stage cp.async.
template <int CIN, int COUT, bool RELU>
__global__ __launch_bounds__(256, 2)
void conv3x3_pair(const uint2* __restrict__ in2, const uint4* __restrict__ wpk,
                  float* __restrict__ out) {
    constexpr int PLANE = 612;
    constexpr int WP2 = COUT + 4;
    constexpr int XBUF = 4 * PLANE;
    constexpr int WBUF = 9 * 4 * WP2;
    constexpr int NCH = CIN / 16;
    constexpr int NSL = 4 * 612;
    constexpr int WITER = (WBUF / 2 + 255) / 256;

    extern __shared__ uint2 sm[];
    uint2* s_x = sm;
    uint2* s_w = sm + 3 * XBUF;
    int* s_idx = (int*)(sm + 3 * (XBUF + WBUF));

    const int tid = threadIdx.x;
    const int lane = tid & 31, warp = tid >> 5;
    const int q = lane >> 2, t = lane & 3;
    const int w0 = blockIdx.x * 32, h0 = blockIdx.y * 16, b = blockIdx.z;

    for (int i = tid; i < NSL; i += 256) {
        int tt = i / 612, pos = i % 612;
        int y = pos / 34, xx = pos % 34;
        int gh = h0 + y - 1, gw = w0 + xx - 1;
        bool ok = (gh >= 0) && (gh < HH) && (gw >= 0) && (gw < WW);
        int ghc = min(max(gh, 0), HH - 1), gwc = min(max(gw, 0), WW - 1);
        int off8 = tt * HW + ghc * WW + gwc;
        s_idx[i] = off8 | ((ok ? 0 : 1) << 18);
    }

    const uint32_t smx = (uint32_t)__cvta_generic_to_shared(s_x);
    const uint32_t smw = (uint32_t)__cvta_generic_to_shared(s_w);

    auto stage_x = [&](int ch, int buf) {
        const char* base = (const char*)in2 + ((size_t)b * NCH + ch) * 4 * HW * 8;
        uint32_t sb = smx + buf * (XBUF * 8);
#pragma unroll
        for (int j = 0; j < 10; j++) {
            int i = tid + j * 256;
            if (i < NSL) {
                int wv = s_idx[i];
                const char* src = base + ((size_t)(wv & 0x3FFFF)) * 8;
                int sz = ((wv >> 18) & 1) ? 0 : 8;
                asm volatile("cp.async.ca.shared.global [%0], [%1], 8, %2;"
                             :: "r"(sb + (unsigned)i * 8), "l"(src), "r"(sz));
            }
        }
    };
    auto stage_w = [&](int ch, int buf) {
        const uint4* src = wpk + ch * (WBUF / 2);
        uint32_t sb = smw + buf * (WBUF * 8);
#pragma unroll
        for (int j = 0; j < WITER; j++) {
            int i = tid + j * 256;
            if (i < WBUF / 2)
                asm volatile("cp.async.cg.shared.global [%0], [%1], 16;"
                             :: "r"(sb + (unsigned)i * 16), "l"(src + i));
        }
    };

    float acc0[8][4], acc1[8][4];
#pragma unroll
    for (int i = 0; i < 8; i++)
#pragma unroll
        for (int k = 0; k < 4; k++) { acc0[i][k] = 0.f; acc1[i][k] = 0.f; }

    stage_x(0, 0); stage_w(0, 0);
    asm volatile("cp.async.commit_group;");
    if (NCH > 1) {
        stage_x(1, 1); stage_w(1, 1);
    }
    asm volatile("cp.async.commit_group;");

#pragma unroll 1
    for (int c = 0; c < NCH; c++) {
        if (c + 1 < NCH) asm volatile("cp.async.wait_group 1;");
        else             asm volatile("cp.async.wait_group 0;");
        __syncthreads();
        if (c + 2 < NCH) {
            stage_x(c + 2, (c + 2) % 3); stage_w(c + 2, (c + 2) % 3);
            asm volatile("cp.async.commit_group;");
        }

        const uint2* cx = s_x + (c % 3) * XBUF;
        const uint2* cw = s_w + (c % 3) * WBUF;
#pragma unroll
        for (int kk = 0; kk < 9; kk++) {
            const int ky = kk / 3, kx = kk % 3;
            const uint2* wb = cw + (kk * 4 + t) * WP2;
            uint2 w00 = wb[q], w01 = wb[q + 8];
            uint2 w10 = make_uint2(0, 0), w11 = make_uint2(0, 0);
            if (COUT == 32) { w10 = wb[q + 16]; w11 = wb[q + 24]; }
            const uint2* xb = cx + t * PLANE + ky * 34 + kx + q;
#pragma unroll
            for (int nt = 0; nt < 8; nt++) {
                int r = 2 * warp + (nt >> 2);
                int cb = (nt & 3) * 8;
                uint2 pb = xb[r * 34 + cb];
                mma_bf16(acc0[nt][0], acc0[nt][1], acc0[nt][2], acc0[nt][3],
                         w00.x, w01.x, w00.y, w01.y, pb.x, pb.y);
                if (COUT == 32)
                    mma_bf16(acc1[nt][0], acc1[nt][1], acc1[nt][2], acc1[nt][3],
                             w10.x, w11.x, w10.y, w11.y, pb.x, pb.y);
            }
        }
    }

    float* ob = out + (size_t)b * COUT * HW;
#pragma unroll
    for (int nt = 0; nt < 8; nt++) {
        int h = h0 + 2 * warp + (nt >> 2);
        int w = w0 + (nt & 3) * 8 + 2 * t;
        size_t pix = (size_t)h * WW + w;
        float v[8] = {acc0[nt][0], acc0[nt][1], acc0[nt][2], acc0[nt][3],
                      acc1[nt][0], acc1[nt][1], acc1[nt][2], acc1[nt][3]};
#pragma unroll
        for (int m = 0; m < (COUT == 32 ? 4 : 2); m++) {
            float v0 = v[m * 2], v1 = v[m * 2 + 1];
            if (RELU) { v0 = fmaxf(v0, 0.f); v1 = fmaxf(v1, 0.f); }
            int co = (m & 1) * 8 + (m >> 1) * 16 + q;
            *(float2*)&ob[(size_t)co * HW + pix] = make_float2(v0, v1);
        }
    }
}

// ---------------- att2 conv: planar f32 input, bf16 convert at stage ---------
__global__ __launch_bounds__(256, 2)
void conv3x3_att2(const float* __restrict__ in, const uint4* __restrict__ wpk,
                  float* __restrict__ out) {
    constexpr int PLANE = 612;
    constexpr int WP2 = 20;
    __shared__ uint2 s_x[4 * PLANE];
    __shared__ uint2 s_w[9 * 4 * WP2];

    const int tid = threadIdx.x;
    const int lane = tid & 31, warp = tid >> 5;
    const int q = lane >> 2, t = lane & 3;
    const int w0 = blockIdx.x * 32, h0 = blockIdx.y * 16, b = blockIdx.z;

    const float* inb = in + (size_t)b * 16 * HW;
    for (int i = tid; i < 4 * 612; i += 256) {
        int tt = i / 612, pos = i % 612;
        int y = pos / 34, xx = pos % 34;
        int gh = h0 + y - 1, gw = w0 + xx - 1;
        bool ok = (gh >= 0) && (gh < HH) && (gw >= 0) && (gw < WW);
        size_t o = (size_t)gh * WW + gw;
        float v0 = 0.f, v1 = 0.f, v2 = 0.f, v3 = 0.f;
        if (ok) {
            v0 = inb[(size_t)(2 * tt) * HW + o];
            v1 = inb[(size_t)(2 * tt + 1) * HW + o];
            v2 = inb[(size_t)(2 * tt + 8) * HW + o];
            v3 = inb[(size_t)(2 * tt + 9) * HW + o];
        }
        s_x[tt * PLANE + pos] = make_uint2(pbf(v0, v1), pbf(v2, v3));
    }
    for (int i = tid; i < 9 * 4 * WP2 / 2; i += 256)
        ((uint4*)s_w)[i] = wpk[i];
    __syncthreads();

    float acc[8][4];
#pragma unroll
    for (int i = 0; i < 8; i++) { acc[i][0]=0.f; acc[i][1]=0.f; acc[i][2]=0.f; acc[i][3]=0.f; }

#pragma unroll
    for (int kk = 0; kk < 9; kk++) {
        const int ky = kk / 3, kx = kk % 3;
        const uint2* wb = s_w + (kk * 4 + t) * WP2;
        uint2 w00 = wb[q], w01 = wb[q + 8];
        const uint2* xb = s_x + t * PLANE + ky * 34 + kx + q;
#pragma unroll
        for (int nt = 0; nt < 8; nt++) {
            int r = 2 * warp + (nt >> 2);
            int cb = (nt & 3) * 8;
            uint2 pb = xb[r * 34 + cb];
            mma_bf16(acc[nt][0], acc[nt][1], acc[nt][2], acc[nt][3],
                     w00.x, w01.x, w00.y, w01.y, pb.x, pb.y);
        }
    }

    float* ob = out + (size_t)b * 16 * HW;
#pragma unroll
    for (int nt = 0; nt < 8; nt++) {
        int h = h0 + 2 * warp + (nt >> 2);
        int w = w0 + (nt & 3) * 8 + 2 * t;
        size_t pix = (size_t)h * WW + w;
        float v0 = fmaxf(acc[nt][0], 0.f), v1 = fmaxf(acc[nt][1], 0.f);
        float v2 = fmaxf(acc[nt][2], 0.f), v3 = fmaxf(acc[nt][3], 0.f);
        *(float2*)&ob[(size_t)q * HW + pix] = make_float2(v0, v1);
        *(float2*)&ob[(size_t)(q + 8) * HW + pix] = make_float2(v2, v3);
    }
}

// ---------------- attention 1x1 conv (16 -> 4) + bias + sigmoid -------------
__global__ void weight_kernel(const float* __restrict__ att2,
                              const float* __restrict__ w3,
                              const float* __restrict__ b3,
                              float* __restrict__ wmap) {
    int idx = blockIdx.x * blockDim.x + threadIdx.x;
    if (idx >= BB * HW) return;
    int b = idx / HW, p = idx % HW;
    const float* base = att2 + (size_t)b * 16 * HW + p;
    float v[16];
#pragma unroll
    for (int c = 0; c < 16; c++) v[c] = base[(size_t)c * HW];
#pragma unroll
    for (int d = 0; d < 4; d++) {
        float s = b3[d];
#pragma unroll
        for (int c = 0; c < 16; c++) s += v[c] * w3[d * 16 + c];
        wmap[((size_t)b * 4 + d) * HW + p] = 1.f / (1.f + expf(-s));
    }
}

// ---------------- final 1x1 conv (32 -> 1) + sigmoid -------------------------
__global__ void final_kernel(const float* __restrict__ in,
                             const float* __restrict__ w_out,
                             float* __restrict__ out) {
    int idx = blockIdx.x * blockDim.x + threadIdx.x;
    if (idx >= BB * HW) return;
    int b = idx / HW, p = idx % HW;
    const float* base = in + (size_t)b * CC * HW + p;
    float s = 0.f;
#pragma unroll
    for (int c = 0; c < CC; c++) s += base[(size_t)c * HW] * w_out[c];
    out[idx] = 1.f / (1.f + expf(-s));
}

// ---------------- vertical scans: 4 channels/thread, bf16-packed output ------
// dirs 0 (top->down) and 2 (down->top). grid (BB, 8, 4): pg -> (ch, t)
__global__ void scan_vert(const float* __restrict__ x,
                          const float* __restrict__ alpha,
                          const float* __restrict__ wmap,
                          uint2* __restrict__ gated2) {
    int b = blockIdx.x, pg = blockIdx.y, cn = blockIdx.z;
    int ch = pg >> 2, t = pg & 3;
    int cb = ch * 16 + 2 * t;
    int w = threadIdx.x;
    float a0 = alpha[cb], a1 = alpha[cb + 1], a2 = alpha[cb + 8], a3 = alpha[cb + 9];
    const float* x0 = x + ((size_t)(b * CC + cb)) * HW + w;
    const float* x1 = x0 + (size_t)HW;
    const float* x2p = x0 + (size_t)8 * HW;
    const float* x3 = x0 + (size_t)9 * HW;
    const float* wm0 = wmap + ((size_t)b * 4 + 0) * HW + w;
    const float* wm2 = wmap + ((size_t)b * 4 + 2) * HW + w;
    uint2* g0 = gated2 + ((size_t)((b * 8 + 0 + ch) * 4 + t)) * HW + w;
    uint2* g2 = gated2 + ((size_t)((b * 8 + 4 + ch) * 4 + t)) * HW + w;
    int h0 = cn * 64;

    float p0 = 0.f, p1 = 0.f, p2 = 0.f, p3 = 0.f;
#pragma unroll 2
    for (int h = max(0, h0 - 16); h < h0 + 64; h++) {
        size_t o = (size_t)h * WW;
        float v0 = fmaxf(x0[o] + a0 * p0, 0.f);
        float v1 = fmaxf(x1[o] + a1 * p1, 0.f);
        float v2 = fmaxf(x2p[o] + a2 * p2, 0.f);
        float v3 = fmaxf(x3[o] + a3 * p3, 0.f);
        if (h >= h0) {
            float m = wm0[o];
            g0[o] = make_uint2(pbf(v0 * m, v1 * m), pbf(v2 * m, v3 * m));
        }
        p0 = v0; p1 = v1; p2 = v2; p3 = v3;
    }
    p0 = p1 = p2 = p3 = 0.f;
#pragma unroll 2
    for (int h = min(HH - 1, h0 + 63 + 16); h >= h0; h--) {
        size_t o = (size_t)h * WW;
        float v0 = fmaxf(x0[o] + a0 * p0, 0.f);
        float v1 = fmaxf(x1[o] + a1 * p1, 0.f);
        float v2 = fmaxf(x2p[o] + a2 * p2, 0.f);
        float v3 = fmaxf(x3[o] + a3 * p3, 0.f);
        if (h < h0 + 64) {
            float m = wm2[o];
            g2[o] = make_uint2(pbf(v0 * m, v1 * m), pbf(v2 * m, v3 * m));
        }
        p0 = v0; p1 = v1; p2 = v2; p3 = v3;
    }
}

// ---------------- horizontal scans: dirs 1, 3; 4 ch x 8 rows per block -------
// grid (BB, 8, 32): pg -> (ch, t); z = 8-row block. 32-col chunks, warm 16.
#define HST 265
__global__ __launch_bounds__(256, 2)
void scan_horiz(const float* __restrict__ x, const float* __restrict__ alpha,
                const float* __restrict__ wmap, uint2* __restrict__ gated2) {
    extern __shared__ float sh[];
    float* tin = sh;                       // [4][8][HST] col-skewed
    float* tf  = sh + 4 * 8 * HST;
    float* tr  = sh + 8 * 8 * HST;

    int b = blockIdx.x, pg = blockIdx.y, rb = blockIdx.z;
    int ch = pg >> 2, t = pg & 3;
    int cb = ch * 16 + 2 * t;
    int R0 = rb * 8;
    const int tid = threadIdx.x;
    float av[4] = {alpha[cb], alpha[cb + 1], alpha[cb + 8], alpha[cb + 9]};
    const int coff[4] = {0, 1, 8, 9};

    for (int i = tid; i < 4 * 8 * 256; i += 256) {
        int ci = i >> 11, r = (i >> 8) & 7, col = i & 255;
        float v = x[((size_t)(b * CC + cb + coff[ci])) * HW + (size_t)(R0 + r) * WW + col];
        tin[(ci * 8 + r) * HST + col + (col >> 5)] = v;
    }
    __syncthreads();

    if (tid < 128) {
        int dir = tid >> 6, rem = tid & 63;
        int r = rem & 7, chunk = rem >> 3;
        int base = chunk * 32;
        float* dst = dir ? tr : tf;
        float p[4] = {0.f, 0.f, 0.f, 0.f};
        if (!dir) {
            for (int col = max(0, base - 16); col < base + 32; col++) {
                int cs = col + (col >> 5);
#pragma unroll
                for (int ci = 0; ci < 4; ci++) {
                    float v = fmaxf(tin[(ci * 8 + r) * HST + cs] + av[ci] * p[ci], 0.f);
                    if (col >= base) dst[(ci * 8 + r) * HST + cs] = v;
                    p[ci] = v;
                }
            }
        } else {
            for (int col = min(255, base + 47); col >= base; col--) {
                int cs = col + (col >> 5);
#pragma unroll
                for (int ci = 0; ci < 4; ci++) {
                    float v = fmaxf(tin[(ci * 8 + r) * HST + cs] + av[ci] * p[ci], 0.f);
                    if (col < base + 32) dst[(ci * 8 + r) * HST + cs] = v;
                    p[ci] = v;
                }
            }
        }
    }
    __syncthreads();

    const float* wm1 = wmap + ((size_t)b * 4 + 1) * HW + (size_t)R0 * WW;
    const float* wm3 = wmap + ((size_t)b * 4 + 3) * HW + (size_t)R0 * WW;
    uint2* g1 = gated2 + ((size_t)((b * 8 + 2 + ch) * 4 + t)) * HW + (size_t)R0 * WW;
    uint2* g3 = gated2 + ((size_t)((b * 8 + 6 + ch) * 4 + t)) * HW + (size_t)R0 * WW;
    for (int i = tid; i < 8 * 256; i += 256) {
        int r = i >> 8, col = i & 255;
        int cs = col + (col >> 5);
        float m1 = wm1[i], m3 = wm3[i];
        g1[i] = make_uint2(pbf(tf[(0 * 8 + r) * HST + cs] * m1, tf[(1 * 8 + r) * HST + cs] * m1),
                           pbf(tf[(2 * 8 + r) * HST + cs] * m1, tf[(3 * 8 + r) * HST + cs] * m1));
        g3[i] = make_uint2(pbf(tr[(0 * 8 + r) * HST + cs] * m3, tr[(1 * 8 + r) * HST + cs] * m3),
                           pbf(tr[(2 * 8 + r) * HST + cs] * m3, tr[(3 * 8 + r) * HST + cs] * m3));
    }
}

// ---------------- launch ------------------------------------------------------
extern "C" void kernel_launch(void* const* d_in, const int* in_sizes, int n_in,
                              void* d_out, int out_size) {
    const float* x      = (const float*)d_in[0];
    const float* alpha1 = (const float*)d_in[1];
    const float* alpha2 = (const float*)d_in[2];
    const float* w_in   = (const float*)d_in[3];
    const float* w2     = (const float*)d_in[4];
    const float* w3     = (const float*)d_in[5];
    const float* att_w1 = (const float*)d_in[6];
    const float* att_w2 = (const float*)d_in[7];
    const float* att_w3 = (const float*)d_in[8];
    const float* att_b3 = (const float*)d_in[9];
    const float* w_out  = (const float*)d_in[10];
    float* out = (float*)d_out;

    float *bufA, *wmap;
    uint2 *gated2, *x2;
    uint4* wp;
    cudaGetSymbolAddress((void**)&bufA, g_bufA);
    cudaGetSymbolAddress((void**)&gated2, g_gated2);
    cudaGetSymbolAddress((void**)&wmap, g_wmap);
    cudaGetSymbolAddress((void**)&x2, g_x2);
    cudaGetSymbolAddress((void**)&wp, g_wp);

    constexpr int SMP32 = 3 * (2448 + 9 * 4 * 36) * 8 + 2448 * 4;   // 99648
    constexpr int SMP16 = 3 * (2448 + 9 * 4 * 20) * 8 + 2448 * 4;   // 85824
    constexpr int SMH   = 12 * 8 * HST * 4;                          // 101760
    cudaFuncSetAttribute(conv3x3_pair<32, 32, false>, cudaFuncAttributeMaxDynamicSharedMemorySize, SMP32);
    cudaFuncSetAttribute(conv3x3_pair<128, 32, false>, cudaFuncAttributeMaxDynamicSharedMemorySize, SMP32);
    cudaFuncSetAttribute(conv3x3_pair<128, 32, true>, cudaFuncAttributeMaxDynamicSharedMemorySize, SMP32);
    cudaFuncSetAttribute(conv3x3_pair<32, 16, true>, cudaFuncAttributeMaxDynamicSharedMemorySize, SMP16);
    cudaFuncSetAttribute(scan_horiz, cudaFuncAttributeMaxDynamicSharedMemorySize, SMH);

    // attention scratch: planar f32 at head of gated2 region (used before gating)
    float* att1 = (float*)gated2;
    float* att2 = (float*)gated2 + (size_t)BB * 16 * HW;

    // setup
    repack_x<<<BB * 8 * HW / 256, 256>>>(x, x2);
    prepack_w<<<(2 * 9 * 4 * 36 + 255) / 256, 256>>>(w_in, (uint2*)(wp + WP_WIN), 32, 32, 36);
    prepack_w<<<(8 * 9 * 4 * 36 + 255) / 256, 256>>>(w2, (uint2*)(wp + WP_W2), 128, 32, 36);
    prepack_w<<<(8 * 9 * 4 * 36 + 255) / 256, 256>>>(w3, (uint2*)(wp + WP_W3), 128, 32, 36);
    prepack_w<<<(2 * 9 * 4 * 20 + 255) / 256, 256>>>(att_w1, (uint2*)(wp + WP_AW1), 32, 16, 20);
    prepack_w<<<(1 * 9 * 4 * 20 + 255) / 256, 256>>>(att_w2, (uint2*)(wp + WP_AW2), 16, 16, 20);

    dim3 blk(256);
    dim3 gc(WW / 32, HH / 16, BB);

    // attention branch
    conv3x3_pair<32, 16, true><<<gc, blk, SMP16>>>(x2, wp + WP_AW1, att1);
    conv3x3_att2<<<gc, blk>>>(att1, wp + WP_AW2, att2);
    weight_kernel<<<(BB * HW + 255) / 256, 256>>>(att2, att_w3, att_b3, wmap);

    // main trunk
    conv3x3_pair<32, 32, false><<<gc, blk, SMP32>>>(x2, wp + WP_WIN, bufA);

    scan_vert<<<dim3(BB, 8, 4), 256>>>(bufA, alpha1, wmap, gated2);
    scan_horiz<<<dim3(BB, 8, 32), 256, SMH>>>(bufA, alpha1, wmap, gated2);

    conv3x3_pair<128, 32, false><<<gc, blk, SMP32>>>(gated2, wp + WP_W2, bufA);

    scan_vert<<<dim3(BB, 8, 4), 256>>>(bufA, alpha2, wmap, gated2);
    scan_horiz<<<dim3(BB, 8, 32), 256, SMH>>>(bufA, alpha2, wmap, gated2);

    conv3x3_pair<128, 32, true><<<gc, blk, SMP32>>>(gated2, wp + WP_W3, bufA);

    final_kernel<<<(BB * HW + 255) / 256, 256>>>(bufA, w_out, out);
}

// round 7
// speedup vs baseline: 4.4268x; 1.0527x over previous
#include <cuda_runtime.h>
#include <cuda_bf16.h>
#include <math.h>
#include <stdint.h>

#define BB 8
#define CC 32
#define HH 256
#define WW 256
#define HW (HH*WW)

// ---------------- scratch (device globals; no allocations allowed) ----------
__device__ __nv_bfloat16 g_bufA[(size_t)BB * CC * HW];   // 32 MiB: conv outputs (planar bf16)
__device__ uint2 g_gated2[(size_t)BB * 8 * 4 * HW];      // 128 MiB: gated concat, bf16 pair layout
__device__ float g_wmap[(size_t)BB * 4 * HW];            // 8 MiB: sigmoid gate maps
__device__ uint2 g_x2[(size_t)BB * 2 * 4 * HW];          // 32 MiB: bf16-packed x
__device__ uint4 g_wp[16384];                            // prepacked bf16 weights (smem images)
__device__ __nv_bfloat16 g_att1[(size_t)BB * 16 * HW];   // 16 MiB: att1 (planar bf16)

// g_wp offsets in uint4 units
#define WP_WIN 0
#define WP_W2  1296
#define WP_W3  6480
#define WP_AW1 11664
#define WP_AW2 12384

__device__ __forceinline__ uint32_t pbf(float lo, float hi) {
    uint32_t r;
    asm("cvt.rn.bf16x2.f32 %0, %1, %2;" : "=r"(r) : "f"(hi), "f"(lo));
    return r;
}

__device__ __forceinline__ void mma_bf16(float& d0, float& d1, float& d2, float& d3,
                                         uint32_t a0, uint32_t a1, uint32_t a2, uint32_t a3,
                                         uint32_t b0, uint32_t b1) {
    asm volatile(
        "mma.sync.aligned.m16n8k16.row.col.f32.bf16.bf16.f32 "
        "{%0,%1,%2,%3}, {%4,%5,%6,%7}, {%8,%9}, {%0,%1,%2,%3};"
        : "+f"(d0), "+f"(d1), "+f"(d2), "+f"(d3)
        : "r"(a0), "r"(a1), "r"(a2), "r"(a3), "r"(b0), "r"(b1));
}

// ---------------- setup: pack x into bf16 pair layout ------------------------
__global__ void repack_x(const float* __restrict__ x, uint2* __restrict__ x2) {
    size_t i = (size_t)blockIdx.x * 256 + threadIdx.x;
    int p = (int)(i & (HW - 1));
    int pl = (int)(i >> 16);
    int b = pl >> 3, ch = (pl >> 2) & 1, t = pl & 3;
    const float* s = x + ((size_t)(b * CC + ch * 16 + 2 * t)) * HW + p;
    uint2 v;
    v.x = pbf(s[0], s[(size_t)HW]);
    v.y = pbf(s[(size_t)8 * HW], s[(size_t)9 * HW]);
    x2[i] = v;
}

// ---------------- setup: prepack weights into per-chunk smem images ----------
__global__ void prepack_w(const float* __restrict__ w, uint2* __restrict__ dst,
                          int CIN, int COUT, int WP2) {
    int NCH = CIN >> 4;
    int total = NCH * 9 * 4 * WP2;
    int i = blockIdx.x * 256 + threadIdx.x;
    if (i >= total) return;
    int wp = i % WP2; int rem = i / WP2;
    int t = rem & 3; rem >>= 2; int kk = rem % 9; int ch = rem / 9;
    uint2 v = make_uint2(0u, 0u);
    if (wp < COUT) {
        int cb = ch * 16 + 2 * t;
        v.x = pbf(w[((size_t)wp * CIN + cb) * 9 + kk],     w[((size_t)wp * CIN + cb + 1) * 9 + kk]);
        v.y = pbf(w[((size_t)wp * CIN + cb + 8) * 9 + kk], w[((size_t)wp * CIN + cb + 9) * 9 + kk]);
    }
    dst[i] = v;
}

// ---------------- bf16 tensor-core 3x3 conv (pair-layout input) --------------
// MODE 1: store planar bf16.  MODE 2: fuse 1x1 conv (aux=w_out) + sigmoid,
// warp-shuffle channel reduce, write f32 mask (COUT=32 only).
template <int CIN, int COUT, bool RELU, int MODE>
__global__ __launch_bounds__(256, 2)
void conv3x3_pair(const uint2* __restrict__ in2, const uint4* __restrict__ wpk,
                  void* __restrict__ outp, const float* __restrict__ aux) {
    constexpr int PLANE = 612;
    constexpr int WP2 = COUT + 4;
    constexpr int XBUF = 4 * PLANE;
    constexpr int WBUF = 9 * 4 * WP2;
    constexpr int NCH = CIN / 16;
    constexpr int NSL = 4 * 612;
    constexpr int WITER = (WBUF / 2 + 255) / 256;

    extern __shared__ uint2 sm[];
    uint2* s_x = sm;
    uint2* s_w = sm + 3 * XBUF;
    int* s_idx = (int*)(sm + 3 * (XBUF + WBUF));

    const int tid = threadIdx.x;
    const int lane = tid & 31, warp = tid >> 5;
    const int q = lane >> 2, t = lane & 3;
    const int w0 = blockIdx.x * 32, h0 = blockIdx.y * 16, b = blockIdx.z;

    for (int i = tid; i < NSL; i += 256) {
        int tt = i / 612, pos = i % 612;
        int y = pos / 34, xx = pos % 34;
        int gh = h0 + y - 1, gw = w0 + xx - 1;
        bool ok = (gh >= 0) && (gh < HH) && (gw >= 0) && (gw < WW);
        int ghc = min(max(gh, 0), HH - 1), gwc = min(max(gw, 0), WW - 1);
        int off8 = tt * HW + ghc * WW + gwc;
        s_idx[i] = off8 | ((ok ? 0 : 1) << 18);
    }

    const uint32_t smx = (uint32_t)__cvta_generic_to_shared(s_x);
    const uint32_t smw = (uint32_t)__cvta_generic_to_shared(s_w);

    auto stage_x = [&](int ch, int buf) {
        const char* base = (const char*)in2 + ((size_t)b * NCH + ch) * 4 * HW * 8;
        uint32_t sb = smx + buf * (XBUF * 8);
#pragma unroll
        for (int j = 0; j < 10; j++) {
            int i = tid + j * 256;
            if (i < NSL) {
                int wv = s_idx[i];
                const char* src = base + ((size_t)(wv & 0x3FFFF)) * 8;
                int sz = ((wv >> 18) & 1) ? 0 : 8;
                asm volatile("cp.async.ca.shared.global [%0], [%1], 8, %2;"
                             :: "r"(sb + (unsigned)i * 8), "l"(src), "r"(sz));
            }
        }
    };
    auto stage_w = [&](int ch, int buf) {
        const uint4* src = wpk + ch * (WBUF / 2);
        uint32_t sb = smw + buf * (WBUF * 8);
#pragma unroll
        for (int j = 0; j < WITER; j++) {
            int i = tid + j * 256;
            if (i < WBUF / 2)
                asm volatile("cp.async.cg.shared.global [%0], [%1], 16;"
                             :: "r"(sb + (unsigned)i * 16), "l"(src + i));
        }
    };

    float acc0[8][4], acc1[8][4];
#pragma unroll
    for (int i = 0; i < 8; i++)
#pragma unroll
        for (int k = 0; k < 4; k++) { acc0[i][k] = 0.f; acc1[i][k] = 0.f; }

    stage_x(0, 0); stage_w(0, 0);
    asm volatile("cp.async.commit_group;");
    if (NCH > 1) { stage_x(1, 1); stage_w(1, 1); }
    asm volatile("cp.async.commit_group;");

#pragma unroll 1
    for (int c = 0; c < NCH; c++) {
        if (c + 1 < NCH) asm volatile("cp.async.wait_group 1;");
        else             asm volatile("cp.async.wait_group 0;");
        __syncthreads();
        if (c + 2 < NCH) {
            stage_x(c + 2, (c + 2) % 3); stage_w(c + 2, (c + 2) % 3);
            asm volatile("cp.async.commit_group;");
        }

        const uint2* cx = s_x + (c % 3) * XBUF;
        const uint2* cw = s_w + (c % 3) * WBUF;
#pragma unroll
        for (int kk = 0; kk < 9; kk++) {
            const int ky = kk / 3, kx = kk % 3;
            const uint2* wb = cw + (kk * 4 + t) * WP2;
            uint2 w00 = wb[q], w01 = wb[q + 8];
            uint2 w10 = make_uint2(0, 0), w11 = make_uint2(0, 0);
            if (COUT == 32) { w10 = wb[q + 16]; w11 = wb[q + 24]; }
            const uint2* xb = cx + t * PLANE + ky * 34 + kx + q;
#pragma unroll
            for (int nt = 0; nt < 8; nt++) {
                int r = 2 * warp + (nt >> 2);
                int cb = (nt & 3) * 8;
                uint2 pb = xb[r * 34 + cb];
                mma_bf16(acc0[nt][0], acc0[nt][1], acc0[nt][2], acc0[nt][3],
                         w00.x, w01.x, w00.y, w01.y, pb.x, pb.y);
                if (COUT == 32)
                    mma_bf16(acc1[nt][0], acc1[nt][1], acc1[nt][2], acc1[nt][3],
                             w10.x, w11.x, w10.y, w11.y, pb.x, pb.y);
            }
        }
    }

    if (MODE == 1) {
        __nv_bfloat16* ob = (__nv_bfloat16*)outp + (size_t)b * COUT * HW;
#pragma unroll
        for (int nt = 0; nt < 8; nt++) {
            int h = h0 + 2 * warp + (nt >> 2);
            int w = w0 + (nt & 3) * 8 + 2 * t;
            size_t pix = (size_t)h * WW + w;
            float v[8] = {acc0[nt][0], acc0[nt][1], acc0[nt][2], acc0[nt][3],
                          acc1[nt][0], acc1[nt][1], acc1[nt][2], acc1[nt][3]};
#pragma unroll
            for (int m = 0; m < (COUT == 32 ? 4 : 2); m++) {
                float v0 = v[m * 2], v1 = v[m * 2 + 1];
                if (RELU) { v0 = fmaxf(v0, 0.f); v1 = fmaxf(v1, 0.f); }
                int co = (m & 1) * 8 + (m >> 1) * 16 + q;
                *(uint32_t*)&ob[(size_t)co * HW + pix] = pbf(v0, v1);
            }
        }
    } else {
        // MODE 2: fused 1x1 conv (w_out) + sigmoid -> f32 mask
        float wo0 = aux[q], wo1 = aux[q + 8], wo2 = aux[q + 16], wo3 = aux[q + 24];
        float* om = (float*)outp + (size_t)b * HW;
#pragma unroll
        for (int nt = 0; nt < 8; nt++) {
            int h = h0 + 2 * warp + (nt >> 2);
            int w = w0 + (nt & 3) * 8 + 2 * t;
            float v[8] = {acc0[nt][0], acc0[nt][1], acc0[nt][2], acc0[nt][3],
                          acc1[nt][0], acc1[nt][1], acc1[nt][2], acc1[nt][3]};
#pragma unroll
            for (int i = 0; i < 8; i++) v[i] = fmaxf(v[i], 0.f);
            float s0 = v[0] * wo0 + v[2] * wo1 + v[4] * wo2 + v[6] * wo3;
            float s1 = v[1] * wo0 + v[3] * wo1 + v[5] * wo2 + v[7] * wo3;
#pragma unroll
            for (int off = 4; off < 32; off <<= 1) {
                s0 += __shfl_xor_sync(0xffffffffu, s0, off);
                s1 += __shfl_xor_sync(0xffffffffu, s1, off);
            }
            if (q == 0) {
                float2 rr = make_float2(1.f / (1.f + expf(-s0)), 1.f / (1.f + expf(-s1)));
                *(float2*)&om[(size_t)h * WW + w] = rr;
            }
        }
    }
}

// ---------------- att2 conv (bf16 planar in) + fused 1x1->4 + sigmoid --------
__global__ __launch_bounds__(256, 2)
void conv3x3_att2(const __nv_bfloat16* __restrict__ in, const uint4* __restrict__ wpk,
                  const float* __restrict__ w3, const float* __restrict__ b3,
                  float* __restrict__ wmap) {
    constexpr int PLANE = 612;
    constexpr int WP2 = 20;
    __shared__ uint2 s_x[4 * PLANE];
    __shared__ uint2 s_w[9 * 4 * WP2];

    const int tid = threadIdx.x;
    const int lane = tid & 31, warp = tid >> 5;
    const int q = lane >> 2, t = lane & 3;
    const int w0 = blockIdx.x * 32, h0 = blockIdx.y * 16, b = blockIdx.z;

    const uint16_t* inb = (const uint16_t*)in + (size_t)b * 16 * HW;
    for (int i = tid; i < 4 * 612; i += 256) {
        int tt = i / 612, pos = i % 612;
        int y = pos / 34, xx = pos % 34;
        int gh = h0 + y - 1, gw = w0 + xx - 1;
        bool ok = (gh >= 0) && (gh < HH) && (gw >= 0) && (gw < WW);
        uint32_t wa = 0, wbv = 0;
        if (ok) {
            size_t o = (size_t)gh * WW + gw;
            uint32_t c0 = inb[(size_t)(2 * tt) * HW + o];
            uint32_t c1 = inb[(size_t)(2 * tt + 1) * HW + o];
            uint32_t c8 = inb[(size_t)(2 * tt + 8) * HW + o];
            uint32_t c9 = inb[(size_t)(2 * tt + 9) * HW + o];
            wa = c0 | (c1 << 16);
            wbv = c8 | (c9 << 16);
        }
        s_x[tt * PLANE + pos] = make_uint2(wa, wbv);
    }
    for (int i = tid; i < 9 * 4 * WP2 / 2; i += 256)
        ((uint4*)s_w)[i] = wpk[i];
    __syncthreads();

    float acc[8][4];
#pragma unroll
    for (int i = 0; i < 8; i++) { acc[i][0]=0.f; acc[i][1]=0.f; acc[i][2]=0.f; acc[i][3]=0.f; }

#pragma unroll
    for (int kk = 0; kk < 9; kk++) {
        const int ky = kk / 3, kx = kk % 3;
        const uint2* wb = s_w + (kk * 4 + t) * WP2;
        uint2 w00 = wb[q], w01 = wb[q + 8];
        const uint2* xb = s_x + t * PLANE + ky * 34 + kx + q;
#pragma unroll
        for (int nt = 0; nt < 8; nt++) {
            int r = 2 * warp + (nt >> 2);
            int cb = (nt & 3) * 8;
            uint2 pb = xb[r * 34 + cb];
            mma_bf16(acc[nt][0], acc[nt][1], acc[nt][2], acc[nt][3],
                     w00.x, w01.x, w00.y, w01.y, pb.x, pb.y);
        }
    }

    // fused: relu -> 1x1 conv (16->4) + bias -> sigmoid -> wmap
    float w3a[4], w3b[4], b3v[4];
#pragma unroll
    for (int d = 0; d < 4; d++) {
        w3a[d] = w3[d * 16 + q];
        w3b[d] = w3[d * 16 + q + 8];
        b3v[d] = b3[d];
    }
    float* wm = wmap + (size_t)b * 4 * HW;
#pragma unroll
    for (int nt = 0; nt < 8; nt++) {
        int h = h0 + 2 * warp + (nt >> 2);
        int w = w0 + (nt & 3) * 8 + 2 * t;
        float v0 = fmaxf(acc[nt][0], 0.f), v1 = fmaxf(acc[nt][1], 0.f);
        float v2 = fmaxf(acc[nt][2], 0.f), v3 = fmaxf(acc[nt][3], 0.f);
#pragma unroll
        for (int d = 0; d < 4; d++) {
            float s0 = v0 * w3a[d] + v2 * w3b[d];
            float s1 = v1 * w3a[d] + v3 * w3b[d];
#pragma unroll
            for (int off = 4; off < 32; off <<= 1) {
                s0 += __shfl_xor_sync(0xffffffffu, s0, off);
                s1 += __shfl_xor_sync(0xffffffffu, s1, off);
            }
            if (q == 0) {
                float2 rr = make_float2(1.f / (1.f + expf(-(s0 + b3v[d]))),
                                        1.f / (1.f + expf(-(s1 + b3v[d]))));
                *(float2*)&wm[(size_t)d * HW + (size_t)h * WW + w] = rr;
            }
        }
    }
}

// ---------------- vertical scans: bf16 input, bf16-packed gated output -------
__global__ void scan_vert(const __nv_bfloat16* __restrict__ x,
                          const float* __restrict__ alpha,
                          const float* __restrict__ wmap,
                          uint2* __restrict__ gated2) {
    int b = blockIdx.x, pg = blockIdx.y, cn = blockIdx.z;
    int ch = pg >> 2, t = pg & 3;
    int cb = ch * 16 + 2 * t;
    int w = threadIdx.x;
    float a0 = alpha[cb], a1 = alpha[cb + 1], a2 = alpha[cb + 8], a3 = alpha[cb + 9];
    const __nv_bfloat16* x0 = x + ((size_t)(b * CC + cb)) * HW + w;
    const __nv_bfloat16* x1 = x0 + (size_t)HW;
    const __nv_bfloat16* x2p = x0 + (size_t)8 * HW;
    const __nv_bfloat16* x3 = x0 + (size_t)9 * HW;
    const float* wm0 = wmap + ((size_t)b * 4 + 0) * HW + w;
    const float* wm2 = wmap + ((size_t)b * 4 + 2) * HW + w;
    uint2* g0 = gated2 + ((size_t)((b * 8 + 0 + ch) * 4 + t)) * HW + w;
    uint2* g2 = gated2 + ((size_t)((b * 8 + 4 + ch) * 4 + t)) * HW + w;
    int h0 = cn * 64;

    float p0 = 0.f, p1 = 0.f, p2 = 0.f, p3 = 0.f;
#pragma unroll 2
    for (int h = max(0, h0 - 16); h < h0 + 64; h++) {
        size_t o = (size_t)h * WW;
        float v0 = fmaxf(__bfloat162float(x0[o]) + a0 * p0, 0.f);
        float v1 = fmaxf(__bfloat162float(x1[o]) + a1 * p1, 0.f);
        float v2 = fmaxf(__bfloat162float(x2p[o]) + a2 * p2, 0.f);
        float v3 = fmaxf(__bfloat162float(x3[o]) + a3 * p3, 0.f);
        if (h >= h0) {
            float m = wm0[o];
            g0[o] = make_uint2(pbf(v0 * m, v1 * m), pbf(v2 * m, v3 * m));
        }
        p0 = v0; p1 = v1; p2 = v2; p3 = v3;
    }
    p0 = p1 = p2 = p3 = 0.f;
#pragma unroll 2
    for (int h = min(HH - 1, h0 + 63 + 16); h >= h0; h--) {
        size_t o = (size_t)h * WW;
        float v0 = fmaxf(__bfloat162float(x0[o]) + a0 * p0, 0.f);
        float v1 = fmaxf(__bfloat162float(x1[o]) + a1 * p1, 0.f);
        float v2 = fmaxf(__bfloat162float(x2p[o]) + a2 * p2, 0.f);
        float v3 = fmaxf(__bfloat162float(x3[o]) + a3 * p3, 0.f);
        if (h < h0 + 64) {
            float m = wm2[o];
            g2[o] = make_uint2(pbf(v0 * m, v1 * m), pbf(v2 * m, v3 * m));
        }
        p0 = v0; p1 = v1; p2 = v2; p3 = v3;
    }
}

// ---------------- horizontal scans: bf16 input ------------------------------
#define HST 265
__global__ __launch_bounds__(256, 2)
void scan_horiz(const __nv_bfloat16* __restrict__ x, const float* __restrict__ alpha,
                const float* __restrict__ wmap, uint2* __restrict__ gated2) {
    extern __shared__ float sh[];
    float* tin = sh;
    float* tf  = sh + 4 * 8 * HST;
    float* tr  = sh + 8 * 8 * HST;

    int b = blockIdx.x, pg = blockIdx.y, rb = blockIdx.z;
    int ch = pg >> 2, t = pg & 3;
    int cb = ch * 16 + 2 * t;
    int R0 = rb * 8;
    const int tid = threadIdx.x;
    float av[4] = {alpha[cb], alpha[cb + 1], alpha[cb + 8], alpha[cb + 9]};
    const int coff[4] = {0, 1, 8, 9};

    for (int i = tid; i < 4 * 8 * 256; i += 256) {
        int ci = i >> 11, r = (i >> 8) & 7, col = i & 255;
        float v = __bfloat162float(
            x[((size_t)(b * CC + cb + coff[ci])) * HW + (size_t)(R0 + r) * WW + col]);
        tin[(ci * 8 + r) * HST + col + (col >> 5)] = v;
    }
    __syncthreads();

    if (tid < 128) {
        int dir = tid >> 6, rem = tid & 63;
        int r = rem & 7, chunk = rem >> 3;
        int base = chunk * 32;
        float* dst = dir ? tr : tf;
        float p[4] = {0.f, 0.f, 0.f, 0.f};
        if (!dir) {
            for (int col = max(0, base - 16); col < base + 32; col++) {
                int cs = col + (col >> 5);
#pragma unroll
                for (int ci = 0; ci < 4; ci++) {
                    float v = fmaxf(tin[(ci * 8 + r) * HST + cs] + av[ci] * p[ci], 0.f);
                    if (col >= base) dst[(ci * 8 + r) * HST + cs] = v;
                    p[ci] = v;
                }
            }
        } else {
            for (int col = min(255, base + 47); col >= base; col--) {
                int cs = col + (col >> 5);
#pragma unroll
                for (int ci = 0; ci < 4; ci++) {
                    float v = fmaxf(tin[(ci * 8 + r) * HST + cs] + av[ci] * p[ci], 0.f);
                    if (col < base + 32) dst[(ci * 8 + r) * HST + cs] = v;
                    p[ci] = v;
                }
            }
        }
    }
    __syncthreads();

    const float* wm1 = wmap + ((size_t)b * 4 + 1) * HW + (size_t)R0 * WW;
    const float* wm3 = wmap + ((size_t)b * 4 + 3) * HW + (size_t)R0 * WW;
    uint2* g1 = gated2 + ((size_t)((b * 8 + 2 + ch) * 4 + t)) * HW + (size_t)R0 * WW;
    uint2* g3 = gated2 + ((size_t)((b * 8 + 6 + ch) * 4 + t)) * HW + (size_t)R0 * WW;
    for (int i = tid; i < 8 * 256; i += 256) {
        int r = i >> 8, col = i & 255;
        int cs = col + (col >> 5);
        float m1 = wm1[i], m3 = wm3[i];
        g1[i] = make_uint2(pbf(tf[(0 * 8 + r) * HST + cs] * m1, tf[(1 * 8 + r) * HST + cs] * m1),
                           pbf(tf[(2 * 8 + r) * HST + cs] * m1, tf[(3 * 8 + r) * HST + cs] * m1));
        g3[i] = make_uint2(pbf(tr[(0 * 8 + r) * HST + cs] * m3, tr[(1 * 8 + r) * HST + cs] * m3),
                           pbf(tr[(2 * 8 + r) * HST + cs] * m3, tr[(3 * 8 + r) * HST + cs] * m3));
    }
}

// ---------------- launch ------------------------------------------------------
extern "C" void kernel_launch(void* const* d_in, const int* in_sizes, int n_in,
                              void* d_out, int out_size) {
    const float* x      = (const float*)d_in[0];
    const float* alpha1 = (const float*)d_in[1];
    const float* alpha2 = (const float*)d_in[2];
    const float* w_in   = (const float*)d_in[3];
    const float* w2     = (const float*)d_in[4];
    const float* w3     = (const float*)d_in[5];
    const float* att_w1 = (const float*)d_in[6];
    const float* att_w2 = (const float*)d_in[7];
    const float* att_w3 = (const float*)d_in[8];
    const float* att_b3 = (const float*)d_in[9];
    const float* w_out  = (const float*)d_in[10];
    float* out = (float*)d_out;

    __nv_bfloat16 *bufA, *att1;
    float *wmap;
    uint2 *gated2, *x2;
    uint4* wp;
    cudaGetSymbolAddress((void**)&bufA, g_bufA);
    cudaGetSymbolAddress((void**)&gated2, g_gated2);
    cudaGetSymbolAddress((void**)&wmap, g_wmap);
    cudaGetSymbolAddress((void**)&x2, g_x2);
    cudaGetSymbolAddress((void**)&wp, g_wp);
    cudaGetSymbolAddress((void**)&att1, g_att1);

    constexpr int SMP32 = 3 * (2448 + 9 * 4 * 36) * 8 + 2448 * 4;   // 99648
    constexpr int SMP16 = 3 * (2448 + 9 * 4 * 20) * 8 + 2448 * 4;   // 85824
    constexpr int SMH   = 12 * 8 * HST * 4;                          // 101760
    cudaFuncSetAttribute(conv3x3_pair<32, 32, false, 1>, cudaFuncAttributeMaxDynamicSharedMemorySize, SMP32);
    cudaFuncSetAttribute(conv3x3_pair<128, 32, false, 1>, cudaFuncAttributeMaxDynamicSharedMemorySize, SMP32);
    cudaFuncSetAttribute(conv3x3_pair<128, 32, true, 2>, cudaFuncAttributeMaxDynamicSharedMemorySize, SMP32);
    cudaFuncSetAttribute(conv3x3_pair<32, 16, true, 1>, cudaFuncAttributeMaxDynamicSharedMemorySize, SMP16);
    cudaFuncSetAttribute(scan_horiz, cudaFuncAttributeMaxDynamicSharedMemorySize, SMH);

    // setup
    repack_x<<<BB * 8 * HW / 256, 256>>>(x, x2);
    prepack_w<<<(2 * 9 * 4 * 36 + 255) / 256, 256>>>(w_in, (uint2*)(wp + WP_WIN), 32, 32, 36);
    prepack_w<<<(8 * 9 * 4 * 36 + 255) / 256, 256>>>(w2, (uint2*)(wp + WP_W2), 128, 32, 36);
    prepack_w<<<(8 * 9 * 4 * 36 + 255) / 256, 256>>>(w3, (uint2*)(wp + WP_W3), 128, 32, 36);
    prepack_w<<<(2 * 9 * 4 * 20 + 255) / 256, 256>>>(att_w1, (uint2*)(wp + WP_AW1), 32, 16, 20);
    prepack_w<<<(1 * 9 * 4 * 20 + 255) / 256, 256>>>(att_w2, (uint2*)(wp + WP_AW2), 16, 16, 20);

    dim3 blk(256);
    dim3 gc(WW / 32, HH / 16, BB);

    // attention branch (att2 + 1x1 + sigmoid fused)
    conv3x3_pair<32, 16, true, 1><<<gc, blk, SMP16>>>(x2, wp + WP_AW1, att1, nullptr);
    conv3x3_att2<<<gc, blk>>>(att1, wp + WP_AW2, att_w3, att_b3, wmap);

    // main trunk
    conv3x3_pair<32, 32, false, 1><<<gc, blk, SMP32>>>(x2, wp + WP_WIN, bufA, nullptr);

    scan_vert<<<dim3(BB, 8, 4), 256>>>(bufA, alpha1, wmap, gated2);
    scan_horiz<<<dim3(BB, 8, 32), 256, SMH>>>(bufA, alpha1, wmap, gated2);

    conv3x3_pair<128, 32, false, 1><<<gc, blk, SMP32>>>(gated2, wp + WP_W2, bufA, nullptr);

    scan_vert<<<dim3(BB, 8, 4), 256>>>(bufA, alpha2, wmap, gated2);
    scan_horiz<<<dim3(BB, 8, 32), 256, SMH>>>(bufA, alpha2, wmap, gated2);

    // final conv + 1x1 + sigmoid fused -> mask
    conv3x3_pair<128, 32, true, 2><<<gc, blk, SMP32>>>(gated2, wp + WP_W3, out, w_out);
}

// round 8
// speedup vs baseline: 5.4629x; 1.2340x over previous
#include <cuda_runtime.h>
#include <cuda_bf16.h>
#include <math.h>
#include <stdint.h>

#define BB 8
#define CC 32
#define HH 256
#define WW 256
#define HW (HH*WW)

// ---------------- scratch (device globals; no allocations allowed) ----------
__device__ __nv_bfloat16 g_bufA[(size_t)BB * CC * HW];   // 32 MiB
__device__ uint2 g_gated2[(size_t)BB * 8 * 4 * HW];      // 128 MiB
__device__ float g_wmap[(size_t)BB * 4 * HW];            // 8 MiB
__device__ uint2 g_x2[(size_t)BB * 2 * 4 * HW];          // 32 MiB
__device__ uint4 g_wp[16384];                            // prepacked bf16 weights
__device__ __nv_bfloat16 g_att1[(size_t)BB * 16 * HW];   // 16 MiB

// g_wp offsets in uint4 units
#define WP_WIN 0
#define WP_W2  1296
#define WP_W3  6480
#define WP_AW1 11664
#define WP_AW2 12384

__device__ __forceinline__ uint32_t pbf(float lo, float hi) {
    uint32_t r;
    asm("cvt.rn.bf16x2.f32 %0, %1, %2;" : "=r"(r) : "f"(hi), "f"(lo));
    return r;
}

__device__ __forceinline__ void mma_bf16(float& d0, float& d1, float& d2, float& d3,
                                         uint32_t a0, uint32_t a1, uint32_t a2, uint32_t a3,
                                         uint32_t b0, uint32_t b1) {
    asm volatile(
        "mma.sync.aligned.m16n8k16.row.col.f32.bf16.bf16.f32 "
        "{%0,%1,%2,%3}, {%4,%5,%6,%7}, {%8,%9}, {%0,%1,%2,%3};"
        : "+f"(d0), "+f"(d1), "+f"(d2), "+f"(d3)
        : "r"(a0), "r"(a1), "r"(a2), "r"(a3), "r"(b0), "r"(b1));
}

// ---------------- merged setup: repack_x + all weight prepacks ---------------
#define NXB 16384   // repack blocks (BB*8*HW/256)
__global__ void setup_all(const float* __restrict__ x, uint2* __restrict__ x2,
                          const float* __restrict__ w_in, const float* __restrict__ w2,
                          const float* __restrict__ w3, const float* __restrict__ aw1,
                          const float* __restrict__ aw2, uint2* __restrict__ wp2) {
    if (blockIdx.x < NXB) {
        size_t i = (size_t)blockIdx.x * 256 + threadIdx.x;
        int p = (int)(i & (HW - 1));
        int pl = (int)(i >> 16);
        int b = pl >> 3, ch = (pl >> 2) & 1, t = pl & 3;
        const float* s = x + ((size_t)(b * CC + ch * 16 + 2 * t)) * HW + p;
        uint2 v;
        v.x = pbf(s[0], s[(size_t)HW]);
        v.y = pbf(s[(size_t)8 * HW], s[(size_t)9 * HW]);
        x2[i] = v;
        return;
    }
    int i = (blockIdx.x - NXB) * 256 + threadIdx.x;
    if (i >= 25488) return;
    const float* src; int CIN, COUT, WP2, base;
    if (i < 2592)       { src = w_in; CIN = 32;  COUT = 32; WP2 = 36; base = 0; }
    else if (i < 12960) { src = w2;   CIN = 128; COUT = 32; WP2 = 36; base = 2592; }
    else if (i < 23328) { src = w3;   CIN = 128; COUT = 32; WP2 = 36; base = 12960; }
    else if (i < 24768) { src = aw1;  CIN = 32;  COUT = 16; WP2 = 20; base = 23328; }
    else                { src = aw2;  CIN = 16;  COUT = 16; WP2 = 20; base = 24768; }
    int j = i - base;
    int wpos = j % WP2; int rem = j / WP2;
    int t = rem & 3; rem >>= 2; int kk = rem % 9; int ch = rem / 9;
    uint2 v = make_uint2(0u, 0u);
    if (wpos < COUT) {
        int cb = ch * 16 + 2 * t;
        v.x = pbf(src[((size_t)wpos * CIN + cb) * 9 + kk],     src[((size_t)wpos * CIN + cb + 1) * 9 + kk]);
        v.y = pbf(src[((size_t)wpos * CIN + cb + 8) * 9 + kk], src[((size_t)wpos * CIN + cb + 9) * 9 + kk]);
    }
    wp2[i] = v;
}

// ---------------- bf16 tensor-core 3x3 conv body (pair-layout input) ---------
// MODE 1: store planar bf16.  MODE 2: fused 1x1 (aux) + sigmoid -> f32 mask.
template <int CIN, int COUT, bool RELU, int MODE>
__device__ __forceinline__ void conv_body(const uint2* __restrict__ in2,
                                          const uint4* __restrict__ wpk,
                                          void* __restrict__ outp,
                                          const float* __restrict__ aux, int b) {
    constexpr int PLANE = 612;
    constexpr int WP2 = COUT + 4;
    constexpr int XBUF = 4 * PLANE;
    constexpr int WBUF = 9 * 4 * WP2;
    constexpr int NCH = CIN / 16;
    constexpr int NSL = 4 * 612;
    constexpr int WITER = (WBUF / 2 + 255) / 256;

    extern __shared__ uint2 sm[];
    uint2* s_x = sm;
    uint2* s_w = sm + 3 * XBUF;
    int* s_idx = (int*)(sm + 3 * (XBUF + WBUF));

    const int tid = threadIdx.x;
    const int lane = tid & 31, warp = tid >> 5;
    const int q = lane >> 2, t = lane & 3;
    const int w0 = blockIdx.x * 32, h0 = blockIdx.y * 16;

    for (int i = tid; i < NSL; i += 256) {
        int tt = i / 612, pos = i % 612;
        int y = pos / 34, xx = pos % 34;
        int gh = h0 + y - 1, gw = w0 + xx - 1;
        bool ok = (gh >= 0) && (gh < HH) && (gw >= 0) && (gw < WW);
        int ghc = min(max(gh, 0), HH - 1), gwc = min(max(gw, 0), WW - 1);
        int off8 = tt * HW + ghc * WW + gwc;
        s_idx[i] = off8 | ((ok ? 0 : 1) << 18);
    }

    const uint32_t smx = (uint32_t)__cvta_generic_to_shared(s_x);
    const uint32_t smw = (uint32_t)__cvta_generic_to_shared(s_w);

    auto stage_x = [&](int ch, int buf) {
        const char* base = (const char*)in2 + ((size_t)b * NCH + ch) * 4 * HW * 8;
        uint32_t sb = smx + buf * (XBUF * 8);
#pragma unroll
        for (int j = 0; j < 10; j++) {
            int i = tid + j * 256;
            if (i < NSL) {
                int wv = s_idx[i];
                const char* src = base + ((size_t)(wv & 0x3FFFF)) * 8;
                int sz = ((wv >> 18) & 1) ? 0 : 8;
                asm volatile("cp.async.ca.shared.global [%0], [%1], 8, %2;"
                             :: "r"(sb + (unsigned)i * 8), "l"(src), "r"(sz));
            }
        }
    };
    auto stage_w = [&](int ch, int buf) {
        const uint4* src = wpk + ch * (WBUF / 2);
        uint32_t sb = smw + buf * (WBUF * 8);
#pragma unroll
        for (int j = 0; j < WITER; j++) {
            int i = tid + j * 256;
            if (i < WBUF / 2)
                asm volatile("cp.async.cg.shared.global [%0], [%1], 16;"
                             :: "r"(sb + (unsigned)i * 16), "l"(src + i));
        }
    };

    float acc0[8][4], acc1[8][4];
#pragma unroll
    for (int i = 0; i < 8; i++)
#pragma unroll
        for (int k = 0; k < 4; k++) { acc0[i][k] = 0.f; acc1[i][k] = 0.f; }

    stage_x(0, 0); stage_w(0, 0);
    asm volatile("cp.async.commit_group;");
    if (NCH > 1) { stage_x(1, 1); stage_w(1, 1); }
    asm volatile("cp.async.commit_group;");

#pragma unroll 1
    for (int c = 0; c < NCH; c++) {
        if (c + 1 < NCH) asm volatile("cp.async.wait_group 1;");
        else             asm volatile("cp.async.wait_group 0;");
        __syncthreads();
        if (c + 2 < NCH) {
            stage_x(c + 2, (c + 2) % 3); stage_w(c + 2, (c + 2) % 3);
            asm volatile("cp.async.commit_group;");
        }

        const uint2* cx = s_x + (c % 3) * XBUF;
        const uint2* cw = s_w + (c % 3) * WBUF;
#pragma unroll
        for (int kk = 0; kk < 9; kk++) {
            const int ky = kk / 3, kx = kk % 3;
            const uint2* wb = cw + (kk * 4 + t) * WP2;
            uint2 w00 = wb[q], w01 = wb[q + 8];
            uint2 w10 = make_uint2(0, 0), w11 = make_uint2(0, 0);
            if (COUT == 32) { w10 = wb[q + 16]; w11 = wb[q + 24]; }
            const uint2* xb = cx + t * PLANE + ky * 34 + kx + q;
#pragma unroll
            for (int nt = 0; nt < 8; nt++) {
                int r = 2 * warp + (nt >> 2);
                int cb = (nt & 3) * 8;
                uint2 pb = xb[r * 34 + cb];
                mma_bf16(acc0[nt][0], acc0[nt][1], acc0[nt][2], acc0[nt][3],
                         w00.x, w01.x, w00.y, w01.y, pb.x, pb.y);
                if (COUT == 32)
                    mma_bf16(acc1[nt][0], acc1[nt][1], acc1[nt][2], acc1[nt][3],
                             w10.x, w11.x, w10.y, w11.y, pb.x, pb.y);
            }
        }
    }

    if (MODE == 1) {
        __nv_bfloat16* ob = (__nv_bfloat16*)outp + (size_t)b * COUT * HW;
#pragma unroll
        for (int nt = 0; nt < 8; nt++) {
            int h = h0 + 2 * warp + (nt >> 2);
            int w = w0 + (nt & 3) * 8 + 2 * t;
            size_t pix = (size_t)h * WW + w;
            float v[8] = {acc0[nt][0], acc0[nt][1], acc0[nt][2], acc0[nt][3],
                          acc1[nt][0], acc1[nt][1], acc1[nt][2], acc1[nt][3]};
#pragma unroll
            for (int m = 0; m < (COUT == 32 ? 4 : 2); m++) {
                float v0 = v[m * 2], v1 = v[m * 2 + 1];
                if (RELU) { v0 = fmaxf(v0, 0.f); v1 = fmaxf(v1, 0.f); }
                int co = (m & 1) * 8 + (m >> 1) * 16 + q;
                *(uint32_t*)&ob[(size_t)co * HW + pix] = pbf(v0, v1);
            }
        }
    } else {
        float wo0 = aux[q], wo1 = aux[q + 8], wo2 = aux[q + 16], wo3 = aux[q + 24];
        float* om = (float*)outp + (size_t)b * HW;
#pragma unroll
        for (int nt = 0; nt < 8; nt++) {
            int h = h0 + 2 * warp + (nt >> 2);
            int w = w0 + (nt & 3) * 8 + 2 * t;
            float v[8] = {acc0[nt][0], acc0[nt][1], acc0[nt][2], acc0[nt][3],
                          acc1[nt][0], acc1[nt][1], acc1[nt][2], acc1[nt][3]};
#pragma unroll
            for (int i = 0; i < 8; i++) v[i] = fmaxf(v[i], 0.f);
            float s0 = v[0] * wo0 + v[2] * wo1 + v[4] * wo2 + v[6] * wo3;
            float s1 = v[1] * wo0 + v[3] * wo1 + v[5] * wo2 + v[7] * wo3;
#pragma unroll
            for (int off = 4; off < 32; off <<= 1) {
                s0 += __shfl_xor_sync(0xffffffffu, s0, off);
                s1 += __shfl_xor_sync(0xffffffffu, s1, off);
            }
            if (q == 0) {
                float2 rr = make_float2(1.f / (1.f + expf(-s0)), 1.f / (1.f + expf(-s1)));
                *(float2*)&om[(size_t)h * WW + w] = rr;
            }
        }
    }
}

// ---------------- conv wrappers ----------------------------------------------
// stage1: z<BB -> trunk conv1 (32->32), else attention att1 (32->16)
__global__ __launch_bounds__(256, 2)
void conv_stage1(const uint2* __restrict__ x2, const uint4* __restrict__ wp,
                 __nv_bfloat16* __restrict__ bufA, __nv_bfloat16* __restrict__ att1) {
    if (blockIdx.z < BB)
        conv_body<32, 32, false, 1>(x2, wp + WP_WIN, bufA, nullptr, blockIdx.z);
    else
        conv_body<32, 16, true, 1>(x2, wp + WP_AW1, att1, nullptr, blockIdx.z - BB);
}
__global__ __launch_bounds__(256, 2)
void conv_mid(const uint2* __restrict__ g, const uint4* __restrict__ wp,
              __nv_bfloat16* __restrict__ bufA) {
    conv_body<128, 32, false, 1>(g, wp + WP_W2, bufA, nullptr, blockIdx.z);
}
__global__ __launch_bounds__(256, 2)
void conv_last(const uint2* __restrict__ g, const uint4* __restrict__ wp,
               float* __restrict__ out, const float* __restrict__ w_out) {
    conv_body<128, 32, true, 2>(g, wp + WP_W3, out, w_out, blockIdx.z);
}

// ---------------- att2 conv (bf16 planar in) + fused 1x1->4 + sigmoid --------
__global__ __launch_bounds__(256, 2)
void conv3x3_att2(const __nv_bfloat16* __restrict__ in, const uint4* __restrict__ wpk,
                  const float* __restrict__ w3, const float* __restrict__ b3,
                  float* __restrict__ wmap) {
    constexpr int PLANE = 612;
    constexpr int WP2 = 20;
    __shared__ uint2 s_x[4 * PLANE];
    __shared__ uint2 s_w[9 * 4 * WP2];

    const int tid = threadIdx.x;
    const int lane = tid & 31, warp = tid >> 5;
    const int q = lane >> 2, t = lane & 3;
    const int w0 = blockIdx.x * 32, h0 = blockIdx.y * 16, b = blockIdx.z;

    const uint16_t* inb = (const uint16_t*)in + (size_t)b * 16 * HW;
    for (int i = tid; i < 4 * 612; i += 256) {
        int tt = i / 612, pos = i % 612;
        int y = pos / 34, xx = pos % 34;
        int gh = h0 + y - 1, gw = w0 + xx - 1;
        bool ok = (gh >= 0) && (gh < HH) && (gw >= 0) && (gw < WW);
        uint32_t wa = 0, wbv = 0;
        if (ok) {
            size_t o = (size_t)gh * WW + gw;
            uint32_t c0 = inb[(size_t)(2 * tt) * HW + o];
            uint32_t c1 = inb[(size_t)(2 * tt + 1) * HW + o];
            uint32_t c8 = inb[(size_t)(2 * tt + 8) * HW + o];
            uint32_t c9 = inb[(size_t)(2 * tt + 9) * HW + o];
            wa = c0 | (c1 << 16);
            wbv = c8 | (c9 << 16);
        }
        s_x[tt * PLANE + pos] = make_uint2(wa, wbv);
    }
    for (int i = tid; i < 9 * 4 * WP2 / 2; i += 256)
        ((uint4*)s_w)[i] = wpk[i];
    __syncthreads();

    float acc[8][4];
#pragma unroll
    for (int i = 0; i < 8; i++) { acc[i][0]=0.f; acc[i][1]=0.f; acc[i][2]=0.f; acc[i][3]=0.f; }

#pragma unroll
    for (int kk = 0; kk < 9; kk++) {
        const int ky = kk / 3, kx = kk % 3;
        const uint2* wb = s_w + (kk * 4 + t) * WP2;
        uint2 w00 = wb[q], w01 = wb[q + 8];
        const uint2* xb = s_x + t * PLANE + ky * 34 + kx + q;
#pragma unroll
        for (int nt = 0; nt < 8; nt++) {
            int r = 2 * warp + (nt >> 2);
            int cb = (nt & 3) * 8;
            uint2 pb = xb[r * 34 + cb];
            mma_bf16(acc[nt][0], acc[nt][1], acc[nt][2], acc[nt][3],
                     w00.x, w01.x, w00.y, w01.y, pb.x, pb.y);
        }
    }

    float w3a[4], w3b[4], b3v[4];
#pragma unroll
    for (int d = 0; d < 4; d++) {
        w3a[d] = w3[d * 16 + q];
        w3b[d] = w3[d * 16 + q + 8];
        b3v[d] = b3[d];
    }
    float* wm = wmap + (size_t)b * 4 * HW;
#pragma unroll
    for (int nt = 0; nt < 8; nt++) {
        int h = h0 + 2 * warp + (nt >> 2);
        int w = w0 + (nt & 3) * 8 + 2 * t;
        float v0 = fmaxf(acc[nt][0], 0.f), v1 = fmaxf(acc[nt][1], 0.f);
        float v2 = fmaxf(acc[nt][2], 0.f), v3 = fmaxf(acc[nt][3], 0.f);
#pragma unroll
        for (int d = 0; d < 4; d++) {
            float s0 = v0 * w3a[d] + v2 * w3b[d];
            float s1 = v1 * w3a[d] + v3 * w3b[d];
#pragma unroll
            for (int off = 4; off < 32; off <<= 1) {
                s0 += __shfl_xor_sync(0xffffffffu, s0, off);
                s1 += __shfl_xor_sync(0xffffffffu, s1, off);
            }
            if (q == 0) {
                float2 rr = make_float2(1.f / (1.f + expf(-(s0 + b3v[d]))),
                                        1.f / (1.f + expf(-(s1 + b3v[d]))));
                *(float2*)&wm[(size_t)d * HW + (size_t)h * WW + w] = rr;
            }
        }
    }
}

// ---------------- merged scans: z<4 vertical, z>=4 horizontal ----------------
#define HST 265
__global__ __launch_bounds__(256, 2)
void scan_both(const __nv_bfloat16* __restrict__ x, const float* __restrict__ alpha,
               const float* __restrict__ wmap, uint2* __restrict__ gated2) {
    int b = blockIdx.x, pg = blockIdx.y;
    int ch = pg >> 2, t = pg & 3;
    int cb = ch * 16 + 2 * t;

    if (blockIdx.z < 4) {
        // ------- vertical (dirs 0, 2), 64-row chunk, warm 16 -------
        int cn = blockIdx.z;
        int w = threadIdx.x;
        float a0 = alpha[cb], a1 = alpha[cb + 1], a2 = alpha[cb + 8], a3 = alpha[cb + 9];
        const __nv_bfloat16* x0 = x + ((size_t)(b * CC + cb)) * HW + w;
        const __nv_bfloat16* x1 = x0 + (size_t)HW;
        const __nv_bfloat16* x2p = x0 + (size_t)8 * HW;
        const __nv_bfloat16* x3 = x0 + (size_t)9 * HW;
        const float* wm0 = wmap + ((size_t)b * 4 + 0) * HW + w;
        const float* wm2 = wmap + ((size_t)b * 4 + 2) * HW + w;
        uint2* g0 = gated2 + ((size_t)((b * 8 + 0 + ch) * 4 + t)) * HW + w;
        uint2* g2 = gated2 + ((size_t)((b * 8 + 4 + ch) * 4 + t)) * HW + w;
        int h0 = cn * 64;

        float p0 = 0.f, p1 = 0.f, p2 = 0.f, p3 = 0.f;
#pragma unroll 2
        for (int h = max(0, h0 - 16); h < h0 + 64; h++) {
            size_t o = (size_t)h * WW;
            float v0 = fmaxf(__bfloat162float(x0[o]) + a0 * p0, 0.f);
            float v1 = fmaxf(__bfloat162float(x1[o]) + a1 * p1, 0.f);
            float v2 = fmaxf(__bfloat162float(x2p[o]) + a2 * p2, 0.f);
            float v3 = fmaxf(__bfloat162float(x3[o]) + a3 * p3, 0.f);
            if (h >= h0) {
                float m = wm0[o];
                g0[o] = make_uint2(pbf(v0 * m, v1 * m), pbf(v2 * m, v3 * m));
            }
            p0 = v0; p1 = v1; p2 = v2; p3 = v3;
        }
        p0 = p1 = p2 = p3 = 0.f;
#pragma unroll 2
        for (int h = min(HH - 1, h0 + 63 + 16); h >= h0; h--) {
            size_t o = (size_t)h * WW;
            float v0 = fmaxf(__bfloat162float(x0[o]) + a0 * p0, 0.f);
            float v1 = fmaxf(__bfloat162float(x1[o]) + a1 * p1, 0.f);
            float v2 = fmaxf(__bfloat162float(x2p[o]) + a2 * p2, 0.f);
            float v3 = fmaxf(__bfloat162float(x3[o]) + a3 * p3, 0.f);
            if (h < h0 + 64) {
                float m = wm2[o];
                g2[o] = make_uint2(pbf(v0 * m, v1 * m), pbf(v2 * m, v3 * m));
            }
            p0 = v0; p1 = v1; p2 = v2; p3 = v3;
        }
        return;
    }

    // ------- horizontal (dirs 1, 3), 8-row block, 32-col chunks, warm 16 -------
    extern __shared__ float sh[];
    float* tin = sh;
    float* tf  = sh + 4 * 8 * HST;
    float* tr  = sh + 8 * 8 * HST;

    int rb = blockIdx.z - 4;
    int R0 = rb * 8;
    const int tid = threadIdx.x;
    float av[4] = {alpha[cb], alpha[cb + 1], alpha[cb + 8], alpha[cb + 9]};
    const int coff[4] = {0, 1, 8, 9};

    for (int i = tid; i < 4 * 8 * 256; i += 256) {
        int ci = i >> 11, r = (i >> 8) & 7, col = i & 255;
        float v = __bfloat162float(
            x[((size_t)(b * CC + cb + coff[ci])) * HW + (size_t)(R0 + r) * WW + col]);
        tin[(ci * 8 + r) * HST + col + (col >> 5)] = v;
    }
    __syncthreads();

    if (tid < 128) {
        int dir = tid >> 6, rem = tid & 63;
        int r = rem & 7, chunk = rem >> 3;
        int base = chunk * 32;
        float* dst = dir ? tr : tf;
        float p[4] = {0.f, 0.f, 0.f, 0.f};
        if (!dir) {
            for (int col = max(0, base - 16); col < base + 32; col++) {
                int cs = col + (col >> 5);
#pragma unroll
                for (int ci = 0; ci < 4; ci++) {
                    float v = fmaxf(tin[(ci * 8 + r) * HST + cs] + av[ci] * p[ci], 0.f);
                    if (col >= base) dst[(ci * 8 + r) * HST + cs] = v;
                    p[ci] = v;
                }
            }
        } else {
            for (int col = min(255, base + 47); col >= base; col--) {
                int cs = col + (col >> 5);
#pragma unroll
                for (int ci = 0; ci < 4; ci++) {
                    float v = fmaxf(tin[(ci * 8 + r) * HST + cs] + av[ci] * p[ci], 0.f);
                    if (col < base + 32) dst[(ci * 8 + r) * HST + cs] = v;
                    p[ci] = v;
                }
            }
        }
    }
    __syncthreads();

    const float* wm1 = wmap + ((size_t)b * 4 + 1) * HW + (size_t)R0 * WW;
    const float* wm3 = wmap + ((size_t)b * 4 + 3) * HW + (size_t)R0 * WW;
    uint2* g1 = gated2 + ((size_t)((b * 8 + 2 + ch) * 4 + t)) * HW + (size_t)R0 * WW;
    uint2* g3 = gated2 + ((size_t)((b * 8 + 6 + ch) * 4 + t)) * HW + (size_t)R0 * WW;
    for (int i = tid; i < 8 * 256; i += 256) {
        int r = i >> 8, col = i & 255;
        int cs = col + (col >> 5);
        float m1 = wm1[i], m3 = wm3[i];
        g1[i] = make_uint2(pbf(tf[(0 * 8 + r) * HST + cs] * m1, tf[(1 * 8 + r) * HST + cs] * m1),
                           pbf(tf[(2 * 8 + r) * HST + cs] * m1, tf[(3 * 8 + r) * HST + cs] * m1));
        g3[i] = make_uint2(pbf(tr[(0 * 8 + r) * HST + cs] * m3, tr[(1 * 8 + r) * HST + cs] * m3),
                           pbf(tr[(2 * 8 + r) * HST + cs] * m3, tr[(3 * 8 + r) * HST + cs] * m3));
    }
}

// ---------------- launch ------------------------------------------------------
extern "C" void kernel_launch(void* const* d_in, const int* in_sizes, int n_in,
                              void* d_out, int out_size) {
    const float* x      = (const float*)d_in[0];
    const float* alpha1 = (const float*)d_in[1];
    const float* alpha2 = (const float*)d_in[2];
    const float* w_in   = (const float*)d_in[3];
    const float* w2     = (const float*)d_in[4];
    const float* w3     = (const float*)d_in[5];
    const float* att_w1 = (const float*)d_in[6];
    const float* att_w2 = (const float*)d_in[7];
    const float* att_w3 = (const float*)d_in[8];
    const float* att_b3 = (const float*)d_in[9];
    const float* w_out  = (const float*)d_in[10];
    float* out = (float*)d_out;

    __nv_bfloat16 *bufA, *att1;
    float *wmap;
    uint2 *gated2, *x2;
    uint4* wp;
    cudaGetSymbolAddress((void**)&bufA, g_bufA);
    cudaGetSymbolAddress((void**)&gated2, g_gated2);
    cudaGetSymbolAddress((void**)&wmap, g_wmap);
    cudaGetSymbolAddress((void**)&x2, g_x2);
    cudaGetSymbolAddress((void**)&wp, g_wp);
    cudaGetSymbolAddress((void**)&att1, g_att1);

    constexpr int SMP32 = 3 * (2448 + 9 * 4 * 36) * 8 + 2448 * 4;   // 99648
    constexpr int SMH   = 12 * 8 * HST * 4;                          // 101760
    cudaFuncSetAttribute(conv_stage1, cudaFuncAttributeMaxDynamicSharedMemorySize, SMP32);
    cudaFuncSetAttribute(conv_mid, cudaFuncAttributeMaxDynamicSharedMemorySize, SMP32);
    cudaFuncSetAttribute(conv_last, cudaFuncAttributeMaxDynamicSharedMemorySize, SMP32);
    cudaFuncSetAttribute(scan_both, cudaFuncAttributeMaxDynamicSharedMemorySize, SMH);

    dim3 blk(256);
    // 1) setup: repack x + prepack all weights
    setup_all<<<NXB + 100, blk>>>(x, x2, w_in, w2, w3, att_w1, att_w2, (uint2*)wp);

    // 2) conv1 (trunk) + att1 (attention), merged grid
    conv_stage1<<<dim3(WW / 32, HH / 16, 2 * BB), blk, SMP32>>>(x2, wp, bufA, att1);

    // 3) att2 + fused 1x1 + sigmoid -> wmap
    conv3x3_att2<<<dim3(WW / 32, HH / 16, BB), blk>>>(att1, wp + WP_AW2, att_w3, att_b3, wmap);

    // 4) scans stage 1 (vert + horiz merged)
    scan_both<<<dim3(BB, 8, 36), blk, SMH>>>(bufA, alpha1, wmap, gated2);

    // 5) conv2
    conv_mid<<<dim3(WW / 32, HH / 16, BB), blk, SMP32>>>(gated2, wp, bufA);

    // 6) scans stage 2
    scan_both<<<dim3(BB, 8, 36), blk, SMH>>>(bufA, alpha2, wmap, gated2);

    // 7) conv3 + fused 1x1 + sigmoid -> mask
    conv_last<<<dim3(WW / 32, HH / 16, BB), blk, SMP32>>>(gated2, wp, out, w_out);
}

// round 9
// speedup vs baseline: 6.3918x; 1.1700x over previous
#include <cuda_runtime.h>
#include <cuda_bf16.h>
#include <math.h>
#include <stdint.h>

#define BB 8
#define CC 32
#define HH 256
#define WW 256
#define HW (HH*WW)

// ---------------- scratch (device globals; no allocations allowed) ----------
__device__ __nv_bfloat16 g_bufA[(size_t)BB * CC * HW];   // 32 MiB
__device__ uint2 g_gated2[(size_t)BB * 8 * 4 * HW];      // 128 MiB
__device__ float g_wmap[(size_t)BB * 4 * HW];            // 8 MiB
__device__ uint2 g_x2[(size_t)BB * 2 * 4 * HW];          // 32 MiB
__device__ uint4 g_wp[16384];                            // prepacked bf16 weights
__device__ __nv_bfloat16 g_att1[(size_t)BB * 16 * HW];   // 16 MiB

// g_wp offsets in uint4 units
#define WP_WIN 0
#define WP_W2  1296
#define WP_W3  6480
#define WP_AW1 11664
#define WP_AW2 12384

__device__ __forceinline__ uint32_t pbf(float lo, float hi) {
    uint32_t r;
    asm("cvt.rn.bf16x2.f32 %0, %1, %2;" : "=r"(r) : "f"(hi), "f"(lo));
    return r;
}

__device__ __forceinline__ void mma_bf16(float& d0, float& d1, float& d2, float& d3,
                                         uint32_t a0, uint32_t a1, uint32_t a2, uint32_t a3,
                                         uint32_t b0, uint32_t b1) {
    asm volatile(
        "mma.sync.aligned.m16n8k16.row.col.f32.bf16.bf16.f32 "
        "{%0,%1,%2,%3}, {%4,%5,%6,%7}, {%8,%9}, {%0,%1,%2,%3};"
        : "+f"(d0), "+f"(d1), "+f"(d2), "+f"(d3)
        : "r"(a0), "r"(a1), "r"(a2), "r"(a3), "r"(b0), "r"(b1));
}

// ---------------- merged setup: repack_x + all weight prepacks ---------------
#define NXB 16384   // repack blocks (BB*8*HW/256)
__global__ void setup_all(const float* __restrict__ x, uint2* __restrict__ x2,
                          const float* __restrict__ w_in, const float* __restrict__ w2,
                          const float* __restrict__ w3, const float* __restrict__ aw1,
                          const float* __restrict__ aw2, uint2* __restrict__ wp2) {
    if (blockIdx.x < NXB) {
        size_t i = (size_t)blockIdx.x * 256 + threadIdx.x;
        int p = (int)(i & (HW - 1));
        int pl = (int)(i >> 16);
        int b = pl >> 3, ch = (pl >> 2) & 1, t = pl & 3;
        const float* s = x + ((size_t)(b * CC + ch * 16 + 2 * t)) * HW + p;
        uint2 v;
        v.x = pbf(s[0], s[(size_t)HW]);
        v.y = pbf(s[(size_t)8 * HW], s[(size_t)9 * HW]);
        x2[i] = v;
        return;
    }
    int i = (blockIdx.x - NXB) * 256 + threadIdx.x;
    if (i >= 25488) return;
    const float* src; int CIN, COUT, WP2, base;
    if (i < 2592)       { src = w_in; CIN = 32;  COUT = 32; WP2 = 36; base = 0; }
    else if (i < 12960) { src = w2;   CIN = 128; COUT = 32; WP2 = 36; base = 2592; }
    else if (i < 23328) { src = w3;   CIN = 128; COUT = 32; WP2 = 36; base = 12960; }
    else if (i < 24768) { src = aw1;  CIN = 32;  COUT = 16; WP2 = 20; base = 23328; }
    else                { src = aw2;  CIN = 16;  COUT = 16; WP2 = 20; base = 24768; }
    int j = i - base;
    int wpos = j % WP2; int rem = j / WP2;
    int t = rem & 3; rem >>= 2; int kk = rem % 9; int ch = rem / 9;
    uint2 v = make_uint2(0u, 0u);
    if (wpos < COUT) {
        int cb = ch * 16 + 2 * t;
        v.x = pbf(src[((size_t)wpos * CIN + cb) * 9 + kk],     src[((size_t)wpos * CIN + cb + 1) * 9 + kk]);
        v.y = pbf(src[((size_t)wpos * CIN + cb + 8) * 9 + kk], src[((size_t)wpos * CIN + cb + 9) * 9 + kk]);
    }
    wp2[i] = v;
}

// ---------------- bf16 tensor-core 3x3 conv body (pair-layout input) ---------
template <int CIN, int COUT, bool RELU, int MODE>
__device__ __forceinline__ void conv_body(const uint2* __restrict__ in2,
                                          const uint4* __restrict__ wpk,
                                          void* __restrict__ outp,
                                          const float* __restrict__ aux, int b) {
    constexpr int PLANE = 612;
    constexpr int WP2 = COUT + 4;
    constexpr int XBUF = 4 * PLANE;
    constexpr int WBUF = 9 * 4 * WP2;
    constexpr int NCH = CIN / 16;
    constexpr int NSL = 4 * 612;
    constexpr int WITER = (WBUF / 2 + 255) / 256;

    extern __shared__ uint2 sm[];
    uint2* s_x = sm;
    uint2* s_w = sm + 3 * XBUF;
    int* s_idx = (int*)(sm + 3 * (XBUF + WBUF));

    const int tid = threadIdx.x;
    const int lane = tid & 31, warp = tid >> 5;
    const int q = lane >> 2, t = lane & 3;
    const int w0 = blockIdx.x * 32, h0 = blockIdx.y * 16;

    for (int i = tid; i < NSL; i += 256) {
        int tt = i / 612, pos = i % 612;
        int y = pos / 34, xx = pos % 34;
        int gh = h0 + y - 1, gw = w0 + xx - 1;
        bool ok = (gh >= 0) && (gh < HH) && (gw >= 0) && (gw < WW);
        int ghc = min(max(gh, 0), HH - 1), gwc = min(max(gw, 0), WW - 1);
        int off8 = tt * HW + ghc * WW + gwc;
        s_idx[i] = off8 | ((ok ? 0 : 1) << 18);
    }

    const uint32_t smx = (uint32_t)__cvta_generic_to_shared(s_x);
    const uint32_t smw = (uint32_t)__cvta_generic_to_shared(s_w);

    auto stage_x = [&](int ch, int buf) {
        const char* base = (const char*)in2 + ((size_t)b * NCH + ch) * 4 * HW * 8;
        uint32_t sb = smx + buf * (XBUF * 8);
#pragma unroll
        for (int j = 0; j < 10; j++) {
            int i = tid + j * 256;
            if (i < NSL) {
                int wv = s_idx[i];
                const char* src = base + ((size_t)(wv & 0x3FFFF)) * 8;
                int sz = ((wv >> 18) & 1) ? 0 : 8;
                asm volatile("cp.async.ca.shared.global [%0], [%1], 8, %2;"
                             :: "r"(sb + (unsigned)i * 8), "l"(src), "r"(sz));
            }
        }
    };
    auto stage_w = [&](int ch, int buf) {
        const uint4* src = wpk + ch * (WBUF / 2);
        uint32_t sb = smw + buf * (WBUF * 8);
#pragma unroll
        for (int j = 0; j < WITER; j++) {
            int i = tid + j * 256;
            if (i < WBUF / 2)
                asm volatile("cp.async.cg.shared.global [%0], [%1], 16;"
                             :: "r"(sb + (unsigned)i * 16), "l"(src + i));
        }
    };

    float acc0[8][4], acc1[8][4];
#pragma unroll
    for (int i = 0; i < 8; i++)
#pragma unroll
        for (int k = 0; k < 4; k++) { acc0[i][k] = 0.f; acc1[i][k] = 0.f; }

    stage_x(0, 0); stage_w(0, 0);
    asm volatile("cp.async.commit_group;");
    if (NCH > 1) { stage_x(1, 1); stage_w(1, 1); }
    asm volatile("cp.async.commit_group;");

#pragma unroll 1
    for (int c = 0; c < NCH; c++) {
        if (c + 1 < NCH) asm volatile("cp.async.wait_group 1;");
        else             asm volatile("cp.async.wait_group 0;");
        __syncthreads();
        if (c + 2 < NCH) {
            stage_x(c + 2, (c + 2) % 3); stage_w(c + 2, (c + 2) % 3);
            asm volatile("cp.async.commit_group;");
        }

        const uint2* cx = s_x + (c % 3) * XBUF;
        const uint2* cw = s_w + (c % 3) * WBUF;
#pragma unroll
        for (int kk = 0; kk < 9; kk++) {
            const int ky = kk / 3, kx = kk % 3;
            const uint2* wb = cw + (kk * 4 + t) * WP2;
            uint2 w00 = wb[q], w01 = wb[q + 8];
            uint2 w10 = make_uint2(0, 0), w11 = make_uint2(0, 0);
            if (COUT == 32) { w10 = wb[q + 16]; w11 = wb[q + 24]; }
            const uint2* xb = cx + t * PLANE + ky * 34 + kx + q;
#pragma unroll
            for (int nt = 0; nt < 8; nt++) {
                int r = 2 * warp + (nt >> 2);
                int cb = (nt & 3) * 8;
                uint2 pb = xb[r * 34 + cb];
                mma_bf16(acc0[nt][0], acc0[nt][1], acc0[nt][2], acc0[nt][3],
                         w00.x, w01.x, w00.y, w01.y, pb.x, pb.y);
                if (COUT == 32)
                    mma_bf16(acc1[nt][0], acc1[nt][1], acc1[nt][2], acc1[nt][3],
                             w10.x, w11.x, w10.y, w11.y, pb.x, pb.y);
            }
        }
    }

    if (MODE == 1) {
        __nv_bfloat16* ob = (__nv_bfloat16*)outp + (size_t)b * COUT * HW;
#pragma unroll
        for (int nt = 0; nt < 8; nt++) {
            int h = h0 + 2 * warp + (nt >> 2);
            int w = w0 + (nt & 3) * 8 + 2 * t;
            size_t pix = (size_t)h * WW + w;
            float v[8] = {acc0[nt][0], acc0[nt][1], acc0[nt][2], acc0[nt][3],
                          acc1[nt][0], acc1[nt][1], acc1[nt][2], acc1[nt][3]};
#pragma unroll
            for (int m = 0; m < (COUT == 32 ? 4 : 2); m++) {
                float v0 = v[m * 2], v1 = v[m * 2 + 1];
                if (RELU) { v0 = fmaxf(v0, 0.f); v1 = fmaxf(v1, 0.f); }
                int co = (m & 1) * 8 + (m >> 1) * 16 + q;
                *(uint32_t*)&ob[(size_t)co * HW + pix] = pbf(v0, v1);
            }
        }
    } else {
        float wo0 = aux[q], wo1 = aux[q + 8], wo2 = aux[q + 16], wo3 = aux[q + 24];
        float* om = (float*)outp + (size_t)b * HW;
#pragma unroll
        for (int nt = 0; nt < 8; nt++) {
            int h = h0 + 2 * warp + (nt >> 2);
            int w = w0 + (nt & 3) * 8 + 2 * t;
            float v[8] = {acc0[nt][0], acc0[nt][1], acc0[nt][2], acc0[nt][3],
                          acc1[nt][0], acc1[nt][1], acc1[nt][2], acc1[nt][3]};
#pragma unroll
            for (int i = 0; i < 8; i++) v[i] = fmaxf(v[i], 0.f);
            float s0 = v[0] * wo0 + v[2] * wo1 + v[4] * wo2 + v[6] * wo3;
            float s1 = v[1] * wo0 + v[3] * wo1 + v[5] * wo2 + v[7] * wo3;
#pragma unroll
            for (int off = 4; off < 32; off <<= 1) {
                s0 += __shfl_xor_sync(0xffffffffu, s0, off);
                s1 += __shfl_xor_sync(0xffffffffu, s1, off);
            }
            if (q == 0) {
                float2 rr = make_float2(1.f / (1.f + expf(-s0)), 1.f / (1.f + expf(-s1)));
                *(float2*)&om[(size_t)h * WW + w] = rr;
            }
        }
    }
}

// ---------------- conv wrappers ----------------------------------------------
__global__ __launch_bounds__(256, 2)
void conv_stage1(const uint2* __restrict__ x2, const uint4* __restrict__ wp,
                 __nv_bfloat16* __restrict__ bufA, __nv_bfloat16* __restrict__ att1) {
    if (blockIdx.z < BB)
        conv_body<32, 32, false, 1>(x2, wp + WP_WIN, bufA, nullptr, blockIdx.z);
    else
        conv_body<32, 16, true, 1>(x2, wp + WP_AW1, att1, nullptr, blockIdx.z - BB);
}
__global__ __launch_bounds__(256, 2)
void conv_mid(const uint2* __restrict__ g, const uint4* __restrict__ wp,
              __nv_bfloat16* __restrict__ bufA) {
    conv_body<128, 32, false, 1>(g, wp + WP_W2, bufA, nullptr, blockIdx.z);
}
__global__ __launch_bounds__(256, 2)
void conv_last(const uint2* __restrict__ g, const uint4* __restrict__ wp,
               float* __restrict__ out, const float* __restrict__ w_out) {
    conv_body<128, 32, true, 2>(g, wp + WP_W3, out, w_out, blockIdx.z);
}

// ---------------- att2 conv (bf16 planar in) + fused 1x1->4 + sigmoid --------
__global__ __launch_bounds__(256, 2)
void conv3x3_att2(const __nv_bfloat16* __restrict__ in, const uint4* __restrict__ wpk,
                  const float* __restrict__ w3, const float* __restrict__ b3,
                  float* __restrict__ wmap) {
    constexpr int PLANE = 612;
    constexpr int WP2 = 20;
    __shared__ uint2 s_x[4 * PLANE];
    __shared__ uint2 s_w[9 * 4 * WP2];

    const int tid = threadIdx.x;
    const int lane = tid & 31, warp = tid >> 5;
    const int q = lane >> 2, t = lane & 3;
    const int w0 = blockIdx.x * 32, h0 = blockIdx.y * 16, b = blockIdx.z;

    const uint16_t* inb = (const uint16_t*)in + (size_t)b * 16 * HW;
    for (int i = tid; i < 4 * 612; i += 256) {
        int tt = i / 612, pos = i % 612;
        int y = pos / 34, xx = pos % 34;
        int gh = h0 + y - 1, gw = w0 + xx - 1;
        bool ok = (gh >= 0) && (gh < HH) && (gw >= 0) && (gw < WW);
        uint32_t wa = 0, wbv = 0;
        if (ok) {
            size_t o = (size_t)gh * WW + gw;
            uint32_t c0 = inb[(size_t)(2 * tt) * HW + o];
            uint32_t c1 = inb[(size_t)(2 * tt + 1) * HW + o];
            uint32_t c8 = inb[(size_t)(2 * tt + 8) * HW + o];
            uint32_t c9 = inb[(size_t)(2 * tt + 9) * HW + o];
            wa = c0 | (c1 << 16);
            wbv = c8 | (c9 << 16);
        }
        s_x[tt * PLANE + pos] = make_uint2(wa, wbv);
    }
    for (int i = tid; i < 9 * 4 * WP2 / 2; i += 256)
        ((uint4*)s_w)[i] = wpk[i];
    __syncthreads();

    float acc[8][4];
#pragma unroll
    for (int i = 0; i < 8; i++) { acc[i][0]=0.f; acc[i][1]=0.f; acc[i][2]=0.f; acc[i][3]=0.f; }

#pragma unroll
    for (int kk = 0; kk < 9; kk++) {
        const int ky = kk / 3, kx = kk % 3;
        const uint2* wb = s_w + (kk * 4 + t) * WP2;
        uint2 w00 = wb[q], w01 = wb[q + 8];
        const uint2* xb = s_x + t * PLANE + ky * 34 + kx + q;
#pragma unroll
        for (int nt = 0; nt < 8; nt++) {
            int r = 2 * warp + (nt >> 2);
            int cb = (nt & 3) * 8;
            uint2 pb = xb[r * 34 + cb];
            mma_bf16(acc[nt][0], acc[nt][1], acc[nt][2], acc[nt][3],
                     w00.x, w01.x, w00.y, w01.y, pb.x, pb.y);
        }
    }

    float w3a[4], w3b[4], b3v[4];
#pragma unroll
    for (int d = 0; d < 4; d++) {
        w3a[d] = w3[d * 16 + q];
        w3b[d] = w3[d * 16 + q + 8];
        b3v[d] = b3[d];
    }
    float* wm = wmap + (size_t)b * 4 * HW;
#pragma unroll
    for (int nt = 0; nt < 8; nt++) {
        int h = h0 + 2 * warp + (nt >> 2);
        int w = w0 + (nt & 3) * 8 + 2 * t;
        float v0 = fmaxf(acc[nt][0], 0.f), v1 = fmaxf(acc[nt][1], 0.f);
        float v2 = fmaxf(acc[nt][2], 0.f), v3 = fmaxf(acc[nt][3], 0.f);
#pragma unroll
        for (int d = 0; d < 4; d++) {
            float s0 = v0 * w3a[d] + v2 * w3b[d];
            float s1 = v1 * w3a[d] + v3 * w3b[d];
#pragma unroll
            for (int off = 4; off < 32; off <<= 1) {
                s0 += __shfl_xor_sync(0xffffffffu, s0, off);
                s1 += __shfl_xor_sync(0xffffffffu, s1, off);
            }
            if (q == 0) {
                float2 rr = make_float2(1.f / (1.f + expf(-(s0 + b3v[d]))),
                                        1.f / (1.f + expf(-(s1 + b3v[d]))));
                *(float2*)&wm[(size_t)d * HW + (size_t)h * WW + w] = rr;
            }
        }
    }
}

// ---------------- merged scans: z<4 vertical, z>=4 horizontal ----------------
// Horiz smem tiles packed as bf16 uint2 (4 ch / 8B); 256 scan threads,
// 16-col chunks (chain 32), warm 16. smem 50112 B -> 4 blocks/SM.
#define HSTRIDE 261
__global__ __launch_bounds__(256, 4)
void scan_both(const __nv_bfloat16* __restrict__ x, const float* __restrict__ alpha,
               const float* __restrict__ wmap, uint2* __restrict__ gated2) {
    int b = blockIdx.x, pg = blockIdx.y;
    int ch = pg >> 2, t = pg & 3;
    int cb = ch * 16 + 2 * t;

    if (blockIdx.z < 4) {
        // ------- vertical (dirs 0, 2), 64-row chunk, warm 16 -------
        int cn = blockIdx.z;
        int w = threadIdx.x;
        float a0 = alpha[cb], a1 = alpha[cb + 1], a2 = alpha[cb + 8], a3 = alpha[cb + 9];
        const __nv_bfloat16* x0 = x + ((size_t)(b * CC + cb)) * HW + w;
        const __nv_bfloat16* x1 = x0 + (size_t)HW;
        const __nv_bfloat16* x2p = x0 + (size_t)8 * HW;
        const __nv_bfloat16* x3 = x0 + (size_t)9 * HW;
        const float* wm0 = wmap + ((size_t)b * 4 + 0) * HW + w;
        const float* wm2 = wmap + ((size_t)b * 4 + 2) * HW + w;
        uint2* g0 = gated2 + ((size_t)((b * 8 + 0 + ch) * 4 + t)) * HW + w;
        uint2* g2 = gated2 + ((size_t)((b * 8 + 4 + ch) * 4 + t)) * HW + w;
        int h0 = cn * 64;

        float p0 = 0.f, p1 = 0.f, p2 = 0.f, p3 = 0.f;
#pragma unroll 2
        for (int h = max(0, h0 - 16); h < h0 + 64; h++) {
            size_t o = (size_t)h * WW;
            float v0 = fmaxf(__bfloat162float(x0[o]) + a0 * p0, 0.f);
            float v1 = fmaxf(__bfloat162float(x1[o]) + a1 * p1, 0.f);
            float v2 = fmaxf(__bfloat162float(x2p[o]) + a2 * p2, 0.f);
            float v3 = fmaxf(__bfloat162float(x3[o]) + a3 * p3, 0.f);
            if (h >= h0) {
                float m = wm0[o];
                g0[o] = make_uint2(pbf(v0 * m, v1 * m), pbf(v2 * m, v3 * m));
            }
            p0 = v0; p1 = v1; p2 = v2; p3 = v3;
        }
        p0 = p1 = p2 = p3 = 0.f;
#pragma unroll 2
        for (int h = min(HH - 1, h0 + 63 + 16); h >= h0; h--) {
            size_t o = (size_t)h * WW;
            float v0 = fmaxf(__bfloat162float(x0[o]) + a0 * p0, 0.f);
            float v1 = fmaxf(__bfloat162float(x1[o]) + a1 * p1, 0.f);
            float v2 = fmaxf(__bfloat162float(x2p[o]) + a2 * p2, 0.f);
            float v3 = fmaxf(__bfloat162float(x3[o]) + a3 * p3, 0.f);
            if (h < h0 + 64) {
                float m = wm2[o];
                g2[o] = make_uint2(pbf(v0 * m, v1 * m), pbf(v2 * m, v3 * m));
            }
            p0 = v0; p1 = v1; p2 = v2; p3 = v3;
        }
        return;
    }

    // ------- horizontal (dirs 1, 3), 8-row block, 16-col chunks, warm 16 -------
    extern __shared__ uint2 shu[];
    uint2* tin = shu;
    uint2* tf  = shu + 8 * HSTRIDE;
    uint2* tr  = shu + 16 * HSTRIDE;

    int rb = blockIdx.z - 4;
    int R0 = rb * 8;
    const int tid = threadIdx.x;
    float a0 = alpha[cb], a1 = alpha[cb + 1], a2 = alpha[cb + 8], a3 = alpha[cb + 9];

    const uint16_t* xb16 = (const uint16_t*)x + (size_t)(b * CC + cb) * HW + (size_t)R0 * WW;
    for (int i = tid; i < 8 * 256; i += 256) {
        int r = i >> 8, col = i & 255;
        size_t o = (size_t)r * WW + col;
        uint32_t c0 = xb16[o];
        uint32_t c1 = xb16[o + (size_t)HW];
        uint32_t c8 = xb16[o + (size_t)8 * HW];
        uint32_t c9 = xb16[o + (size_t)9 * HW];
        tin[r * HSTRIDE + col] = make_uint2(c0 | (c1 << 16), c8 | (c9 << 16));
    }
    __syncthreads();

    {
        int dir = tid >> 7, rem = tid & 127;
        int r = rem & 7, ck = rem >> 3;      // ck 0..15, 16-col chunks
        int base = ck * 16;
        uint2* dst = dir ? tr : tf;
        float p0 = 0.f, p1 = 0.f, p2 = 0.f, p3 = 0.f;
        if (!dir) {
            for (int col = max(0, base - 16); col < base + 16; col++) {
                uint2 wv = tin[r * HSTRIDE + col];
                float2 lo = __bfloat1622float2(*reinterpret_cast<__nv_bfloat162*>(&wv.x));
                float2 hi = __bfloat1622float2(*reinterpret_cast<__nv_bfloat162*>(&wv.y));
                float v0 = fmaxf(lo.x + a0 * p0, 0.f);
                float v1 = fmaxf(lo.y + a1 * p1, 0.f);
                float v2 = fmaxf(hi.x + a2 * p2, 0.f);
                float v3 = fmaxf(hi.y + a3 * p3, 0.f);
                if (col >= base)
                    dst[r * HSTRIDE + col] = make_uint2(pbf(v0, v1), pbf(v2, v3));
                p0 = v0; p1 = v1; p2 = v2; p3 = v3;
            }
        } else {
            for (int col = min(255, base + 31); col >= base; col--) {
                uint2 wv = tin[r * HSTRIDE + col];
                float2 lo = __bfloat1622float2(*reinterpret_cast<__nv_bfloat162*>(&wv.x));
                float2 hi = __bfloat1622float2(*reinterpret_cast<__nv_bfloat162*>(&wv.y));
                float v0 = fmaxf(lo.x + a0 * p0, 0.f);
                float v1 = fmaxf(lo.y + a1 * p1, 0.f);
                float v2 = fmaxf(hi.x + a2 * p2, 0.f);
                float v3 = fmaxf(hi.y + a3 * p3, 0.f);
                if (col < base + 16)
                    dst[r * HSTRIDE + col] = make_uint2(pbf(v0, v1), pbf(v2, v3));
                p0 = v0; p1 = v1; p2 = v2; p3 = v3;
            }
        }
    }
    __syncthreads();

    const float* wm1 = wmap + ((size_t)b * 4 + 1) * HW + (size_t)R0 * WW;
    const float* wm3 = wmap + ((size_t)b * 4 + 3) * HW + (size_t)R0 * WW;
    uint2* g1 = gated2 + ((size_t)((b * 8 + 2 + ch) * 4 + t)) * HW + (size_t)R0 * WW;
    uint2* g3 = gated2 + ((size_t)((b * 8 + 6 + ch) * 4 + t)) * HW + (size_t)R0 * WW;
    for (int i = tid; i < 8 * 256; i += 256) {
        int r = i >> 8, col = i & 255;
        float m1 = wm1[i], m3 = wm3[i];
        uint2 f = tf[r * HSTRIDE + col];
        uint2 rv = tr[r * HSTRIDE + col];
        float2 flo = __bfloat1622float2(*reinterpret_cast<__nv_bfloat162*>(&f.x));
        float2 fhi = __bfloat1622float2(*reinterpret_cast<__nv_bfloat162*>(&f.y));
        float2 rlo = __bfloat1622float2(*reinterpret_cast<__nv_bfloat162*>(&rv.x));
        float2 rhi = __bfloat1622float2(*reinterpret_cast<__nv_bfloat162*>(&rv.y));
        g1[i] = make_uint2(pbf(flo.x * m1, flo.y * m1), pbf(fhi.x * m1, fhi.y * m1));
        g3[i] = make_uint2(pbf(rlo.x * m3, rlo.y * m3), pbf(rhi.x * m3, rhi.y * m3));
    }
}

// ---------------- launch ------------------------------------------------------
extern "C" void kernel_launch(void* const* d_in, const int* in_sizes, int n_in,
                              void* d_out, int out_size) {
    const float* x      = (const float*)d_in[0];
    const float* alpha1 = (const float*)d_in[1];
    const float* alpha2 = (const float*)d_in[2];
    const float* w_in   = (const float*)d_in[3];
    const float* w2     = (const float*)d_in[4];
    const float* w3     = (const float*)d_in[5];
    const float* att_w1 = (const float*)d_in[6];
    const float* att_w2 = (const float*)d_in[7];
    const float* att_w3 = (const float*)d_in[8];
    const float* att_b3 = (const float*)d_in[9];
    const float* w_out  = (const float*)d_in[10];
    float* out = (float*)d_out;

    __nv_bfloat16 *bufA, *att1;
    float *wmap;
    uint2 *gated2, *x2;
    uint4* wp;
    cudaGetSymbolAddress((void**)&bufA, g_bufA);
    cudaGetSymbolAddress((void**)&gated2, g_gated2);
    cudaGetSymbolAddress((void**)&wmap, g_wmap);
    cudaGetSymbolAddress((void**)&x2, g_x2);
    cudaGetSymbolAddress((void**)&wp, g_wp);
    cudaGetSymbolAddress((void**)&att1, g_att1);

    constexpr int SMP32 = 3 * (2448 + 9 * 4 * 36) * 8 + 2448 * 4;   // 99648
    constexpr int SMH   = 24 * HSTRIDE * 8;                          // 50112
    cudaFuncSetAttribute(conv_stage1, cudaFuncAttributeMaxDynamicSharedMemorySize, SMP32);
    cudaFuncSetAttribute(conv_mid, cudaFuncAttributeMaxDynamicSharedMemorySize, SMP32);
    cudaFuncSetAttribute(conv_last, cudaFuncAttributeMaxDynamicSharedMemorySize, SMP32);
    cudaFuncSetAttribute(scan_both, cudaFuncAttributeMaxDynamicSharedMemorySize, SMH);

    dim3 blk(256);
    // 1) setup: repack x + prepack all weights
    setup_all<<<NXB + 100, blk>>>(x, x2, w_in, w2, w3, att_w1, att_w2, (uint2*)wp);

    // 2) conv1 (trunk) + att1 (attention), merged grid
    conv_stage1<<<dim3(WW / 32, HH / 16, 2 * BB), blk, SMP32>>>(x2, wp, bufA, att1);

    // 3) att2 + fused 1x1 + sigmoid -> wmap
    conv3x3_att2<<<dim3(WW / 32, HH / 16, BB), blk>>>(att1, wp + WP_AW2, att_w3, att_b3, wmap);

    // 4) scans stage 1 (vert + horiz merged)
    scan_both<<<dim3(BB, 8, 36), blk, SMH>>>(bufA, alpha1, wmap, gated2);

    // 5) conv2
    conv_mid<<<dim3(WW / 32, HH / 16, BB), blk, SMP32>>>(gated2, wp, bufA);

    // 6) scans stage 2
    scan_both<<<dim3(BB, 8, 36), blk, SMH>>>(bufA, alpha2, wmap, gated2);

    // 7) conv3 + fused 1x1 + sigmoid -> mask
    conv_last<<<dim3(WW / 32, HH / 16, BB), blk, SMP32>>>(gated2, wp, out, w_out);
}

// round 10
// speedup vs baseline: 6.6568x; 1.0415x over previous
#include <cuda_runtime.h>
#include <cuda_bf16.h>
#include <math.h>
#include <stdint.h>

#define BB 8
#define CC 32
#define HH 256
#define WW 256
#define HW (HH*WW)

// ---------------- scratch (device globals; no allocations allowed) ----------
__device__ uint2 g_bufA2[(size_t)BB * 8 * HW];           // 32 MiB: conv out, pair layout
__device__ uint2 g_gated2[(size_t)BB * 8 * 4 * HW];      // 128 MiB: gated concat, pair layout
__device__ float g_wmap[(size_t)BB * 4 * HW];            // 8 MiB
__device__ uint2 g_x2[(size_t)BB * 2 * 4 * HW];          // 32 MiB: bf16-packed x
__device__ uint4 g_wp[16384];                            // prepacked bf16 weights
__device__ __nv_bfloat16 g_att1[(size_t)BB * 16 * HW];   // 16 MiB: att1 planar

// g_wp offsets in uint4 units
#define WP_WIN 0
#define WP_W2  1296
#define WP_W3  6480
#define WP_AW1 11664
#define WP_AW2 12384

__device__ __forceinline__ uint32_t pbf(float lo, float hi) {
    uint32_t r;
    asm("cvt.rn.bf16x2.f32 %0, %1, %2;" : "=r"(r) : "f"(hi), "f"(lo));
    return r;
}

__device__ __forceinline__ void mma_bf16(float& d0, float& d1, float& d2, float& d3,
                                         uint32_t a0, uint32_t a1, uint32_t a2, uint32_t a3,
                                         uint32_t b0, uint32_t b1) {
    asm volatile(
        "mma.sync.aligned.m16n8k16.row.col.f32.bf16.bf16.f32 "
        "{%0,%1,%2,%3}, {%4,%5,%6,%7}, {%8,%9}, {%0,%1,%2,%3};"
        : "+f"(d0), "+f"(d1), "+f"(d2), "+f"(d3)
        : "r"(a0), "r"(a1), "r"(a2), "r"(a3), "r"(b0), "r"(b1));
}

// ---------------- merged setup: repack_x + all weight prepacks ---------------
// W2/W3 use the bufA/gated pair mapping: slot tt of chunk ci (dir=ci>>1,
// half=ci&1) packs channels {c1, c1+8, c1+16, c1+24}, c1 = dir*32 + half*4 + tt.
#define NXB 16384
__global__ void setup_all(const float* __restrict__ x, uint2* __restrict__ x2,
                          const float* __restrict__ w_in, const float* __restrict__ w2,
                          const float* __restrict__ w3, const float* __restrict__ aw1,
                          const float* __restrict__ aw2, uint2* __restrict__ wp2) {
    if (blockIdx.x < NXB) {
        size_t i = (size_t)blockIdx.x * 256 + threadIdx.x;
        int p = (int)(i & (HW - 1));
        int pl = (int)(i >> 16);
        int b = pl >> 3, ch = (pl >> 2) & 1, t = pl & 3;
        const float* s = x + ((size_t)(b * CC + ch * 16 + 2 * t)) * HW + p;
        uint2 v;
        v.x = pbf(s[0], s[(size_t)HW]);
        v.y = pbf(s[(size_t)8 * HW], s[(size_t)9 * HW]);
        x2[i] = v;
        return;
    }
    int i = (blockIdx.x - NXB) * 256 + threadIdx.x;
    if (i >= 25488) return;
    const float* src; int CIN, COUT, WP2, base; bool pairmap;
    if (i < 2592)       { src = w_in; CIN = 32;  COUT = 32; WP2 = 36; base = 0;     pairmap = false; }
    else if (i < 12960) { src = w2;   CIN = 128; COUT = 32; WP2 = 36; base = 2592;  pairmap = true; }
    else if (i < 23328) { src = w3;   CIN = 128; COUT = 32; WP2 = 36; base = 12960; pairmap = true; }
    else if (i < 24768) { src = aw1;  CIN = 32;  COUT = 16; WP2 = 20; base = 23328; pairmap = false; }
    else                { src = aw2;  CIN = 16;  COUT = 16; WP2 = 20; base = 24768; pairmap = false; }
    int j = i - base;
    int wpos = j % WP2; int rem = j / WP2;
    int t = rem & 3; rem >>= 2; int kk = rem % 9; int ch = rem / 9;
    uint2 v = make_uint2(0u, 0u);
    if (wpos < COUT) {
        if (!pairmap) {
            int cb = ch * 16 + 2 * t;
            v.x = pbf(src[((size_t)wpos * CIN + cb) * 9 + kk],     src[((size_t)wpos * CIN + cb + 1) * 9 + kk]);
            v.y = pbf(src[((size_t)wpos * CIN + cb + 8) * 9 + kk], src[((size_t)wpos * CIN + cb + 9) * 9 + kk]);
        } else {
            int d = ch >> 1, half = ch & 1;
            int c1 = d * 32 + half * 4 + t;
            v.x = pbf(src[((size_t)wpos * CIN + c1) * 9 + kk],      src[((size_t)wpos * CIN + c1 + 8) * 9 + kk]);
            v.y = pbf(src[((size_t)wpos * CIN + c1 + 16) * 9 + kk], src[((size_t)wpos * CIN + c1 + 24) * 9 + kk]);
        }
    }
    wp2[i] = v;
}

// ---------------- bf16 tensor-core 3x3 conv body (pair-layout input) ---------
// MODE 1 + COUT=32: store pair-layout uint4 (2 pixels).  MODE 1 + COUT=16:
// planar bf16 (att1).  MODE 2: fused 1x1 (aux) + sigmoid -> f32 mask.
template <int CIN, int COUT, bool RELU, int MODE>
__device__ __forceinline__ void conv_body(const uint2* __restrict__ in2,
                                          const uint4* __restrict__ wpk,
                                          void* __restrict__ outp,
                                          const float* __restrict__ aux, int b) {
    constexpr int PLANE = 612;
    constexpr int WP2 = COUT + 4;
    constexpr int XBUF = 4 * PLANE;
    constexpr int WBUF = 9 * 4 * WP2;
    constexpr int NCH = CIN / 16;
    constexpr int NSL = 4 * 612;
    constexpr int WITER = (WBUF / 2 + 255) / 256;

    extern __shared__ uint2 sm[];
    uint2* s_x = sm;
    uint2* s_w = sm + 3 * XBUF;
    int* s_idx = (int*)(sm + 3 * (XBUF + WBUF));

    const int tid = threadIdx.x;
    const int lane = tid & 31, warp = tid >> 5;
    const int q = lane >> 2, t = lane & 3;
    const int w0 = blockIdx.x * 32, h0 = blockIdx.y * 16;

    for (int i = tid; i < NSL; i += 256) {
        int tt = i / 612, pos = i % 612;
        int y = pos / 34, xx = pos % 34;
        int gh = h0 + y - 1, gw = w0 + xx - 1;
        bool ok = (gh >= 0) && (gh < HH) && (gw >= 0) && (gw < WW);
        int ghc = min(max(gh, 0), HH - 1), gwc = min(max(gw, 0), WW - 1);
        int off8 = tt * HW + ghc * WW + gwc;
        s_idx[i] = off8 | ((ok ? 0 : 1) << 18);
    }

    const uint32_t smx = (uint32_t)__cvta_generic_to_shared(s_x);
    const uint32_t smw = (uint32_t)__cvta_generic_to_shared(s_w);

    auto stage_x = [&](int ch, int buf) {
        const char* base = (const char*)in2 + ((size_t)b * NCH + ch) * 4 * HW * 8;
        uint32_t sb = smx + buf * (XBUF * 8);
#pragma unroll
        for (int j = 0; j < 10; j++) {
            int i = tid + j * 256;
            if (i < NSL) {
                int wv = s_idx[i];
                const char* src = base + ((size_t)(wv & 0x3FFFF)) * 8;
                int sz = ((wv >> 18) & 1) ? 0 : 8;
                asm volatile("cp.async.ca.shared.global [%0], [%1], 8, %2;"
                             :: "r"(sb + (unsigned)i * 8), "l"(src), "r"(sz));
            }
        }
    };
    auto stage_w = [&](int ch, int buf) {
        const uint4* src = wpk + ch * (WBUF / 2);
        uint32_t sb = smw + buf * (WBUF * 8);
#pragma unroll
        for (int j = 0; j < WITER; j++) {
            int i = tid + j * 256;
            if (i < WBUF / 2)
                asm volatile("cp.async.cg.shared.global [%0], [%1], 16;"
                             :: "r"(sb + (unsigned)i * 16), "l"(src + i));
        }
    };

    float acc0[8][4], acc1[8][4];
#pragma unroll
    for (int i = 0; i < 8; i++)
#pragma unroll
        for (int k = 0; k < 4; k++) { acc0[i][k] = 0.f; acc1[i][k] = 0.f; }

    stage_x(0, 0); stage_w(0, 0);
    asm volatile("cp.async.commit_group;");
    if (NCH > 1) { stage_x(1, 1); stage_w(1, 1); }
    asm volatile("cp.async.commit_group;");

#pragma unroll 1
    for (int c = 0; c < NCH; c++) {
        if (c + 1 < NCH) asm volatile("cp.async.wait_group 1;");
        else             asm volatile("cp.async.wait_group 0;");
        __syncthreads();
        if (c + 2 < NCH) {
            stage_x(c + 2, (c + 2) % 3); stage_w(c + 2, (c + 2) % 3);
            asm volatile("cp.async.commit_group;");
        }

        const uint2* cx = s_x + (c % 3) * XBUF;
        const uint2* cw = s_w + (c % 3) * WBUF;
#pragma unroll
        for (int kk = 0; kk < 9; kk++) {
            const int ky = kk / 3, kx = kk % 3;
            const uint2* wb = cw + (kk * 4 + t) * WP2;
            uint2 w00 = wb[q], w01 = wb[q + 8];
            uint2 w10 = make_uint2(0, 0), w11 = make_uint2(0, 0);
            if (COUT == 32) { w10 = wb[q + 16]; w11 = wb[q + 24]; }
            const uint2* xb = cx + t * PLANE + ky * 34 + kx + q;
#pragma unroll
            for (int nt = 0; nt < 8; nt++) {
                int r = 2 * warp + (nt >> 2);
                int cb = (nt & 3) * 8;
                uint2 pb = xb[r * 34 + cb];
                mma_bf16(acc0[nt][0], acc0[nt][1], acc0[nt][2], acc0[nt][3],
                         w00.x, w01.x, w00.y, w01.y, pb.x, pb.y);
                if (COUT == 32)
                    mma_bf16(acc1[nt][0], acc1[nt][1], acc1[nt][2], acc1[nt][3],
                             w10.x, w11.x, w10.y, w11.y, pb.x, pb.y);
            }
        }
    }

    if (MODE == 1 && COUT == 32) {
        // pair layout: plane q holds channels {q, q+8, q+16, q+24}
        uint2* ob2 = (uint2*)outp + ((size_t)(b * 8 + q)) * HW;
#pragma unroll
        for (int nt = 0; nt < 8; nt++) {
            int h = h0 + 2 * warp + (nt >> 2);
            int w = w0 + (nt & 3) * 8 + 2 * t;
            size_t pix = (size_t)h * WW + w;
            float v00 = acc0[nt][0], v01 = acc0[nt][1];   // co=q, px 0/1
            float v80 = acc0[nt][2], v81 = acc0[nt][3];   // co=q+8
            float vG0 = acc1[nt][0], vG1 = acc1[nt][1];   // co=q+16
            float vT0 = acc1[nt][2], vT1 = acc1[nt][3];   // co=q+24
            if (RELU) {
                v00 = fmaxf(v00, 0.f); v01 = fmaxf(v01, 0.f);
                v80 = fmaxf(v80, 0.f); v81 = fmaxf(v81, 0.f);
                vG0 = fmaxf(vG0, 0.f); vG1 = fmaxf(vG1, 0.f);
                vT0 = fmaxf(vT0, 0.f); vT1 = fmaxf(vT1, 0.f);
            }
            uint4 st;
            st.x = pbf(v00, v80); st.y = pbf(vG0, vT0);
            st.z = pbf(v01, v81); st.w = pbf(vG1, vT1);
            *(uint4*)&ob2[pix] = st;
        }
    } else if (MODE == 1) {
        __nv_bfloat16* ob = (__nv_bfloat16*)outp + (size_t)b * COUT * HW;
#pragma unroll
        for (int nt = 0; nt < 8; nt++) {
            int h = h0 + 2 * warp + (nt >> 2);
            int w = w0 + (nt & 3) * 8 + 2 * t;
            size_t pix = (size_t)h * WW + w;
#pragma unroll
            for (int m = 0; m < 2; m++) {
                float v0 = acc0[nt][m * 2], v1 = acc0[nt][m * 2 + 1];
                if (RELU) { v0 = fmaxf(v0, 0.f); v1 = fmaxf(v1, 0.f); }
                int co = m * 8 + q;
                *(uint32_t*)&ob[(size_t)co * HW + pix] = pbf(v0, v1);
            }
        }
    } else {
        float wo0 = aux[q], wo1 = aux[q + 8], wo2 = aux[q + 16], wo3 = aux[q + 24];
        float* om = (float*)outp + (size_t)b * HW;
#pragma unroll
        for (int nt = 0; nt < 8; nt++) {
            int h = h0 + 2 * warp + (nt >> 2);
            int w = w0 + (nt & 3) * 8 + 2 * t;
            float v[8] = {acc0[nt][0], acc0[nt][1], acc0[nt][2], acc0[nt][3],
                          acc1[nt][0], acc1[nt][1], acc1[nt][2], acc1[nt][3]};
#pragma unroll
            for (int i = 0; i < 8; i++) v[i] = fmaxf(v[i], 0.f);
            float s0 = v[0] * wo0 + v[2] * wo1 + v[4] * wo2 + v[6] * wo3;
            float s1 = v[1] * wo0 + v[3] * wo1 + v[5] * wo2 + v[7] * wo3;
#pragma unroll
            for (int off = 4; off < 32; off <<= 1) {
                s0 += __shfl_xor_sync(0xffffffffu, s0, off);
                s1 += __shfl_xor_sync(0xffffffffu, s1, off);
            }
            if (q == 0) {
                float2 rr = make_float2(1.f / (1.f + expf(-s0)), 1.f / (1.f + expf(-s1)));
                *(float2*)&om[(size_t)h * WW + w] = rr;
            }
        }
    }
}

// ---------------- conv wrappers ----------------------------------------------
__global__ __launch_bounds__(256, 2)
void conv_stage1(const uint2* __restrict__ x2, const uint4* __restrict__ wp,
                 uint2* __restrict__ bufA2, __nv_bfloat16* __restrict__ att1) {
    if (blockIdx.z < BB)
        conv_body<32, 32, false, 1>(x2, wp + WP_WIN, bufA2, nullptr, blockIdx.z);
    else
        conv_body<32, 16, true, 1>(x2, wp + WP_AW1, att1, nullptr, blockIdx.z - BB);
}
__global__ __launch_bounds__(256, 2)
void conv_mid(const uint2* __restrict__ g, const uint4* __restrict__ wp,
              uint2* __restrict__ bufA2) {
    conv_body<128, 32, false, 1>(g, wp + WP_W2, bufA2, nullptr, blockIdx.z);
}
__global__ __launch_bounds__(256, 2)
void conv_last(const uint2* __restrict__ g, const uint4* __restrict__ wp,
               float* __restrict__ out, const float* __restrict__ w_out) {
    conv_body<128, 32, true, 2>(g, wp + WP_W3, out, w_out, blockIdx.z);
}

// ---------------- att2 conv (bf16 planar in) + fused 1x1->4 + sigmoid --------
__global__ __launch_bounds__(256, 2)
void conv3x3_att2(const __nv_bfloat16* __restrict__ in, const uint4* __restrict__ wpk,
                  const float* __restrict__ w3, const float* __restrict__ b3,
                  float* __restrict__ wmap) {
    constexpr int PLANE = 612;
    constexpr int WP2 = 20;
    __shared__ uint2 s_x[4 * PLANE];
    __shared__ uint2 s_w[9 * 4 * WP2];

    const int tid = threadIdx.x;
    const int lane = tid & 31, warp = tid >> 5;
    const int q = lane >> 2, t = lane & 3;
    const int w0 = blockIdx.x * 32, h0 = blockIdx.y * 16, b = blockIdx.z;

    const uint16_t* inb = (const uint16_t*)in + (size_t)b * 16 * HW;
    for (int i = tid; i < 4 * 612; i += 256) {
        int tt = i / 612, pos = i % 612;
        int y = pos / 34, xx = pos % 34;
        int gh = h0 + y - 1, gw = w0 + xx - 1;
        bool ok = (gh >= 0) && (gh < HH) && (gw >= 0) && (gw < WW);
        uint32_t wa = 0, wbv = 0;
        if (ok) {
            size_t o = (size_t)gh * WW + gw;
            uint32_t c0 = inb[(size_t)(2 * tt) * HW + o];
            uint32_t c1 = inb[(size_t)(2 * tt + 1) * HW + o];
            uint32_t c8 = inb[(size_t)(2 * tt + 8) * HW + o];
            uint32_t c9 = inb[(size_t)(2 * tt + 9) * HW + o];
            wa = c0 | (c1 << 16);
            wbv = c8 | (c9 << 16);
        }
        s_x[tt * PLANE + pos] = make_uint2(wa, wbv);
    }
    for (int i = tid; i < 9 * 4 * WP2 / 2; i += 256)
        ((uint4*)s_w)[i] = wpk[i];
    __syncthreads();

    float acc[8][4];
#pragma unroll
    for (int i = 0; i < 8; i++) { acc[i][0]=0.f; acc[i][1]=0.f; acc[i][2]=0.f; acc[i][3]=0.f; }

#pragma unroll
    for (int kk = 0; kk < 9; kk++) {
        const int ky = kk / 3, kx = kk % 3;
        const uint2* wb = s_w + (kk * 4 + t) * WP2;
        uint2 w00 = wb[q], w01 = wb[q + 8];
        const uint2* xb = s_x + t * PLANE + ky * 34 + kx + q;
#pragma unroll
        for (int nt = 0; nt < 8; nt++) {
            int r = 2 * warp + (nt >> 2);
            int cb = (nt & 3) * 8;
            uint2 pb = xb[r * 34 + cb];
            mma_bf16(acc[nt][0], acc[nt][1], acc[nt][2], acc[nt][3],
                     w00.x, w01.x, w00.y, w01.y, pb.x, pb.y);
        }
    }

    float w3a[4], w3b[4], b3v[4];
#pragma unroll
    for (int d = 0; d < 4; d++) {
        w3a[d] = w3[d * 16 + q];
        w3b[d] = w3[d * 16 + q + 8];
        b3v[d] = b3[d];
    }
    float* wm = wmap + (size_t)b * 4 * HW;
#pragma unroll
    for (int nt = 0; nt < 8; nt++) {
        int h = h0 + 2 * warp + (nt >> 2);
        int w = w0 + (nt & 3) * 8 + 2 * t;
        float v0 = fmaxf(acc[nt][0], 0.f), v1 = fmaxf(acc[nt][1], 0.f);
        float v2 = fmaxf(acc[nt][2], 0.f), v3 = fmaxf(acc[nt][3], 0.f);
#pragma unroll
        for (int d = 0; d < 4; d++) {
            float s0 = v0 * w3a[d] + v2 * w3b[d];
            float s1 = v1 * w3a[d] + v3 * w3b[d];
#pragma unroll
            for (int off = 4; off < 32; off <<= 1) {
                s0 += __shfl_xor_sync(0xffffffffu, s0, off);
                s1 += __shfl_xor_sync(0xffffffffu, s1, off);
            }
            if (q == 0) {
                float2 rr = make_float2(1.f / (1.f + expf(-(s0 + b3v[d]))),
                                        1.f / (1.f + expf(-(s1 + b3v[d]))));
                *(float2*)&wm[(size_t)d * HW + (size_t)h * WW + w] = rr;
            }
        }
    }
}

// ---------------- merged scans: z<4 vertical, z>=4 horizontal ----------------
// bufA is pair layout: plane (b*8+q) uint2 word = channels {q, q+8, q+16, q+24}.
#define HSTRIDE 261
__global__ __launch_bounds__(256, 4)
void scan_both(const uint2* __restrict__ bufA2, const float* __restrict__ alpha,
               const float* __restrict__ wmap, uint2* __restrict__ gated2) {
    int b = blockIdx.x, q = blockIdx.y;   // q = plane 0..7
    float a0 = alpha[q], a1 = alpha[q + 8], a2 = alpha[q + 16], a3 = alpha[q + 24];
    int half = q >> 2, tt = q & 3;

    if (blockIdx.z < 4) {
        // ------- vertical (dirs 0, 2), 64-row chunk, warm 16 -------
        int cn = blockIdx.z;
        int w = threadIdx.x;
        const uint2* xp = bufA2 + ((size_t)(b * 8 + q)) * HW + w;
        const float* wm0 = wmap + ((size_t)b * 4 + 0) * HW + w;
        const float* wm2 = wmap + ((size_t)b * 4 + 2) * HW + w;
        uint2* g0 = gated2 + ((size_t)((b * 8 + 0 + half) * 4 + tt)) * HW + w;
        uint2* g2 = gated2 + ((size_t)((b * 8 + 4 + half) * 4 + tt)) * HW + w;
        int h0 = cn * 64;

        float p0 = 0.f, p1 = 0.f, p2 = 0.f, p3 = 0.f;
#pragma unroll 2
        for (int h = max(0, h0 - 16); h < h0 + 64; h++) {
            size_t o = (size_t)h * WW;
            uint2 wv = xp[o];
            float2 lo = __bfloat1622float2(*reinterpret_cast<__nv_bfloat162*>(&wv.x));
            float2 hi = __bfloat1622float2(*reinterpret_cast<__nv_bfloat162*>(&wv.y));
            float v0 = fmaxf(lo.x + a0 * p0, 0.f);
            float v1 = fmaxf(lo.y + a1 * p1, 0.f);
            float v2 = fmaxf(hi.x + a2 * p2, 0.f);
            float v3 = fmaxf(hi.y + a3 * p3, 0.f);
            if (h >= h0) {
                float m = wm0[o];
                g0[o] = make_uint2(pbf(v0 * m, v1 * m), pbf(v2 * m, v3 * m));
            }
            p0 = v0; p1 = v1; p2 = v2; p3 = v3;
        }
        p0 = p1 = p2 = p3 = 0.f;
#pragma unroll 2
        for (int h = min(HH - 1, h0 + 63 + 16); h >= h0; h--) {
            size_t o = (size_t)h * WW;
            uint2 wv = xp[o];
            float2 lo = __bfloat1622float2(*reinterpret_cast<__nv_bfloat162*>(&wv.x));
            float2 hi = __bfloat1622float2(*reinterpret_cast<__nv_bfloat162*>(&wv.y));
            float v0 = fmaxf(lo.x + a0 * p0, 0.f);
            float v1 = fmaxf(lo.y + a1 * p1, 0.f);
            float v2 = fmaxf(hi.x + a2 * p2, 0.f);
            float v3 = fmaxf(hi.y + a3 * p3, 0.f);
            if (h < h0 + 64) {
                float m = wm2[o];
                g2[o] = make_uint2(pbf(v0 * m, v1 * m), pbf(v2 * m, v3 * m));
            }
            p0 = v0; p1 = v1; p2 = v2; p3 = v3;
        }
        return;
    }

    // ------- horizontal (dirs 1, 3), 8-row block, 16-col chunks, warm 16 -------
    extern __shared__ uint2 shu[];
    uint2* tin = shu;
    uint2* tf  = shu + 8 * HSTRIDE;
    uint2* tr  = shu + 16 * HSTRIDE;

    int rb = blockIdx.z - 4;
    int R0 = rb * 8;
    const int tid = threadIdx.x;

    const uint2* xp = bufA2 + ((size_t)(b * 8 + q)) * HW + (size_t)R0 * WW;
    for (int i = tid; i < 8 * 256; i += 256) {
        int r = i >> 8, col = i & 255;
        tin[r * HSTRIDE + col] = xp[(size_t)r * WW + col];
    }
    __syncthreads();

    {
        int dir = tid >> 7, rem = tid & 127;
        int r = rem & 7, ck = rem >> 3;
        int base = ck * 16;
        uint2* dst = dir ? tr : tf;
        float p0 = 0.f, p1 = 0.f, p2 = 0.f, p3 = 0.f;
        if (!dir) {
            for (int col = max(0, base - 16); col < base + 16; col++) {
                uint2 wv = tin[r * HSTRIDE + col];
                float2 lo = __bfloat1622float2(*reinterpret_cast<__nv_bfloat162*>(&wv.x));
                float2 hi = __bfloat1622float2(*reinterpret_cast<__nv_bfloat162*>(&wv.y));
                float v0 = fmaxf(lo.x + a0 * p0, 0.f);
                float v1 = fmaxf(lo.y + a1 * p1, 0.f);
                float v2 = fmaxf(hi.x + a2 * p2, 0.f);
                float v3 = fmaxf(hi.y + a3 * p3, 0.f);
                if (col >= base)
                    dst[r * HSTRIDE + col] = make_uint2(pbf(v0, v1), pbf(v2, v3));
                p0 = v0; p1 = v1; p2 = v2; p3 = v3;
            }
        } else {
            for (int col = min(255, base + 31); col >= base; col--) {
                uint2 wv = tin[r * HSTRIDE + col];
                float2 lo = __bfloat1622float2(*reinterpret_cast<__nv_bfloat162*>(&wv.x));
                float2 hi = __bfloat1622float2(*reinterpret_cast<__nv_bfloat162*>(&wv.y));
                float v0 = fmaxf(lo.x + a0 * p0, 0.f);
                float v1 = fmaxf(lo.y + a1 * p1, 0.f);
                float v2 = fmaxf(hi.x + a2 * p2, 0.f);
                float v3 = fmaxf(hi.y + a3 * p3, 0.f);
                if (col < base + 16)
                    dst[r * HSTRIDE + col] = make_uint2(pbf(v0, v1), pbf(v2, v3));
                p0 = v0; p1 = v1; p2 = v2; p3 = v3;
            }
        }
    }
    __syncthreads();

    const float* wm1 = wmap + ((size_t)b * 4 + 1) * HW + (size_t)R0 * WW;
    const float* wm3 = wmap + ((size_t)b * 4 + 3) * HW + (size_t)R0 * WW;
    uint2* g1 = gated2 + ((size_t)((b * 8 + 2 + half) * 4 + tt)) * HW + (size_t)R0 * WW;
    uint2* g3 = gated2 + ((size_t)((b * 8 + 6 + half) * 4 + tt)) * HW + (size_t)R0 * WW;
    for (int i = tid; i < 8 * 256; i += 256) {
        int r = i >> 8, col = i & 255;
        float m1 = wm1[i], m3 = wm3[i];
        uint2 f = tf[r * HSTRIDE + col];
        uint2 rv = tr[r * HSTRIDE + col];
        float2 flo = __bfloat1622float2(*reinterpret_cast<__nv_bfloat162*>(&f.x));
        float2 fhi = __bfloat1622float2(*reinterpret_cast<__nv_bfloat162*>(&f.y));
        float2 rlo = __bfloat1622float2(*reinterpret_cast<__nv_bfloat162*>(&rv.x));
        float2 rhi = __bfloat1622float2(*reinterpret_cast<__nv_bfloat162*>(&rv.y));
        g1[i] = make_uint2(pbf(flo.x * m1, flo.y * m1), pbf(fhi.x * m1, fhi.y * m1));
        g3[i] = make_uint2(pbf(rlo.x * m3, rlo.y * m3), pbf(rhi.x * m3, rhi.y * m3));
    }
}

// ---------------- launch ------------------------------------------------------
extern "C" void kernel_launch(void* const* d_in, const int* in_sizes, int n_in,
                              void* d_out, int out_size) {
    const float* x      = (const float*)d_in[0];
    const float* alpha1 = (const float*)d_in[1];
    const float* alpha2 = (const float*)d_in[2];
    const float* w_in   = (const float*)d_in[3];
    const float* w2     = (const float*)d_in[4];
    const float* w3     = (const float*)d_in[5];
    const float* att_w1 = (const float*)d_in[6];
    const float* att_w2 = (const float*)d_in[7];
    const float* att_w3 = (const float*)d_in[8];
    const float* att_b3 = (const float*)d_in[9];
    const float* w_out  = (const float*)d_in[10];
    float* out = (float*)d_out;

    __nv_bfloat16 *att1;
    float *wmap;
    uint2 *bufA2, *gated2, *x2;
    uint4* wp;
    cudaGetSymbolAddress((void**)&bufA2, g_bufA2);
    cudaGetSymbolAddress((void**)&gated2, g_gated2);
    cudaGetSymbolAddress((void**)&wmap, g_wmap);
    cudaGetSymbolAddress((void**)&x2, g_x2);
    cudaGetSymbolAddress((void**)&wp, g_wp);
    cudaGetSymbolAddress((void**)&att1, g_att1);

    constexpr int SMP32 = 3 * (2448 + 9 * 4 * 36) * 8 + 2448 * 4;   // 99648
    constexpr int SMH   = 24 * HSTRIDE * 8;                          // 50112
    cudaFuncSetAttribute(conv_stage1, cudaFuncAttributeMaxDynamicSharedMemorySize, SMP32);
    cudaFuncSetAttribute(conv_mid, cudaFuncAttributeMaxDynamicSharedMemorySize, SMP32);
    cudaFuncSetAttribute(conv_last, cudaFuncAttributeMaxDynamicSharedMemorySize, SMP32);
    cudaFuncSetAttribute(scan_both, cudaFuncAttributeMaxDynamicSharedMemorySize, SMH);

    dim3 blk(256);
    // 1) setup: repack x + prepack all weights
    setup_all<<<NXB + 100, blk>>>(x, x2, w_in, w2, w3, att_w1, att_w2, (uint2*)wp);

    // 2) conv1 (trunk, pair-layout out) + att1 (attention, planar out)
    conv_stage1<<<dim3(WW / 32, HH / 16, 2 * BB), blk, SMP32>>>(x2, wp, bufA2, att1);

    // 3) att2 + fused 1x1 + sigmoid -> wmap
    conv3x3_att2<<<dim3(WW / 32, HH / 16, BB), blk>>>(att1, wp + WP_AW2, att_w3, att_b3, wmap);

    // 4) scans stage 1
    scan_both<<<dim3(BB, 8, 36), blk, SMH>>>(bufA2, alpha1, wmap, gated2);

    // 5) conv2
    conv_mid<<<dim3(WW / 32, HH / 16, BB), blk, SMP32>>>(gated2, wp, bufA2);

    // 6) scans stage 2
    scan_both<<<dim3(BB, 8, 36), blk, SMH>>>(bufA2, alpha2, wmap, gated2);

    // 7) conv3 + fused 1x1 + sigmoid -> mask
    conv_last<<<dim3(WW / 32, HH / 16, BB), blk, SMP32>>>(gated2, wp, out, w_out);
}

// round 11
// speedup vs baseline: 6.6855x; 1.0043x over previous
#include <cuda_runtime.h>
#include <cuda_bf16.h>
#include <math.h>
#include <stdint.h>

#define BB 8
#define CC 32
#define HH 256
#define WW 256
#define HW (HH*WW)

// ---------------- scratch (device globals; no allocations allowed) ----------
__device__ uint2 g_bufA2[(size_t)BB * 8 * HW];           // 32 MiB: conv out, pair layout
__device__ uint2 g_gated2[(size_t)BB * 8 * 4 * HW];      // 128 MiB: gated concat, pair layout
__device__ uint32_t g_wmapb[(size_t)BB * 4 * HW];        // 8 MiB: gate maps, dup'd bf16x2
__device__ uint2 g_x2[(size_t)BB * 2 * 4 * HW];          // 32 MiB: bf16-packed x
__device__ uint4 g_wp[16384];                            // prepacked bf16 weights
__device__ __nv_bfloat16 g_att1[(size_t)BB * 16 * HW];   // 16 MiB: att1 planar

// g_wp offsets in uint4 units
#define WP_WIN 0
#define WP_W2  1296
#define WP_W3  6480
#define WP_AW1 11664
#define WP_AW2 12384

__device__ __forceinline__ uint32_t pbf(float lo, float hi) {
    uint32_t r;
    asm("cvt.rn.bf16x2.f32 %0, %1, %2;" : "=r"(r) : "f"(hi), "f"(lo));
    return r;
}
__device__ __forceinline__ uint32_t b2u(__nv_bfloat162 v) {
    return *reinterpret_cast<uint32_t*>(&v);
}
__device__ __forceinline__ __nv_bfloat162 u2b(uint32_t v) {
    return *reinterpret_cast<__nv_bfloat162*>(&v);
}

__device__ __forceinline__ void mma_bf16(float& d0, float& d1, float& d2, float& d3,
                                         uint32_t a0, uint32_t a1, uint32_t a2, uint32_t a3,
                                         uint32_t b0, uint32_t b1) {
    asm volatile(
        "mma.sync.aligned.m16n8k16.row.col.f32.bf16.bf16.f32 "
        "{%0,%1,%2,%3}, {%4,%5,%6,%7}, {%8,%9}, {%0,%1,%2,%3};"
        : "+f"(d0), "+f"(d1), "+f"(d2), "+f"(d3)
        : "r"(a0), "r"(a1), "r"(a2), "r"(a3), "r"(b0), "r"(b1));
}

// ---------------- merged setup: repack_x + all weight prepacks ---------------
#define NXB 16384
__global__ void setup_all(const float* __restrict__ x, uint2* __restrict__ x2,
                          const float* __restrict__ w_in, const float* __restrict__ w2,
                          const float* __restrict__ w3, const float* __restrict__ aw1,
                          const float* __restrict__ aw2, uint2* __restrict__ wp2) {
    if (blockIdx.x < NXB) {
        size_t i = (size_t)blockIdx.x * 256 + threadIdx.x;
        int p = (int)(i & (HW - 1));
        int pl = (int)(i >> 16);
        int b = pl >> 3, ch = (pl >> 2) & 1, t = pl & 3;
        const float* s = x + ((size_t)(b * CC + ch * 16 + 2 * t)) * HW + p;
        uint2 v;
        v.x = pbf(s[0], s[(size_t)HW]);
        v.y = pbf(s[(size_t)8 * HW], s[(size_t)9 * HW]);
        x2[i] = v;
        return;
    }
    int i = (blockIdx.x - NXB) * 256 + threadIdx.x;
    if (i >= 25488) return;
    const float* src; int CIN, COUT, WP2, base; bool pairmap;
    if (i < 2592)       { src = w_in; CIN = 32;  COUT = 32; WP2 = 36; base = 0;     pairmap = false; }
    else if (i < 12960) { src = w2;   CIN = 128; COUT = 32; WP2 = 36; base = 2592;  pairmap = true; }
    else if (i < 23328) { src = w3;   CIN = 128; COUT = 32; WP2 = 36; base = 12960; pairmap = true; }
    else if (i < 24768) { src = aw1;  CIN = 32;  COUT = 16; WP2 = 20; base = 23328; pairmap = false; }
    else                { src = aw2;  CIN = 16;  COUT = 16; WP2 = 20; base = 24768; pairmap = false; }
    int j = i - base;
    int wpos = j % WP2; int rem = j / WP2;
    int t = rem & 3; rem >>= 2; int kk = rem % 9; int ch = rem / 9;
    uint2 v = make_uint2(0u, 0u);
    if (wpos < COUT) {
        if (!pairmap) {
            int cb = ch * 16 + 2 * t;
            v.x = pbf(src[((size_t)wpos * CIN + cb) * 9 + kk],     src[((size_t)wpos * CIN + cb + 1) * 9 + kk]);
            v.y = pbf(src[((size_t)wpos * CIN + cb + 8) * 9 + kk], src[((size_t)wpos * CIN + cb + 9) * 9 + kk]);
        } else {
            int d = ch >> 1, half = ch & 1;
            int c1 = d * 32 + half * 4 + t;
            v.x = pbf(src[((size_t)wpos * CIN + c1) * 9 + kk],      src[((size_t)wpos * CIN + c1 + 8) * 9 + kk]);
            v.y = pbf(src[((size_t)wpos * CIN + c1 + 16) * 9 + kk], src[((size_t)wpos * CIN + c1 + 24) * 9 + kk]);
        }
    }
    wp2[i] = v;
}

// ---------------- bf16 tensor-core 3x3 conv body (pair-layout input) ---------
template <int CIN, int COUT, bool RELU, int MODE>
__device__ __forceinline__ void conv_body(const uint2* __restrict__ in2,
                                          const uint4* __restrict__ wpk,
                                          void* __restrict__ outp,
                                          const float* __restrict__ aux, int b) {
    constexpr int PLANE = 612;
    constexpr int WP2 = COUT + 4;
    constexpr int XBUF = 4 * PLANE;
    constexpr int WBUF = 9 * 4 * WP2;
    constexpr int NCH = CIN / 16;
    constexpr int NSL = 4 * 612;
    constexpr int WITER = (WBUF / 2 + 255) / 256;

    extern __shared__ uint2 sm[];
    uint2* s_x = sm;
    uint2* s_w = sm + 3 * XBUF;
    int* s_idx = (int*)(sm + 3 * (XBUF + WBUF));

    const int tid = threadIdx.x;
    const int lane = tid & 31, warp = tid >> 5;
    const int q = lane >> 2, t = lane & 3;
    const int w0 = blockIdx.x * 32, h0 = blockIdx.y * 16;

    for (int i = tid; i < NSL; i += 256) {
        int tt = i / 612, pos = i % 612;
        int y = pos / 34, xx = pos % 34;
        int gh = h0 + y - 1, gw = w0 + xx - 1;
        bool ok = (gh >= 0) && (gh < HH) && (gw >= 0) && (gw < WW);
        int ghc = min(max(gh, 0), HH - 1), gwc = min(max(gw, 0), WW - 1);
        int off8 = tt * HW + ghc * WW + gwc;
        s_idx[i] = off8 | ((ok ? 0 : 1) << 18);
    }

    const uint32_t smx = (uint32_t)__cvta_generic_to_shared(s_x);
    const uint32_t smw = (uint32_t)__cvta_generic_to_shared(s_w);

    auto stage_x = [&](int ch, int buf) {
        const char* base = (const char*)in2 + ((size_t)b * NCH + ch) * 4 * HW * 8;
        uint32_t sb = smx + buf * (XBUF * 8);
#pragma unroll
        for (int j = 0; j < 10; j++) {
            int i = tid + j * 256;
            if (i < NSL) {
                int wv = s_idx[i];
                const char* src = base + ((size_t)(wv & 0x3FFFF)) * 8;
                int sz = ((wv >> 18) & 1) ? 0 : 8;
                asm volatile("cp.async.ca.shared.global [%0], [%1], 8, %2;"
                             :: "r"(sb + (unsigned)i * 8), "l"(src), "r"(sz));
            }
        }
    };
    auto stage_w = [&](int ch, int buf) {
        const uint4* src = wpk + ch * (WBUF / 2);
        uint32_t sb = smw + buf * (WBUF * 8);
#pragma unroll
        for (int j = 0; j < WITER; j++) {
            int i = tid + j * 256;
            if (i < WBUF / 2)
                asm volatile("cp.async.cg.shared.global [%0], [%1], 16;"
                             :: "r"(sb + (unsigned)i * 16), "l"(src + i));
        }
    };

    float acc0[8][4], acc1[8][4];
#pragma unroll
    for (int i = 0; i < 8; i++)
#pragma unroll
        for (int k = 0; k < 4; k++) { acc0[i][k] = 0.f; acc1[i][k] = 0.f; }

    stage_x(0, 0); stage_w(0, 0);
    asm volatile("cp.async.commit_group;");
    if (NCH > 1) { stage_x(1, 1); stage_w(1, 1); }
    asm volatile("cp.async.commit_group;");

#pragma unroll 1
    for (int c = 0; c < NCH; c++) {
        if (c + 1 < NCH) asm volatile("cp.async.wait_group 1;");
        else             asm volatile("cp.async.wait_group 0;");
        __syncthreads();
        if (c + 2 < NCH) {
            stage_x(c + 2, (c + 2) % 3); stage_w(c + 2, (c + 2) % 3);
            asm volatile("cp.async.commit_group;");
        }

        const uint2* cx = s_x + (c % 3) * XBUF;
        const uint2* cw = s_w + (c % 3) * WBUF;
#pragma unroll
        for (int kk = 0; kk < 9; kk++) {
            const int ky = kk / 3, kx = kk % 3;
            const uint2* wb = cw + (kk * 4 + t) * WP2;
            uint2 w00 = wb[q], w01 = wb[q + 8];
            uint2 w10 = make_uint2(0, 0), w11 = make_uint2(0, 0);
            if (COUT == 32) { w10 = wb[q + 16]; w11 = wb[q + 24]; }
            const uint2* xb = cx + t * PLANE + ky * 34 + kx + q;
#pragma unroll
            for (int nt = 0; nt < 8; nt++) {
                int r = 2 * warp + (nt >> 2);
                int cb = (nt & 3) * 8;
                uint2 pb = xb[r * 34 + cb];
                mma_bf16(acc0[nt][0], acc0[nt][1], acc0[nt][2], acc0[nt][3],
                         w00.x, w01.x, w00.y, w01.y, pb.x, pb.y);
                if (COUT == 32)
                    mma_bf16(acc1[nt][0], acc1[nt][1], acc1[nt][2], acc1[nt][3],
                             w10.x, w11.x, w10.y, w11.y, pb.x, pb.y);
            }
        }
    }

    if (MODE == 1 && COUT == 32) {
        uint2* ob2 = (uint2*)outp + ((size_t)(b * 8 + q)) * HW;
#pragma unroll
        for (int nt = 0; nt < 8; nt++) {
            int h = h0 + 2 * warp + (nt >> 2);
            int w = w0 + (nt & 3) * 8 + 2 * t;
            size_t pix = (size_t)h * WW + w;
            float v00 = acc0[nt][0], v01 = acc0[nt][1];
            float v80 = acc0[nt][2], v81 = acc0[nt][3];
            float vG0 = acc1[nt][0], vG1 = acc1[nt][1];
            float vT0 = acc1[nt][2], vT1 = acc1[nt][3];
            if (RELU) {
                v00 = fmaxf(v00, 0.f); v01 = fmaxf(v01, 0.f);
                v80 = fmaxf(v80, 0.f); v81 = fmaxf(v81, 0.f);
                vG0 = fmaxf(vG0, 0.f); vG1 = fmaxf(vG1, 0.f);
                vT0 = fmaxf(vT0, 0.f); vT1 = fmaxf(vT1, 0.f);
            }
            uint4 st;
            st.x = pbf(v00, v80); st.y = pbf(vG0, vT0);
            st.z = pbf(v01, v81); st.w = pbf(vG1, vT1);
            *(uint4*)&ob2[pix] = st;
        }
    } else if (MODE == 1) {
        __nv_bfloat16* ob = (__nv_bfloat16*)outp + (size_t)b * COUT * HW;
#pragma unroll
        for (int nt = 0; nt < 8; nt++) {
            int h = h0 + 2 * warp + (nt >> 2);
            int w = w0 + (nt & 3) * 8 + 2 * t;
            size_t pix = (size_t)h * WW + w;
#pragma unroll
            for (int m = 0; m < 2; m++) {
                float v0 = acc0[nt][m * 2], v1 = acc0[nt][m * 2 + 1];
                if (RELU) { v0 = fmaxf(v0, 0.f); v1 = fmaxf(v1, 0.f); }
                int co = m * 8 + q;
                *(uint32_t*)&ob[(size_t)co * HW + pix] = pbf(v0, v1);
            }
        }
    } else {
        float wo0 = aux[q], wo1 = aux[q + 8], wo2 = aux[q + 16], wo3 = aux[q + 24];
        float* om = (float*)outp + (size_t)b * HW;
#pragma unroll
        for (int nt = 0; nt < 8; nt++) {
            int h = h0 + 2 * warp + (nt >> 2);
            int w = w0 + (nt & 3) * 8 + 2 * t;
            float v[8] = {acc0[nt][0], acc0[nt][1], acc0[nt][2], acc0[nt][3],
                          acc1[nt][0], acc1[nt][1], acc1[nt][2], acc1[nt][3]};
#pragma unroll
            for (int i = 0; i < 8; i++) v[i] = fmaxf(v[i], 0.f);
            float s0 = v[0] * wo0 + v[2] * wo1 + v[4] * wo2 + v[6] * wo3;
            float s1 = v[1] * wo0 + v[3] * wo1 + v[5] * wo2 + v[7] * wo3;
#pragma unroll
            for (int off = 4; off < 32; off <<= 1) {
                s0 += __shfl_xor_sync(0xffffffffu, s0, off);
                s1 += __shfl_xor_sync(0xffffffffu, s1, off);
            }
            if (q == 0) {
                float2 rr = make_float2(1.f / (1.f + expf(-s0)), 1.f / (1.f + expf(-s1)));
                *(float2*)&om[(size_t)h * WW + w] = rr;
            }
        }
    }
}

// ---------------- conv wrappers ----------------------------------------------
__global__ __launch_bounds__(256, 2)
void conv_stage1(const uint2* __restrict__ x2, const uint4* __restrict__ wp,
                 uint2* __restrict__ bufA2, __nv_bfloat16* __restrict__ att1) {
    if (blockIdx.z < BB)
        conv_body<32, 32, false, 1>(x2, wp + WP_WIN, bufA2, nullptr, blockIdx.z);
    else
        conv_body<32, 16, true, 1>(x2, wp + WP_AW1, att1, nullptr, blockIdx.z - BB);
}
__global__ __launch_bounds__(256, 2)
void conv_mid(const uint2* __restrict__ g, const uint4* __restrict__ wp,
              uint2* __restrict__ bufA2) {
    conv_body<128, 32, false, 1>(g, wp + WP_W2, bufA2, nullptr, blockIdx.z);
}
__global__ __launch_bounds__(256, 2)
void conv_last(const uint2* __restrict__ g, const uint4* __restrict__ wp,
               float* __restrict__ out, const float* __restrict__ w_out) {
    conv_body<128, 32, true, 2>(g, wp + WP_W3, out, w_out, blockIdx.z);
}

// ---------------- att2 conv + fused 1x1->4 + sigmoid -> dup'd bf16 wmap ------
__global__ __launch_bounds__(256, 2)
void conv3x3_att2(const __nv_bfloat16* __restrict__ in, const uint4* __restrict__ wpk,
                  const float* __restrict__ w3, const float* __restrict__ b3,
                  uint32_t* __restrict__ wmapb) {
    constexpr int PLANE = 612;
    constexpr int WP2 = 20;
    __shared__ uint2 s_x[4 * PLANE];
    __shared__ uint2 s_w[9 * 4 * WP2];

    const int tid = threadIdx.x;
    const int lane = tid & 31, warp = tid >> 5;
    const int q = lane >> 2, t = lane & 3;
    const int w0 = blockIdx.x * 32, h0 = blockIdx.y * 16, b = blockIdx.z;

    const uint16_t* inb = (const uint16_t*)in + (size_t)b * 16 * HW;
    for (int i = tid; i < 4 * 612; i += 256) {
        int tt = i / 612, pos = i % 612;
        int y = pos / 34, xx = pos % 34;
        int gh = h0 + y - 1, gw = w0 + xx - 1;
        bool ok = (gh >= 0) && (gh < HH) && (gw >= 0) && (gw < WW);
        uint32_t wa = 0, wbv = 0;
        if (ok) {
            size_t o = (size_t)gh * WW + gw;
            uint32_t c0 = inb[(size_t)(2 * tt) * HW + o];
            uint32_t c1 = inb[(size_t)(2 * tt + 1) * HW + o];
            uint32_t c8 = inb[(size_t)(2 * tt + 8) * HW + o];
            uint32_t c9 = inb[(size_t)(2 * tt + 9) * HW + o];
            wa = c0 | (c1 << 16);
            wbv = c8 | (c9 << 16);
        }
        s_x[tt * PLANE + pos] = make_uint2(wa, wbv);
    }
    for (int i = tid; i < 9 * 4 * WP2 / 2; i += 256)
        ((uint4*)s_w)[i] = wpk[i];
    __syncthreads();

    float acc[8][4];
#pragma unroll
    for (int i = 0; i < 8; i++) { acc[i][0]=0.f; acc[i][1]=0.f; acc[i][2]=0.f; acc[i][3]=0.f; }

#pragma unroll
    for (int kk = 0; kk < 9; kk++) {
        const int ky = kk / 3, kx = kk % 3;
        const uint2* wb = s_w + (kk * 4 + t) * WP2;
        uint2 w00 = wb[q], w01 = wb[q + 8];
        const uint2* xb = s_x + t * PLANE + ky * 34 + kx + q;
#pragma unroll
        for (int nt = 0; nt < 8; nt++) {
            int r = 2 * warp + (nt >> 2);
            int cb = (nt & 3) * 8;
            uint2 pb = xb[r * 34 + cb];
            mma_bf16(acc[nt][0], acc[nt][1], acc[nt][2], acc[nt][3],
                     w00.x, w01.x, w00.y, w01.y, pb.x, pb.y);
        }
    }

    float w3a[4], w3b[4], b3v[4];
#pragma unroll
    for (int d = 0; d < 4; d++) {
        w3a[d] = w3[d * 16 + q];
        w3b[d] = w3[d * 16 + q + 8];
        b3v[d] = b3[d];
    }
    uint32_t* wm = wmapb + (size_t)b * 4 * HW;
#pragma unroll
    for (int nt = 0; nt < 8; nt++) {
        int h = h0 + 2 * warp + (nt >> 2);
        int w = w0 + (nt & 3) * 8 + 2 * t;
        float v0 = fmaxf(acc[nt][0], 0.f), v1 = fmaxf(acc[nt][1], 0.f);
        float v2 = fmaxf(acc[nt][2], 0.f), v3 = fmaxf(acc[nt][3], 0.f);
#pragma unroll
        for (int d = 0; d < 4; d++) {
            float s0 = v0 * w3a[d] + v2 * w3b[d];
            float s1 = v1 * w3a[d] + v3 * w3b[d];
#pragma unroll
            for (int off = 4; off < 32; off <<= 1) {
                s0 += __shfl_xor_sync(0xffffffffu, s0, off);
                s1 += __shfl_xor_sync(0xffffffffu, s1, off);
            }
            if (q == 0) {
                float m0 = 1.f / (1.f + expf(-(s0 + b3v[d])));
                float m1 = 1.f / (1.f + expf(-(s1 + b3v[d])));
                uint2 st = make_uint2(pbf(m0, m0), pbf(m1, m1));
                *(uint2*)&wm[(size_t)d * HW + (size_t)h * WW + w] = st;
            }
        }
    }
}

// ---------------- merged scans: packed bf16x2 recurrence ---------------------
// plane (b*8+q) word = {bf16x2(q, q+8), bf16x2(q+16, q+24)}.
// v = relu(x + a*p) via 2 chained HFMA2 (alpha split hi+lo) + HMAX2.
#define HSTRIDE 261
__global__ __launch_bounds__(256, 4)
void scan_both(const uint2* __restrict__ bufA2, const float* __restrict__ alpha,
               const uint32_t* __restrict__ wmapb, uint2* __restrict__ gated2) {
    int b = blockIdx.x, q = blockIdx.y;
    float a0 = alpha[q], a1 = alpha[q + 8], a2 = alpha[q + 16], a3 = alpha[q + 24];
    __nv_bfloat16 h0b = __float2bfloat16_rn(a0), h1b = __float2bfloat16_rn(a1);
    __nv_bfloat16 h2b = __float2bfloat16_rn(a2), h3b = __float2bfloat16_rn(a3);
    __nv_bfloat162 ahi01 = __halves2bfloat162(h0b, h1b);
    __nv_bfloat162 ahi23 = __halves2bfloat162(h2b, h3b);
    __nv_bfloat162 alo01 = __halves2bfloat162(
        __float2bfloat16_rn(a0 - __bfloat162float(h0b)),
        __float2bfloat16_rn(a1 - __bfloat162float(h1b)));
    __nv_bfloat162 alo23 = __halves2bfloat162(
        __float2bfloat16_rn(a2 - __bfloat162float(h2b)),
        __float2bfloat16_rn(a3 - __bfloat162float(h3b)));
    const __nv_bfloat162 z2 = __float2bfloat162_rn(0.f);
    int half = q >> 2, tt = q & 3;

    if (blockIdx.z < 4) {
        // ------- vertical (dirs 0, 2), 64-row chunk, warm 16 -------
        int cn = blockIdx.z;
        int w = threadIdx.x;
        const uint2* xp = bufA2 + ((size_t)(b * 8 + q)) * HW + w;
        const uint32_t* wm0 = wmapb + ((size_t)b * 4 + 0) * HW + w;
        const uint32_t* wm2 = wmapb + ((size_t)b * 4 + 2) * HW + w;
        uint2* g0 = gated2 + ((size_t)((b * 8 + 0 + half) * 4 + tt)) * HW + w;
        uint2* g2 = gated2 + ((size_t)((b * 8 + 4 + half) * 4 + tt)) * HW + w;
        int h0 = cn * 64;

        __nv_bfloat162 p01 = z2, p23 = z2;
#pragma unroll 2
        for (int h = max(0, h0 - 16); h < h0 + 64; h++) {
            size_t o = (size_t)h * WW;
            uint2 wv = xp[o];
            __nv_bfloat162 v01 = __hfma2(ahi01, p01, u2b(wv.x));
            v01 = __hfma2(alo01, p01, v01);
            v01 = __hmax2(v01, z2);
            __nv_bfloat162 v23 = __hfma2(ahi23, p23, u2b(wv.y));
            v23 = __hfma2(alo23, p23, v23);
            v23 = __hmax2(v23, z2);
            if (h >= h0) {
                __nv_bfloat162 m2 = u2b(wm0[o]);
                g0[o] = make_uint2(b2u(__hmul2(v01, m2)), b2u(__hmul2(v23, m2)));
            }
            p01 = v01; p23 = v23;
        }
        p01 = z2; p23 = z2;
#pragma unroll 2
        for (int h = min(HH - 1, h0 + 63 + 16); h >= h0; h--) {
            size_t o = (size_t)h * WW;
            uint2 wv = xp[o];
            __nv_bfloat162 v01 = __hfma2(ahi01, p01, u2b(wv.x));
            v01 = __hfma2(alo01, p01, v01);
            v01 = __hmax2(v01, z2);
            __nv_bfloat162 v23 = __hfma2(ahi23, p23, u2b(wv.y));
            v23 = __hfma2(alo23, p23, v23);
            v23 = __hmax2(v23, z2);
            if (h < h0 + 64) {
                __nv_bfloat162 m2 = u2b(wm2[o]);
                g2[o] = make_uint2(b2u(__hmul2(v01, m2)), b2u(__hmul2(v23, m2)));
            }
            p01 = v01; p23 = v23;
        }
        return;
    }

    // ------- horizontal (dirs 1, 3), 8-row block, 16-col chunks, warm 16 -------
    extern __shared__ uint2 shu[];
    uint2* tin = shu;
    uint2* tf  = shu + 8 * HSTRIDE;
    uint2* tr  = shu + 16 * HSTRIDE;

    int rb = blockIdx.z - 4;
    int R0 = rb * 8;
    const int tid = threadIdx.x;

    const uint2* xp = bufA2 + ((size_t)(b * 8 + q)) * HW + (size_t)R0 * WW;
    for (int i = tid; i < 8 * 256; i += 256) {
        int r = i >> 8, col = i & 255;
        tin[r * HSTRIDE + col] = xp[(size_t)r * WW + col];
    }
    __syncthreads();

    {
        int dir = tid >> 7, rem = tid & 127;
        int r = rem & 7, ck = rem >> 3;
        int base = ck * 16;
        uint2* dst = dir ? tr : tf;
        __nv_bfloat162 p01 = z2, p23 = z2;
        if (!dir) {
            for (int col = max(0, base - 16); col < base + 16; col++) {
                uint2 wv = tin[r * HSTRIDE + col];
                __nv_bfloat162 v01 = __hfma2(ahi01, p01, u2b(wv.x));
                v01 = __hfma2(alo01, p01, v01);
                v01 = __hmax2(v01, z2);
                __nv_bfloat162 v23 = __hfma2(ahi23, p23, u2b(wv.y));
                v23 = __hfma2(alo23, p23, v23);
                v23 = __hmax2(v23, z2);
                if (col >= base)
                    dst[r * HSTRIDE + col] = make_uint2(b2u(v01), b2u(v23));
                p01 = v01; p23 = v23;
            }
        } else {
            for (int col = min(255, base + 31); col >= base; col--) {
                uint2 wv = tin[r * HSTRIDE + col];
                __nv_bfloat162 v01 = __hfma2(ahi01, p01, u2b(wv.x));
                v01 = __hfma2(alo01, p01, v01);
                v01 = __hmax2(v01, z2);
                __nv_bfloat162 v23 = __hfma2(ahi23, p23, u2b(wv.y));
                v23 = __hfma2(alo23, p23, v23);
                v23 = __hmax2(v23, z2);
                if (col < base + 16)
                    dst[r * HSTRIDE + col] = make_uint2(b2u(v01), b2u(v23));
                p01 = v01; p23 = v23;
            }
        }
    }
    __syncthreads();

    const uint32_t* wm1 = wmapb + ((size_t)b * 4 + 1) * HW + (size_t)R0 * WW;
    const uint32_t* wm3 = wmapb + ((size_t)b * 4 + 3) * HW + (size_t)R0 * WW;
    uint2* g1 = gated2 + ((size_t)((b * 8 + 2 + half) * 4 + tt)) * HW + (size_t)R0 * WW;
    uint2* g3 = gated2 + ((size_t)((b * 8 + 6 + half) * 4 + tt)) * HW + (size_t)R0 * WW;
    for (int i = tid; i < 8 * 256; i += 256) {
        int r = i >> 8, col = i & 255;
        __nv_bfloat162 m1 = u2b(wm1[i]);
        __nv_bfloat162 m3 = u2b(wm3[i]);
        uint2 f = tf[r * HSTRIDE + col];
        uint2 rv = tr[r * HSTRIDE + col];
        g1[i] = make_uint2(b2u(__hmul2(u2b(f.x), m1)), b2u(__hmul2(u2b(f.y), m1)));
        g3[i] = make_uint2(b2u(__hmul2(u2b(rv.x), m3)), b2u(__hmul2(u2b(rv.y), m3)));
    }
}

// ---------------- launch ------------------------------------------------------
extern "C" void kernel_launch(void* const* d_in, const int* in_sizes, int n_in,
                              void* d_out, int out_size) {
    const float* x      = (const float*)d_in[0];
    const float* alpha1 = (const float*)d_in[1];
    const float* alpha2 = (const float*)d_in[2];
    const float* w_in   = (const float*)d_in[3];
    const float* w2     = (const float*)d_in[4];
    const float* w3     = (const float*)d_in[5];
    const float* att_w1 = (const float*)d_in[6];
    const float* att_w2 = (const float*)d_in[7];
    const float* att_w3 = (const float*)d_in[8];
    const float* att_b3 = (const float*)d_in[9];
    const float* w_out  = (const float*)d_in[10];
    float* out = (float*)d_out;

    __nv_bfloat16 *att1;
    uint32_t *wmapb;
    uint2 *bufA2, *gated2, *x2;
    uint4* wp;
    cudaGetSymbolAddress((void**)&bufA2, g_bufA2);
    cudaGetSymbolAddress((void**)&gated2, g_gated2);
    cudaGetSymbolAddress((void**)&wmapb, g_wmapb);
    cudaGetSymbolAddress((void**)&x2, g_x2);
    cudaGetSymbolAddress((void**)&wp, g_wp);
    cudaGetSymbolAddress((void**)&att1, g_att1);

    constexpr int SMP32 = 3 * (2448 + 9 * 4 * 36) * 8 + 2448 * 4;   // 99648
    constexpr int SMH   = 24 * HSTRIDE * 8;                          // 50112
    cudaFuncSetAttribute(conv_stage1, cudaFuncAttributeMaxDynamicSharedMemorySize, SMP32);
    cudaFuncSetAttribute(conv_mid, cudaFuncAttributeMaxDynamicSharedMemorySize, SMP32);
    cudaFuncSetAttribute(conv_last, cudaFuncAttributeMaxDynamicSharedMemorySize, SMP32);
    cudaFuncSetAttribute(scan_both, cudaFuncAttributeMaxDynamicSharedMemorySize, SMH);

    dim3 blk(256);
    // 1) setup: repack x + prepack all weights
    setup_all<<<NXB + 100, blk>>>(x, x2, w_in, w2, w3, att_w1, att_w2, (uint2*)wp);

    // 2) conv1 (trunk, pair-layout out) + att1 (attention, planar out)
    conv_stage1<<<dim3(WW / 32, HH / 16, 2 * BB), blk, SMP32>>>(x2, wp, bufA2, att1);

    // 3) att2 + fused 1x1 + sigmoid -> wmapb (dup'd bf16)
    conv3x3_att2<<<dim3(WW / 32, HH / 16, BB), blk>>>(att1, wp + WP_AW2, att_w3, att_b3, wmapb);

    // 4) scans stage 1
    scan_both<<<dim3(BB, 8, 36), blk, SMH>>>(bufA2, alpha1, wmapb, gated2);

    // 5) conv2
    conv_mid<<<dim3(WW / 32, HH / 16, BB), blk, SMP32>>>(gated2, wp, bufA2);

    // 6) scans stage 2
    scan_both<<<dim3(BB, 8, 36), blk, SMH>>>(bufA2, alpha2, wmapb, gated2);

    // 7) conv3 + fused 1x1 + sigmoid -> mask
    conv_last<<<dim3(WW / 32, HH / 16, BB), blk, SMP32>>>(gated2, wp, out, w_out);
}